// round 4
// baseline (speedup 1.0000x reference)
#include <cuda_runtime.h>
#include <cuda_bf16.h>
#include <math.h>

#define N_NODES  50000
#define N_EDGES  800000
#define NODE_D   128
#define EDGE_D   100
#define EMB_D    92
#define N_GRAPHS 256
#define N_CONV   3
#define FC_D     128

#define DELTA    (6.0f / 99.0f)
#define N_T      1800
#define H_T      (DELTA / 16.0f)

#define SB    256
#define SGRID ((N_NODES + SB - 1) / SB)

// ---------------- scratch (device globals) ----------------
__device__ float g_x[N_NODES * NODE_D];
__device__ float g_A[N_NODES * 256];                 // dst part (fp32, incl bias)
__device__ __nv_bfloat16 g_Bh[N_NODES * 256];        // src part (bf16)
__device__ __nv_bfloat16 g_tab2[N_T * 512];          // interleaved (lo,hi) bf16 pairs
__device__ int   g_deg[N_NODES];
__device__ int   g_off[N_NODES];
__device__ int   g_rowstart[N_NODES + 1];
__device__ int   g_bsum[SGRID];
__device__ int   g_srcs[N_EDGES];
__device__ int   g_tidx[N_EDGES];
__device__ float g_frac[N_EDGES];
__device__ float g_pool[N_GRAPHS * NODE_D];
__device__ float g_cnt[N_GRAPHS];

// ---------------- helpers ----------------
__device__ __forceinline__ float softplusf(float x) {
    return fmaxf(x, 0.f) + log1pf(__expf(-fabsf(x)));
}
__device__ __forceinline__ float sigmoidf(float x) {
    return 1.f / (1.f + __expf(-x));
}
__device__ __forceinline__ void ffma2(unsigned long long& d,
                                      unsigned long long a,
                                      unsigned long long b) {
    asm("fma.rn.f32x2 %0, %1, %2, %0;" : "+l"(d) : "l"(a), "l"(b));
}
__device__ __forceinline__ float f2lo(unsigned long long v) {
    return __uint_as_float((unsigned)(v & 0xffffffffull));
}
__device__ __forceinline__ float f2hi(unsigned long long v) {
    return __uint_as_float((unsigned)(v >> 32));
}

// ---------------- zero ----------------
__global__ void zero_misc_kernel() {
    int i = blockIdx.x * blockDim.x + threadIdx.x;
    if (i < N_NODES) g_deg[i] = 0;
    if (i < N_GRAPHS * NODE_D) g_pool[i] = 0.f;
    if (i < N_GRAPHS) g_cnt[i] = 0.f;
}

// ---------------- x0 = embedding[z] @ emb_w + emb_b ----------------
__global__ void embed_kernel(const int* __restrict__ z,
                             const float* __restrict__ emb,
                             const float* __restrict__ W,
                             const float* __restrict__ b) {
    __shared__ float er[EMB_D];
    int n = blockIdx.x;
    int zi = z[n];
    if (threadIdx.x < EMB_D) er[threadIdx.x] = emb[zi * EMB_D + threadIdx.x];
    __syncthreads();
    int c = threadIdx.x;
    float acc = b[c];
#pragma unroll 4
    for (int k = 0; k < EMB_D; k++) acc += er[k] * W[k * NODE_D + c];
    g_x[(size_t)n * NODE_D + c] = acc;
}

// ---------------- counting sort by dst: hist + 3-phase scan + scatter ----------------
__global__ void hist_kernel(const int* __restrict__ dst) {
    int e = blockIdx.x * blockDim.x + threadIdx.x;
    if (e < N_EDGES) atomicAdd(&g_deg[dst[e]], 1);
}

__global__ void scan_pass1() {
    __shared__ int ws[8];
    int i = blockIdx.x * SB + threadIdx.x;
    int v = (i < N_NODES) ? g_deg[i] : 0;
#pragma unroll
    for (int off = 16; off > 0; off >>= 1) v += __shfl_xor_sync(0xffffffffu, v, off);
    if ((threadIdx.x & 31) == 0) ws[threadIdx.x >> 5] = v;
    __syncthreads();
    if (threadIdx.x == 0) {
        int s = 0;
#pragma unroll
        for (int w = 0; w < 8; w++) s += ws[w];
        g_bsum[blockIdx.x] = s;
    }
}

__global__ void scan_pass2() {   // 1 block, 256 threads, SGRID <= 256
    __shared__ int sm[SB];
    int t = threadIdx.x;
    int v = (t < SGRID) ? g_bsum[t] : 0;
    sm[t] = v;
    __syncthreads();
#pragma unroll
    for (int off = 1; off < SB; off <<= 1) {
        int u = (t >= off) ? sm[t - off] : 0;
        __syncthreads();
        sm[t] += u;
        __syncthreads();
    }
    if (t < SGRID) g_bsum[t] = sm[t] - v;   // exclusive
}

__global__ void scan_pass3() {
    __shared__ int sm[SB];
    int t = threadIdx.x;
    int i = blockIdx.x * SB + t;
    int v = (i < N_NODES) ? g_deg[i] : 0;
    sm[t] = v;
    __syncthreads();
#pragma unroll
    for (int off = 1; off < SB; off <<= 1) {
        int u = (t >= off) ? sm[t - off] : 0;
        __syncthreads();
        sm[t] += u;
        __syncthreads();
    }
    int ex = g_bsum[blockIdx.x] + sm[t] - v;   // exclusive prefix
    if (i < N_NODES) {
        g_rowstart[i] = ex;
        g_off[i] = ex;
        if (i == N_NODES - 1) g_rowstart[N_NODES] = ex + v;
    }
}

__global__ void scatter_kernel(const float* __restrict__ R,
                               const int* __restrict__ src,
                               const int* __restrict__ dst) {
    int e = blockIdx.x * blockDim.x + threadIdx.x;
    if (e >= N_EDGES) return;
    int s = src[e], d = dst[e];
    float dx = R[s * 3 + 0] - R[d * 3 + 0];
    float dy = R[s * 3 + 1] - R[d * 3 + 1];
    float dz = R[s * 3 + 2] - R[d * 3 + 2];
    float dist = sqrtf(dx * dx + dy * dy + dz * dz);
    float u = fminf(dist / H_T, (float)(N_T - 2));
    int   t = (int)u;
    float f = u - (float)t;
    int pos = atomicAdd(&g_off[d], 1);
    g_srcs[pos] = s;
    g_tidx[pos] = t;
    g_frac[pos] = f;
}

// ---------------- per-layer table (bf16 interleaved lo/hi pairs) ----------------
__global__ void build_tab_kernel(const float* __restrict__ Wl) {
    __shared__ float gs0[EDGE_D], gs1[EDGE_D];
    const float* W3 = Wl + 256 * 256;
    int t = blockIdx.x;                   // 0..N_T-2
    float d0 = (float)t * H_T;
    float d1 = (float)(t + 1) * H_T;
    const float coeff = -0.5f / (DELTA * DELTA);
    if (threadIdx.x < EDGE_D) {
        float u0 = d0 - (float)threadIdx.x * DELTA;
        float u1 = d1 - (float)threadIdx.x * DELTA;
        gs0[threadIdx.x] = expf(coeff * u0 * u0);
        gs1[threadIdx.x] = expf(coeff * u1 * u1);
    }
    __syncthreads();
    int c = threadIdx.x;
    float a0 = 0.f, a1 = 0.f;
#pragma unroll 4
    for (int k = 0; k < EDGE_D; k++) {
        float w = W3[k * 256 + c];
        a0 += gs0[k] * w;
        a1 += gs1[k] * w;
    }
    __nv_bfloat162 p = __floats2bfloat162_rn(a0, a1);
    *(__nv_bfloat162*)(g_tab2 + (size_t)t * 512 + 2 * c) = p;
}

// ---------------- AB GEMM with packed f32x2 FMA ----------------
// cols 0..255 (rows 0..127 of W, dst part, +bias -> g_A fp32)
// cols 256..511 (rows 128..255, src part -> g_Bh bf16)
#define GM 64
#define GN 64
#define GK 16
__global__ void gemm_ab_kernel(const float* __restrict__ Wl,
                               const float* __restrict__ bias) {
    __shared__ float As2[GK][2 * GM];   // duplicated: As2[k][2m]=As2[k][2m+1]=x
    __shared__ float Bs[GK][GN];
    int tid = threadIdx.x;
    int colbase = blockIdx.x * GN;
    int half = (colbase >= 256) ? 1 : 0;
    const float* W = Wl + (half ? 128 * 256 : 0);
    int wcol = colbase & 255;
    int row0 = blockIdx.y * GM;

    int lm = tid >> 2;                  // 0..63  A loader row
    int lk = (tid & 3) * 4;             // A loader k offset
    int br = tid >> 4;                  // 0..15  B loader k
    int bc = (tid & 15) * 4;            // B loader col

    int ty = tid >> 4, tx = tid & 15;   // compute: rows 4ty.., cols 4tx..
    unsigned long long acc[4][2] = {};

    for (int k0 = 0; k0 < NODE_D; k0 += GK) {
        int arow = row0 + lm;
        float4 av = make_float4(0.f, 0.f, 0.f, 0.f);
        if (arow < N_NODES) av = *(const float4*)(g_x + (size_t)arow * NODE_D + k0 + lk);
        As2[lk + 0][2 * lm] = av.x; As2[lk + 0][2 * lm + 1] = av.x;
        As2[lk + 1][2 * lm] = av.y; As2[lk + 1][2 * lm + 1] = av.y;
        As2[lk + 2][2 * lm] = av.z; As2[lk + 2][2 * lm + 1] = av.z;
        As2[lk + 3][2 * lm] = av.w; As2[lk + 3][2 * lm + 1] = av.w;
        *(float4*)&Bs[br][bc] = *(const float4*)(W + (size_t)(k0 + br) * 256 + wcol + bc);
        __syncthreads();
#pragma unroll
        for (int k = 0; k < GK; k++) {
            ulonglong2 a0 = *(const ulonglong2*)&As2[k][8 * ty];      // rows 4ty,4ty+1 (dup pairs)
            ulonglong2 a1 = *(const ulonglong2*)&As2[k][8 * ty + 4];  // rows 4ty+2,4ty+3
            ulonglong2 bv = *(const ulonglong2*)&Bs[k][4 * tx];       // (c0,c1),(c2,c3)
            ffma2(acc[0][0], a0.x, bv.x); ffma2(acc[0][1], a0.x, bv.y);
            ffma2(acc[1][0], a0.y, bv.x); ffma2(acc[1][1], a0.y, bv.y);
            ffma2(acc[2][0], a1.x, bv.x); ffma2(acc[2][1], a1.x, bv.y);
            ffma2(acc[3][0], a1.y, bv.x); ffma2(acc[3][1], a1.y, bv.y);
        }
        __syncthreads();
    }

    int cg = colbase + tx * 4;
    if (!half) {
        float4 bv = *(const float4*)(bias + cg);
#pragma unroll
        for (int r = 0; r < 4; r++) {
            int row = row0 + ty * 4 + r;
            if (row < N_NODES) {
                float4 o = make_float4(f2lo(acc[r][0]) + bv.x, f2hi(acc[r][0]) + bv.y,
                                       f2lo(acc[r][1]) + bv.z, f2hi(acc[r][1]) + bv.w);
                *(float4*)(g_A + (size_t)row * 256 + cg) = o;
            }
        }
    } else {
        int cb = cg - 256;
#pragma unroll
        for (int r = 0; r < 4; r++) {
            int row = row0 + ty * 4 + r;
            if (row < N_NODES) {
                __nv_bfloat162 p0 = __floats2bfloat162_rn(f2lo(acc[r][0]), f2hi(acc[r][0]));
                __nv_bfloat162 p1 = __floats2bfloat162_rn(f2lo(acc[r][1]), f2hi(acc[r][1]));
                uint2 o;
                o.x = *(unsigned*)&p0;
                o.y = *(unsigned*)&p1;
                *(uint2*)(g_Bh + (size_t)row * 256 + cb) = o;
            }
        }
    }
}

// ---------------- fused edge aggregation + LN + residual + softplus ----------------
__global__ void edge_agg_kernel(const float* __restrict__ lng,
                                const float* __restrict__ lnb) {
    int n = blockIdx.x * 8 + (threadIdx.x >> 5);
    if (n >= N_NODES) return;
    int lane = threadIdx.x & 31;

    int row = g_rowstart[n];
    int end = g_rowstart[n + 1];

    const float4* Arow = (const float4*)(g_A + (size_t)n * 256);
    float4 a1 = Arow[lane];        // cols 4l..4l+3   (z1 incl bias)
    float4 a2 = Arow[32 + lane];   // cols 128+4l..   (z2)

    float4 acc = make_float4(0.f, 0.f, 0.f, 0.f);

    for (int e = row; e < end; e++) {
        int   s = __ldg(&g_srcs[e]);
        int   t = __ldg(&g_tidx[e]);
        float f = __ldg(&g_frac[e]);

        const __nv_bfloat16* Bb = g_Bh + (size_t)s * 256;
        uint2 b1u = *(const uint2*)(Bb + 4 * lane);
        uint2 b2u = *(const uint2*)(Bb + 128 + 4 * lane);
        float2 b1a = __bfloat1622float2(*(__nv_bfloat162*)&b1u.x);
        float2 b1b = __bfloat1622float2(*(__nv_bfloat162*)&b1u.y);
        float2 b2a = __bfloat1622float2(*(__nv_bfloat162*)&b2u.x);
        float2 b2b = __bfloat1622float2(*(__nv_bfloat162*)&b2u.y);

        const __nv_bfloat16* Tp = g_tab2 + (size_t)t * 512;
        uint4 t1u = *(const uint4*)(Tp + 8 * lane);          // 4 channels (lo,hi) each
        uint4 t2u = *(const uint4*)(Tp + 256 + 8 * lane);

        float2 w10 = __bfloat1622float2(*(__nv_bfloat162*)&t1u.x);
        float2 w11 = __bfloat1622float2(*(__nv_bfloat162*)&t1u.y);
        float2 w12 = __bfloat1622float2(*(__nv_bfloat162*)&t1u.z);
        float2 w13 = __bfloat1622float2(*(__nv_bfloat162*)&t1u.w);
        float2 w20 = __bfloat1622float2(*(__nv_bfloat162*)&t2u.x);
        float2 w21 = __bfloat1622float2(*(__nv_bfloat162*)&t2u.y);
        float2 w22 = __bfloat1622float2(*(__nv_bfloat162*)&t2u.z);
        float2 w23 = __bfloat1622float2(*(__nv_bfloat162*)&t2u.w);

        float4 z1, z2;
        z1.x = a1.x + b1a.x + w10.x + f * (w10.y - w10.x);
        z1.y = a1.y + b1a.y + w11.x + f * (w11.y - w11.x);
        z1.z = a1.z + b1b.x + w12.x + f * (w12.y - w12.x);
        z1.w = a1.w + b1b.y + w13.x + f * (w13.y - w13.x);
        z2.x = a2.x + b2a.x + w20.x + f * (w20.y - w20.x);
        z2.y = a2.y + b2a.y + w21.x + f * (w21.y - w21.x);
        z2.z = a2.z + b2b.x + w22.x + f * (w22.y - w22.x);
        z2.w = a2.w + b2b.y + w23.x + f * (w23.y - w23.x);

        acc.x += sigmoidf(z1.x) * softplusf(z2.x);
        acc.y += sigmoidf(z1.y) * softplusf(z2.y);
        acc.z += sigmoidf(z1.z) * softplusf(z2.z);
        acc.w += sigmoidf(z1.w) * softplusf(z2.w);
    }

    float s  = acc.x + acc.y + acc.z + acc.w;
    float ss = acc.x * acc.x + acc.y * acc.y + acc.z * acc.z + acc.w * acc.w;
#pragma unroll
    for (int off = 16; off > 0; off >>= 1) {
        s  += __shfl_xor_sync(0xffffffffu, s, off);
        ss += __shfl_xor_sync(0xffffffffu, ss, off);
    }
    float mu = s * (1.f / 128.f);
    float var = ss * (1.f / 128.f) - mu * mu;
    float rinv = rsqrtf(var + 1e-5f);

    float4 gg = ((const float4*)lng)[lane];
    float4 bb = ((const float4*)lnb)[lane];
    float4 xo = ((float4*)g_x)[(size_t)n * 32 + lane];
    float4 o;
    o.x = softplusf((acc.x - mu) * rinv * gg.x + bb.x + xo.x);
    o.y = softplusf((acc.y - mu) * rinv * gg.y + bb.y + xo.y);
    o.z = softplusf((acc.z - mu) * rinv * gg.z + bb.z + xo.z);
    o.w = softplusf((acc.w - mu) * rinv * gg.w + bb.w + xo.w);
    ((float4*)g_x)[(size_t)n * 32 + lane] = o;
}

// ---------------- mean pool ----------------
__global__ void pool_kernel(const int* __restrict__ batch) {
    int n = blockIdx.x * 8 + (threadIdx.x >> 5);
    if (n >= N_NODES) return;
    int lane = threadIdx.x & 31;
    int b = 0;
    if (lane == 0) b = batch[n];
    b = __shfl_sync(0xffffffffu, b, 0);
    float4 v = ((const float4*)g_x)[(size_t)n * 32 + lane];
    float* base = g_pool + (size_t)b * NODE_D + 4 * lane;
    atomicAdd(base + 0, v.x);
    atomicAdd(base + 1, v.y);
    atomicAdd(base + 2, v.z);
    atomicAdd(base + 3, v.w);
    if (lane == 0) atomicAdd(g_cnt + b, 1.f);
}

// ---------------- head MLP ----------------
__global__ void head_kernel(const float* __restrict__ cfc_w, const float* __restrict__ cfc_b,
                            const float* __restrict__ fc_w,  const float* __restrict__ fc_b,
                            const float* __restrict__ out_w, const float* __restrict__ out_b,
                            float* __restrict__ out) {
    __shared__ float h0[FC_D], h1[FC_D];
    __shared__ float red[4];
    int g = blockIdx.x, c = threadIdx.x;
    float cn = fmaxf(g_cnt[g], 1.f);
    h0[c] = g_pool[(size_t)g * NODE_D + c] / cn;
    __syncthreads();
    float acc = cfc_b[c];
#pragma unroll 4
    for (int k = 0; k < NODE_D; k++) acc += h0[k] * cfc_w[k * FC_D + c];
    h1[c] = softplusf(acc);
    __syncthreads();
    acc = fc_b[c];
#pragma unroll 4
    for (int k = 0; k < FC_D; k++) acc += h1[k] * fc_w[k * FC_D + c];
    h0[c] = softplusf(acc);
    __syncthreads();
    acc = fc_b[FC_D + c];
#pragma unroll 4
    for (int k = 0; k < FC_D; k++) acc += h0[k] * fc_w[FC_D * FC_D + k * FC_D + c];
    h1[c] = softplusf(acc);
    __syncthreads();
    float p = h1[c] * out_w[c];
#pragma unroll
    for (int off = 16; off > 0; off >>= 1) p += __shfl_xor_sync(0xffffffffu, p, off);
    if ((c & 31) == 0) red[c >> 5] = p;
    __syncthreads();
    if (c == 0) out[g] = red[0] + red[1] + red[2] + red[3] + out_b[0];
}

// ---------------- launch ----------------
extern "C" void kernel_launch(void* const* d_in, const int* in_sizes, int n_in,
                              void* d_out, int out_size) {
    const int*   z         = (const int*)d_in[0];
    const float* R         = (const float*)d_in[1];
    const int*   ei        = (const int*)d_in[2];
    const int*   batch     = (const int*)d_in[3];
    const float* embedding = (const float*)d_in[4];
    const float* emb_w     = (const float*)d_in[5];
    const float* emb_b     = (const float*)d_in[6];
    const float* conv_w    = (const float*)d_in[7];
    const float* conv_b    = (const float*)d_in[8];
    const float* ln_g      = (const float*)d_in[9];
    const float* ln_b      = (const float*)d_in[10];
    const float* cfc_w     = (const float*)d_in[11];
    const float* cfc_b     = (const float*)d_in[12];
    const float* fc_w      = (const float*)d_in[13];
    const float* fc_b      = (const float*)d_in[14];
    const float* out_w     = (const float*)d_in[15];
    const float* out_b     = (const float*)d_in[16];
    float* out = (float*)d_out;

    const int* src = ei;
    const int* dst = ei + N_EDGES;

    zero_misc_kernel<<<(N_GRAPHS * NODE_D + 255) / 256 + 200, 256>>>();
    embed_kernel<<<N_NODES, NODE_D>>>(z, embedding, emb_w, emb_b);
    hist_kernel<<<(N_EDGES + 255) / 256, 256>>>(dst);
    scan_pass1<<<SGRID, SB>>>();
    scan_pass2<<<1, SB>>>();
    scan_pass3<<<SGRID, SB>>>();
    scatter_kernel<<<(N_EDGES + 255) / 256, 256>>>(R, src, dst);

    for (int l = 0; l < N_CONV; l++) {
        const float* Wl = conv_w + (size_t)l * 356 * 256;
        const float* bl = conv_b + (size_t)l * 256;
        build_tab_kernel<<<N_T - 1, 256>>>(Wl);
        dim3 ggrid(512 / GN, (N_NODES + GM - 1) / GM);
        gemm_ab_kernel<<<ggrid, 256>>>(Wl, bl);
        edge_agg_kernel<<<(N_NODES + 7) / 8, 256>>>(ln_g + l * NODE_D, ln_b + l * NODE_D);
    }

    pool_kernel<<<(N_NODES + 7) / 8, 256>>>(batch);
    head_kernel<<<N_GRAPHS, FC_D>>>(cfc_w, cfc_b, fc_w, fc_b, out_w, out_b, out);
}

// round 7
// speedup vs baseline: 1.4101x; 1.4101x over previous
#include <cuda_runtime.h>
#include <math.h>

#define N_NODES  50000
#define N_EDGES  800000
#define NODE_D   128
#define EDGE_D   100
#define EMB_D    92
#define N_GRAPHS 256
#define N_CONV   3
#define FC_D     128

#define DELTA    (6.0f / 99.0f)
#define N_T      1800
#define H_T      (DELTA / 16.0f)

#define SB    256
#define SGRID ((N_NODES + SB - 1) / SB)

// ---------------- scratch (device globals) ----------------
__device__ float g_x[N_NODES * NODE_D];
__device__ float g_AB[N_NODES * 512];
__device__ float g_tab[N_T * 256];
__device__ int   g_deg[N_NODES];
__device__ int   g_off[N_NODES];
__device__ int   g_rowstart[N_NODES + 1];
__device__ int   g_bsum[SGRID];
__device__ int   g_srcs[N_EDGES];
__device__ int   g_tidx[N_EDGES];
__device__ float g_frac[N_EDGES];
__device__ float g_pool[N_GRAPHS * NODE_D];
__device__ float g_cnt[N_GRAPHS];

// ---------------- fast activations (MUFU-based) ----------------
__device__ __forceinline__ float softplusf(float x) {
    // max(x,0) + log(1 + exp(-|x|)); __expf/__logf -> MUFU EX2/LG2
    return fmaxf(x, 0.f) + __logf(1.f + __expf(-fabsf(x)));
}
__device__ __forceinline__ float sigmoidf(float x) {
    return __fdividef(1.f, 1.f + __expf(-x));
}

// ---------------- zero ----------------
__global__ void zero_misc_kernel() {
    int i = blockIdx.x * blockDim.x + threadIdx.x;
    if (i < N_NODES) g_deg[i] = 0;
    if (i < N_GRAPHS * NODE_D) g_pool[i] = 0.f;
    if (i < N_GRAPHS) g_cnt[i] = 0.f;
}

// ---------------- x0 = embedding[z] @ emb_w + emb_b ----------------
__global__ void embed_kernel(const int* __restrict__ z,
                             const float* __restrict__ emb,
                             const float* __restrict__ W,
                             const float* __restrict__ b) {
    __shared__ float er[EMB_D];
    int n = blockIdx.x;
    int zi = z[n];
    if (threadIdx.x < EMB_D) er[threadIdx.x] = emb[zi * EMB_D + threadIdx.x];
    __syncthreads();
    int c = threadIdx.x;
    float acc = b[c];
#pragma unroll 4
    for (int k = 0; k < EMB_D; k++) acc += er[k] * W[k * NODE_D + c];
    g_x[(size_t)n * NODE_D + c] = acc;
}

// ---------------- counting sort by dst ----------------
__global__ void hist_kernel(const int* __restrict__ dst) {
    int e = blockIdx.x * blockDim.x + threadIdx.x;
    if (e < N_EDGES) atomicAdd(&g_deg[dst[e]], 1);
}

__global__ void scan_pass1() {
    __shared__ int ws[8];
    int i = blockIdx.x * SB + threadIdx.x;
    int v = (i < N_NODES) ? g_deg[i] : 0;
#pragma unroll
    for (int off = 16; off > 0; off >>= 1) v += __shfl_xor_sync(0xffffffffu, v, off);
    if ((threadIdx.x & 31) == 0) ws[threadIdx.x >> 5] = v;
    __syncthreads();
    if (threadIdx.x == 0) {
        int s = 0;
#pragma unroll
        for (int w = 0; w < 8; w++) s += ws[w];
        g_bsum[blockIdx.x] = s;
    }
}

__global__ void scan_pass2() {   // 1 block, 256 threads, SGRID <= 256
    __shared__ int sm[SB];
    int t = threadIdx.x;
    int v = (t < SGRID) ? g_bsum[t] : 0;
    sm[t] = v;
    __syncthreads();
#pragma unroll
    for (int off = 1; off < SB; off <<= 1) {
        int u = (t >= off) ? sm[t - off] : 0;
        __syncthreads();
        sm[t] += u;
        __syncthreads();
    }
    if (t < SGRID) g_bsum[t] = sm[t] - v;   // exclusive
}

__global__ void scan_pass3() {
    __shared__ int sm[SB];
    int t = threadIdx.x;
    int i = blockIdx.x * SB + t;
    int v = (i < N_NODES) ? g_deg[i] : 0;
    sm[t] = v;
    __syncthreads();
#pragma unroll
    for (int off = 1; off < SB; off <<= 1) {
        int u = (t >= off) ? sm[t - off] : 0;
        __syncthreads();
        sm[t] += u;
        __syncthreads();
    }
    int ex = g_bsum[blockIdx.x] + sm[t] - v;
    if (i < N_NODES) {
        g_rowstart[i] = ex;
        g_off[i] = ex;
        if (i == N_NODES - 1) g_rowstart[N_NODES] = ex + v;
    }
}

__global__ void scatter_kernel(const float* __restrict__ R,
                               const int* __restrict__ src,
                               const int* __restrict__ dst) {
    int e = blockIdx.x * blockDim.x + threadIdx.x;
    if (e >= N_EDGES) return;
    int s = src[e], d = dst[e];
    float dx = R[s * 3 + 0] - R[d * 3 + 0];
    float dy = R[s * 3 + 1] - R[d * 3 + 1];
    float dz = R[s * 3 + 2] - R[d * 3 + 2];
    float dist = sqrtf(dx * dx + dy * dy + dz * dz);
    float u = fminf(dist / H_T, (float)(N_T - 2));
    int   t = (int)u;
    float f = u - (float)t;
    int pos = atomicAdd(&g_off[d], 1);
    g_srcs[pos] = s;
    g_tidx[pos] = t;
    g_frac[pos] = f;
}

// ---------------- per-layer table: T[t] = gaussians(t*h) @ W3 (fp32) ----------------
__global__ void build_tab_kernel(const float* __restrict__ Wl) {
    __shared__ float gs[EDGE_D];
    const float* W3 = Wl + 256 * 256;
    int t = blockIdx.x;
    float d = (float)t * H_T;
    const float coeff = -0.5f / (DELTA * DELTA);
    if (threadIdx.x < EDGE_D) {
        float u = d - (float)threadIdx.x * DELTA;
        gs[threadIdx.x] = expf(coeff * u * u);
    }
    __syncthreads();
    int c = threadIdx.x;
    float acc = 0.f;
#pragma unroll 4
    for (int k = 0; k < EDGE_D; k++) acc += gs[k] * W3[k * 256 + c];
    g_tab[(size_t)t * 256 + c] = acc;
}

// ---------------- AB = x @ [W1 | W2] (+bias on first 256 cols) — proven scalar ----------------
#define GM 64
#define GN 64
#define GK 16
__global__ void gemm_ab_kernel(const float* __restrict__ Wl,
                               const float* __restrict__ bias) {
    __shared__ float As[GK][GM];
    __shared__ float Bs[GK][GN];
    int tid = threadIdx.x;
    int bn = blockIdx.x;
    int bm = blockIdx.y;
    int colbase = bn * GN;
    int half = (colbase >= 256) ? 1 : 0;
    const float* W = Wl + (half ? 128 * 256 : 0);
    int wcol = colbase & 255;
    int row0 = bm * GM;

    int lr = tid >> 2;
    int lk = (tid & 3) * 4;
    int br = tid >> 4;
    int bc = (tid & 15) * 4;

    int ty = tid >> 4, tx = tid & 15;
    float acc[4][4] = {};

    for (int k0 = 0; k0 < NODE_D; k0 += GK) {
        int arow = row0 + lr;
        float4 av = make_float4(0.f, 0.f, 0.f, 0.f);
        if (arow < N_NODES) av = *(const float4*)(g_x + (size_t)arow * NODE_D + k0 + lk);
        As[lk + 0][lr] = av.x; As[lk + 1][lr] = av.y;
        As[lk + 2][lr] = av.z; As[lk + 3][lr] = av.w;
        float4 bv = *(const float4*)(W + (size_t)(k0 + br) * 256 + wcol + bc);
        *(float4*)&Bs[br][bc] = bv;
        __syncthreads();
#pragma unroll
        for (int k = 0; k < GK; k++) {
            float4 a = *(float4*)&As[k][ty * 4];
            float4 b = *(float4*)&Bs[k][tx * 4];
            acc[0][0] += a.x * b.x; acc[0][1] += a.x * b.y; acc[0][2] += a.x * b.z; acc[0][3] += a.x * b.w;
            acc[1][0] += a.y * b.x; acc[1][1] += a.y * b.y; acc[1][2] += a.y * b.z; acc[1][3] += a.y * b.w;
            acc[2][0] += a.z * b.x; acc[2][1] += a.z * b.y; acc[2][2] += a.z * b.z; acc[2][3] += a.z * b.w;
            acc[3][0] += a.w * b.x; acc[3][1] += a.w * b.y; acc[3][2] += a.w * b.z; acc[3][3] += a.w * b.w;
        }
        __syncthreads();
    }
    int cg = colbase + tx * 4;
    float4 bv = make_float4(0.f, 0.f, 0.f, 0.f);
    if (!half) bv = *(const float4*)(bias + cg);
#pragma unroll
    for (int i = 0; i < 4; i++) {
        int r = row0 + ty * 4 + i;
        if (r < N_NODES) {
            float4 o = make_float4(acc[i][0] + bv.x, acc[i][1] + bv.y,
                                   acc[i][2] + bv.z, acc[i][3] + bv.w);
            *(float4*)(g_AB + (size_t)r * 512 + cg) = o;
        }
    }
}

// ---------------- fused edge aggregation + LN + residual + softplus (fp32) ----------------
__global__ void edge_agg_kernel(const float* __restrict__ lng,
                                const float* __restrict__ lnb) {
    int n = blockIdx.x * 8 + (threadIdx.x >> 5);
    if (n >= N_NODES) return;
    int lane = threadIdx.x & 31;

    int row = g_rowstart[n];
    int end = g_rowstart[n + 1];

    const float4* Arow = (const float4*)(g_AB + (size_t)n * 512);
    float4 a1 = Arow[lane];        // z1 part incl bias
    float4 a2 = Arow[32 + lane];   // z2 part

    float4 acc = make_float4(0.f, 0.f, 0.f, 0.f);

    for (int e = row; e < end; e++) {
        int   s = __ldg(&g_srcs[e]);
        int   t = __ldg(&g_tidx[e]);
        float f = __ldg(&g_frac[e]);

        const float4* Brow = (const float4*)(g_AB + (size_t)s * 512 + 256);
        float4 b1 = Brow[lane];
        float4 b2 = Brow[32 + lane];
        const float4* Tlo = (const float4*)(g_tab + (size_t)t * 256);
        const float4* Thi = (const float4*)(g_tab + (size_t)(t + 1) * 256);
        float4 w1l = Tlo[lane],      w1h = Thi[lane];
        float4 w2l = Tlo[32 + lane], w2h = Thi[32 + lane];

        float4 z1, z2;
        z1.x = a1.x + b1.x + w1l.x + f * (w1h.x - w1l.x);
        z1.y = a1.y + b1.y + w1l.y + f * (w1h.y - w1l.y);
        z1.z = a1.z + b1.z + w1l.z + f * (w1h.z - w1l.z);
        z1.w = a1.w + b1.w + w1l.w + f * (w1h.w - w1l.w);
        z2.x = a2.x + b2.x + w2l.x + f * (w2h.x - w2l.x);
        z2.y = a2.y + b2.y + w2l.y + f * (w2h.y - w2l.y);
        z2.z = a2.z + b2.z + w2l.z + f * (w2h.z - w2l.z);
        z2.w = a2.w + b2.w + w2l.w + f * (w2h.w - w2l.w);

        acc.x += sigmoidf(z1.x) * softplusf(z2.x);
        acc.y += sigmoidf(z1.y) * softplusf(z2.y);
        acc.z += sigmoidf(z1.z) * softplusf(z2.z);
        acc.w += sigmoidf(z1.w) * softplusf(z2.w);
    }

    float s  = acc.x + acc.y + acc.z + acc.w;
    float ss = acc.x * acc.x + acc.y * acc.y + acc.z * acc.z + acc.w * acc.w;
#pragma unroll
    for (int off = 16; off > 0; off >>= 1) {
        s  += __shfl_xor_sync(0xffffffffu, s, off);
        ss += __shfl_xor_sync(0xffffffffu, ss, off);
    }
    float mu = s * (1.f / 128.f);
    float var = ss * (1.f / 128.f) - mu * mu;
    float rinv = rsqrtf(var + 1e-5f);

    float4 gg = ((const float4*)lng)[lane];
    float4 bb = ((const float4*)lnb)[lane];
    float4 xo = ((float4*)g_x)[(size_t)n * 32 + lane];
    float4 o;
    o.x = softplusf((acc.x - mu) * rinv * gg.x + bb.x + xo.x);
    o.y = softplusf((acc.y - mu) * rinv * gg.y + bb.y + xo.y);
    o.z = softplusf((acc.z - mu) * rinv * gg.z + bb.z + xo.z);
    o.w = softplusf((acc.w - mu) * rinv * gg.w + bb.w + xo.w);
    ((float4*)g_x)[(size_t)n * 32 + lane] = o;
}

// ---------------- mean pool ----------------
__global__ void pool_kernel(const int* __restrict__ batch) {
    int n = blockIdx.x * 8 + (threadIdx.x >> 5);
    if (n >= N_NODES) return;
    int lane = threadIdx.x & 31;
    int b = 0;
    if (lane == 0) b = batch[n];
    b = __shfl_sync(0xffffffffu, b, 0);
    float4 v = ((const float4*)g_x)[(size_t)n * 32 + lane];
    float* base = g_pool + (size_t)b * NODE_D + 4 * lane;
    atomicAdd(base + 0, v.x);
    atomicAdd(base + 1, v.y);
    atomicAdd(base + 2, v.z);
    atomicAdd(base + 3, v.w);
    if (lane == 0) atomicAdd(g_cnt + b, 1.f);
}

// ---------------- head MLP ----------------
__global__ void head_kernel(const float* __restrict__ cfc_w, const float* __restrict__ cfc_b,
                            const float* __restrict__ fc_w,  const float* __restrict__ fc_b,
                            const float* __restrict__ out_w, const float* __restrict__ out_b,
                            float* __restrict__ out) {
    __shared__ float h0[FC_D], h1[FC_D];
    __shared__ float red[4];
    int g = blockIdx.x, c = threadIdx.x;
    float cn = fmaxf(g_cnt[g], 1.f);
    h0[c] = g_pool[(size_t)g * NODE_D + c] / cn;
    __syncthreads();
    float acc = cfc_b[c];
#pragma unroll 4
    for (int k = 0; k < NODE_D; k++) acc += h0[k] * cfc_w[k * FC_D + c];
    h1[c] = softplusf(acc);
    __syncthreads();
    acc = fc_b[c];
#pragma unroll 4
    for (int k = 0; k < FC_D; k++) acc += h1[k] * fc_w[k * FC_D + c];
    h0[c] = softplusf(acc);
    __syncthreads();
    acc = fc_b[FC_D + c];
#pragma unroll 4
    for (int k = 0; k < FC_D; k++) acc += h0[k] * fc_w[FC_D * FC_D + k * FC_D + c];
    h1[c] = softplusf(acc);
    __syncthreads();
    float p = h1[c] * out_w[c];
#pragma unroll
    for (int off = 16; off > 0; off >>= 1) p += __shfl_xor_sync(0xffffffffu, p, off);
    if ((c & 31) == 0) red[c >> 5] = p;
    __syncthreads();
    if (c == 0) out[g] = red[0] + red[1] + red[2] + red[3] + out_b[0];
}

// ---------------- launch ----------------
extern "C" void kernel_launch(void* const* d_in, const int* in_sizes, int n_in,
                              void* d_out, int out_size) {
    const int*   z         = (const int*)d_in[0];
    const float* R         = (const float*)d_in[1];
    const int*   ei        = (const int*)d_in[2];
    const int*   batch     = (const int*)d_in[3];
    const float* embedding = (const float*)d_in[4];
    const float* emb_w     = (const float*)d_in[5];
    const float* emb_b     = (const float*)d_in[6];
    const float* conv_w    = (const float*)d_in[7];
    const float* conv_b    = (const float*)d_in[8];
    const float* ln_g      = (const float*)d_in[9];
    const float* ln_b      = (const float*)d_in[10];
    const float* cfc_w     = (const float*)d_in[11];
    const float* cfc_b     = (const float*)d_in[12];
    const float* fc_w      = (const float*)d_in[13];
    const float* fc_b      = (const float*)d_in[14];
    const float* out_w     = (const float*)d_in[15];
    const float* out_b     = (const float*)d_in[16];
    float* out = (float*)d_out;

    const int* src = ei;
    const int* dst = ei + N_EDGES;

    zero_misc_kernel<<<SGRID, SB>>>();
    embed_kernel<<<N_NODES, NODE_D>>>(z, embedding, emb_w, emb_b);
    hist_kernel<<<(N_EDGES + 255) / 256, 256>>>(dst);
    scan_pass1<<<SGRID, SB>>>();
    scan_pass2<<<1, SB>>>();
    scan_pass3<<<SGRID, SB>>>();
    scatter_kernel<<<(N_EDGES + 255) / 256, 256>>>(R, src, dst);

    for (int l = 0; l < N_CONV; l++) {
        const float* Wl = conv_w + (size_t)l * 356 * 256;
        const float* bl = conv_b + (size_t)l * 256;
        build_tab_kernel<<<N_T, 256>>>(Wl);
        dim3 ggrid(512 / GN, (N_NODES + GM - 1) / GM);
        gemm_ab_kernel<<<ggrid, 256>>>(Wl, bl);
        edge_agg_kernel<<<(N_NODES + 7) / 8, 256>>>(ln_g + l * NODE_D, ln_b + l * NODE_D);
    }

    pool_kernel<<<(N_NODES + 7) / 8, 256>>>(batch);
    head_kernel<<<N_GRAPHS, FC_D>>>(cfc_w, cfc_b, fc_w, fc_b, out_w, out_b, out);
}

// round 8
// speedup vs baseline: 2.2392x; 1.5880x over previous
#include <cuda_runtime.h>
#include <cuda_bf16.h>
#include <math.h>

#define N_NODES  50000
#define N_EDGES  800000
#define NODE_D   128
#define EDGE_D   100
#define EMB_D    92
#define N_GRAPHS 256
#define N_CONV   3
#define FC_D     128

#define DELTA    (6.0f / 99.0f)
#define N_T      1800
#define H_T      (DELTA / 16.0f)

#define SB    256
#define SGRID ((N_NODES + SB - 1) / SB)

// ---------------- scratch (device globals) ----------------
__device__ float g_x[N_NODES * NODE_D];               // node features fp32
__device__ __nv_bfloat16 g_xh[N_NODES * NODE_D];      // bf16 copy for tensor GEMM
__device__ float g_A[N_NODES * 256];                  // dst part (fp32, incl bias)
__device__ __nv_bfloat16 g_Bh[N_NODES * 256];         // src part (bf16)
__device__ uint2 g_Wp[8 * 64 * 32];                   // packed bf16 weights (B frags)
__device__ __nv_bfloat16 g_tab2[N_T * 512];           // interleaved (lo,hi) bf16 pairs
__device__ int   g_deg[N_NODES];
__device__ int   g_off[N_NODES];
__device__ int   g_rowstart[N_NODES + 1];
__device__ int   g_bsum[SGRID];
__device__ int   g_srcs[N_EDGES];
__device__ int   g_tidx[N_EDGES];
__device__ float g_frac[N_EDGES];
__device__ float g_pool[N_GRAPHS * NODE_D];
__device__ float g_cnt[N_GRAPHS];

// ---------------- fast math helpers ----------------
__device__ __forceinline__ float softplusf(float x) {
    return fmaxf(x, 0.f) + __logf(1.f + __expf(-fabsf(x)));
}
__device__ __forceinline__ float sigmoid_tanh(float x) {
    float th;
    asm("tanh.approx.f32 %0, %1;" : "=f"(th) : "f"(0.5f * x));
    return fmaf(0.5f, th, 0.5f);
}
__device__ __forceinline__ float bflo(unsigned u) { return __uint_as_float(u << 16); }
__device__ __forceinline__ float bfhi(unsigned u) { return __uint_as_float(u & 0xffff0000u); }

__device__ __forceinline__ void mma_bf16(float* c, const unsigned* a, uint2 b) {
    asm volatile(
        "mma.sync.aligned.m16n8k16.row.col.f32.bf16.bf16.f32 "
        "{%0,%1,%2,%3}, {%4,%5,%6,%7}, {%8,%9}, {%0,%1,%2,%3};"
        : "+f"(c[0]), "+f"(c[1]), "+f"(c[2]), "+f"(c[3])
        : "r"(a[0]), "r"(a[1]), "r"(a[2]), "r"(a[3]), "r"(b.x), "r"(b.y));
}

// ---------------- zero ----------------
__global__ void zero_misc_kernel() {
    int i = blockIdx.x * blockDim.x + threadIdx.x;
    if (i < N_NODES) g_deg[i] = 0;
    if (i < N_GRAPHS * NODE_D) g_pool[i] = 0.f;
    if (i < N_GRAPHS) g_cnt[i] = 0.f;
}

// ---------------- x0 = embedding[z] @ emb_w + emb_b ----------------
__global__ void embed_kernel(const int* __restrict__ z,
                             const float* __restrict__ emb,
                             const float* __restrict__ W,
                             const float* __restrict__ b) {
    __shared__ float er[EMB_D];
    int n = blockIdx.x;
    int zi = z[n];
    if (threadIdx.x < EMB_D) er[threadIdx.x] = emb[zi * EMB_D + threadIdx.x];
    __syncthreads();
    int c = threadIdx.x;
    float acc = b[c];
#pragma unroll 4
    for (int k = 0; k < EMB_D; k++) acc += er[k] * W[k * NODE_D + c];
    g_x[(size_t)n * NODE_D + c] = acc;
}

// ---------------- counting sort by dst ----------------
__global__ void hist_kernel(const int* __restrict__ dst) {
    int e = blockIdx.x * blockDim.x + threadIdx.x;
    if (e < N_EDGES) atomicAdd(&g_deg[dst[e]], 1);
}

__global__ void scan_pass1() {
    __shared__ int ws[8];
    int i = blockIdx.x * SB + threadIdx.x;
    int v = (i < N_NODES) ? g_deg[i] : 0;
#pragma unroll
    for (int off = 16; off > 0; off >>= 1) v += __shfl_xor_sync(0xffffffffu, v, off);
    if ((threadIdx.x & 31) == 0) ws[threadIdx.x >> 5] = v;
    __syncthreads();
    if (threadIdx.x == 0) {
        int s = 0;
#pragma unroll
        for (int w = 0; w < 8; w++) s += ws[w];
        g_bsum[blockIdx.x] = s;
    }
}

__global__ void scan_pass2() {
    __shared__ int sm[SB];
    int t = threadIdx.x;
    int v = (t < SGRID) ? g_bsum[t] : 0;
    sm[t] = v;
    __syncthreads();
#pragma unroll
    for (int off = 1; off < SB; off <<= 1) {
        int u = (t >= off) ? sm[t - off] : 0;
        __syncthreads();
        sm[t] += u;
        __syncthreads();
    }
    if (t < SGRID) g_bsum[t] = sm[t] - v;
}

__global__ void scan_pass3() {
    __shared__ int sm[SB];
    int t = threadIdx.x;
    int i = blockIdx.x * SB + t;
    int v = (i < N_NODES) ? g_deg[i] : 0;
    sm[t] = v;
    __syncthreads();
#pragma unroll
    for (int off = 1; off < SB; off <<= 1) {
        int u = (t >= off) ? sm[t - off] : 0;
        __syncthreads();
        sm[t] += u;
        __syncthreads();
    }
    int ex = g_bsum[blockIdx.x] + sm[t] - v;
    if (i < N_NODES) {
        g_rowstart[i] = ex;
        g_off[i] = ex;
        if (i == N_NODES - 1) g_rowstart[N_NODES] = ex + v;
    }
}

__global__ void scatter_kernel(const float* __restrict__ R,
                               const int* __restrict__ src,
                               const int* __restrict__ dst) {
    int e = blockIdx.x * blockDim.x + threadIdx.x;
    if (e >= N_EDGES) return;
    int s = src[e], d = dst[e];
    float dx = R[s * 3 + 0] - R[d * 3 + 0];
    float dy = R[s * 3 + 1] - R[d * 3 + 1];
    float dz = R[s * 3 + 2] - R[d * 3 + 2];
    float dist = sqrtf(dx * dx + dy * dy + dz * dz);
    float u = fminf(dist / H_T, (float)(N_T - 2));
    int   t = (int)u;
    float f = u - (float)t;
    int pos = atomicAdd(&g_off[d], 1);
    g_srcs[pos] = s;
    g_tidx[pos] = t;
    g_frac[pos] = f;
}

// ---------------- per-layer table: interleaved (lo,hi) bf16 pairs ----------------
__global__ void build_tab_kernel(const float* __restrict__ Wl) {
    __shared__ float gs0[EDGE_D], gs1[EDGE_D];
    const float* W3 = Wl + 256 * 256;
    int t = blockIdx.x;                   // 0..N_T-2
    float d0 = (float)t * H_T;
    float d1 = (float)(t + 1) * H_T;
    const float coeff = -0.5f / (DELTA * DELTA);
    if (threadIdx.x < EDGE_D) {
        float u0 = d0 - (float)threadIdx.x * DELTA;
        float u1 = d1 - (float)threadIdx.x * DELTA;
        gs0[threadIdx.x] = expf(coeff * u0 * u0);
        gs1[threadIdx.x] = expf(coeff * u1 * u1);
    }
    __syncthreads();
    int c = threadIdx.x;
    float a0 = 0.f, a1 = 0.f;
#pragma unroll 4
    for (int k = 0; k < EDGE_D; k++) {
        float w = W3[k * 256 + c];
        a0 += gs0[k] * w;
        a1 += gs1[k] * w;
    }
    __nv_bfloat162 p = __floats2bfloat162_rn(a0, a1);   // low=lo(t), high=hi(t+1)
    *(__nv_bfloat162*)(g_tab2 + (size_t)t * 512 + 2 * c) = p;
}

// ---------------- per-layer weight pack: B fragments for mma ----------------
// g_Wp[(kt*64 + ntile)*32 + lane] = {B[2u..2u+1][c], B[2u+8..2u+9][c]} bf16x2 pairs
__global__ void pack_w_kernel(const float* __restrict__ Wl) {
    int idx = blockIdx.x * 256 + threadIdx.x;
    if (idx >= 8 * 64 * 32) return;
    int lane = idx & 31;
    int ntile = (idx >> 5) & 63;
    int kt = idx >> 11;
    int u = lane & 3, c = lane >> 2;
    int n = ntile * 8 + c;                   // 0..511
    const float* W = Wl + ((n < 256) ? 0 : 128 * 256);
    int wc = n & 255;
    int k = kt * 16 + 2 * u;
    __nv_bfloat162 v0 = __floats2bfloat162_rn(W[(k + 0) * 256 + wc], W[(k + 1) * 256 + wc]);
    __nv_bfloat162 v1 = __floats2bfloat162_rn(W[(k + 8) * 256 + wc], W[(k + 9) * 256 + wc]);
    g_Wp[idx] = make_uint2(*(unsigned*)&v0, *(unsigned*)&v1);
}

// ---------------- convert x fp32 -> bf16 ----------------
__global__ void convert_x_kernel() {
    int i = blockIdx.x * blockDim.x + threadIdx.x;   // one per 4 elems
    if (i >= N_NODES * NODE_D / 4) return;
    float4 v = ((const float4*)g_x)[i];
    __nv_bfloat162 p0 = __floats2bfloat162_rn(v.x, v.y);
    __nv_bfloat162 p1 = __floats2bfloat162_rn(v.z, v.w);
    ((uint2*)g_xh)[i] = make_uint2(*(unsigned*)&p0, *(unsigned*)&p1);
}

// ---------------- tensor-core GEMM: AB = x @ [W1|W2] ----------------
// block: 256 thr (8 warps as 2x4), tile 64(m) x 256(n), K=128 full
#define TBM 64
__global__ void gemm_mma_kernel(const float* __restrict__ bias) {
    __shared__ __nv_bfloat16 As[TBM][136];   // +8 pad, conflict-free frag loads
    int tid = threadIdx.x;
    int m0 = blockIdx.y * TBM;
    int n0 = blockIdx.x * 256;               // 0 or 256

    // load A tile (64 x 128 bf16)
#pragma unroll
    for (int i = 0; i < 4; i++) {
        int idx = tid + i * 256;             // 0..1023 (16B segments)
        int r = idx >> 4, cs = idx & 15;
        uint4 v = make_uint4(0, 0, 0, 0);
        if (m0 + r < N_NODES) v = *(const uint4*)(g_xh + (size_t)(m0 + r) * NODE_D + cs * 8);
        *(uint4*)&As[r][cs * 8] = v;
    }
    __syncthreads();

    int wid = tid >> 5, lane = tid & 31;
    int wm = wid >> 2, wn = wid & 3;
    int g = lane >> 2, u = lane & 3;
    int mbase = wm * 32;
    int ntile0 = (n0 + wn * 64) >> 3;

    float acc[2][8][4];
#pragma unroll
    for (int a = 0; a < 2; a++)
#pragma unroll
        for (int b = 0; b < 8; b++)
#pragma unroll
            for (int c = 0; c < 4; c++) acc[a][b][c] = 0.f;

#pragma unroll
    for (int kt = 0; kt < 8; kt++) {
        int k0 = kt * 16;
        unsigned afr[2][4];
#pragma unroll
        for (int mf = 0; mf < 2; mf++) {
            int rb = mbase + mf * 16;
            afr[mf][0] = *(unsigned*)&As[rb + g][k0 + 2 * u];
            afr[mf][1] = *(unsigned*)&As[rb + g + 8][k0 + 2 * u];
            afr[mf][2] = *(unsigned*)&As[rb + g][k0 + 8 + 2 * u];
            afr[mf][3] = *(unsigned*)&As[rb + g + 8][k0 + 8 + 2 * u];
        }
        uint2 bfr[8];
#pragma unroll
        for (int j = 0; j < 8; j++)
            bfr[j] = g_Wp[(kt * 64 + ntile0 + j) * 32 + lane];
#pragma unroll
        for (int mf = 0; mf < 2; mf++)
#pragma unroll
            for (int j = 0; j < 8; j++)
                mma_bf16(acc[mf][j], afr[mf], bfr[j]);
    }

    // epilogue
#pragma unroll
    for (int mf = 0; mf < 2; mf++) {
        int row0 = m0 + mbase + mf * 16 + g;
#pragma unroll
        for (int j = 0; j < 8; j++) {
            int col = n0 + wn * 64 + j * 8 + 2 * u;   // global 0..511, even
            float* ac = acc[mf][j];
            if (n0 == 0) {
                float2 bv = *(const float2*)(bias + col);
                if (row0 < N_NODES)
                    *(float2*)(g_A + (size_t)row0 * 256 + col) =
                        make_float2(ac[0] + bv.x, ac[1] + bv.y);
                if (row0 + 8 < N_NODES)
                    *(float2*)(g_A + (size_t)(row0 + 8) * 256 + col) =
                        make_float2(ac[2] + bv.x, ac[3] + bv.y);
            } else {
                int cb = col - 256;
                if (row0 < N_NODES) {
                    __nv_bfloat162 p = __floats2bfloat162_rn(ac[0], ac[1]);
                    *(unsigned*)(g_Bh + (size_t)row0 * 256 + cb) = *(unsigned*)&p;
                }
                if (row0 + 8 < N_NODES) {
                    __nv_bfloat162 p = __floats2bfloat162_rn(ac[2], ac[3]);
                    *(unsigned*)(g_Bh + (size_t)(row0 + 8) * 256 + cb) = *(unsigned*)&p;
                }
            }
        }
    }
}

// ---------------- fused edge aggregation + LN + residual + softplus ----------------
__global__ void edge_agg_kernel(const float* __restrict__ lng,
                                const float* __restrict__ lnb) {
    int n = blockIdx.x * 8 + (threadIdx.x >> 5);
    if (n >= N_NODES) return;
    int lane = threadIdx.x & 31;

    int row = g_rowstart[n];
    int end = g_rowstart[n + 1];

    const float4* Arow = (const float4*)(g_A + (size_t)n * 256);
    float4 a1 = Arow[lane];        // z1 incl bias
    float4 a2 = Arow[32 + lane];   // z2

    float4 acc = make_float4(0.f, 0.f, 0.f, 0.f);

    for (int e = row; e < end; e++) {
        int   s = __ldg(&g_srcs[e]);
        int   t = __ldg(&g_tidx[e]);
        float f = __ldg(&g_frac[e]);

        const __nv_bfloat16* Bb = g_Bh + (size_t)s * 256;
        uint2 b1u = *(const uint2*)(Bb + 4 * lane);
        uint2 b2u = *(const uint2*)(Bb + 128 + 4 * lane);
        const __nv_bfloat16* Tp = g_tab2 + (size_t)t * 512;
        uint4 t1u = *(const uint4*)(Tp + 8 * lane);
        uint4 t2u = *(const uint4*)(Tp + 256 + 8 * lane);

        float4 z1, z2;
        {
            float lo, w;
            lo = bflo(t1u.x); w = fmaf(f, bfhi(t1u.x) - lo, lo);
            z1.x = a1.x + bflo(b1u.x) + w;
            lo = bflo(t1u.y); w = fmaf(f, bfhi(t1u.y) - lo, lo);
            z1.y = a1.y + bfhi(b1u.x) + w;
            lo = bflo(t1u.z); w = fmaf(f, bfhi(t1u.z) - lo, lo);
            z1.z = a1.z + bflo(b1u.y) + w;
            lo = bflo(t1u.w); w = fmaf(f, bfhi(t1u.w) - lo, lo);
            z1.w = a1.w + bfhi(b1u.y) + w;
            lo = bflo(t2u.x); w = fmaf(f, bfhi(t2u.x) - lo, lo);
            z2.x = a2.x + bflo(b2u.x) + w;
            lo = bflo(t2u.y); w = fmaf(f, bfhi(t2u.y) - lo, lo);
            z2.y = a2.y + bfhi(b2u.x) + w;
            lo = bflo(t2u.z); w = fmaf(f, bfhi(t2u.z) - lo, lo);
            z2.z = a2.z + bflo(b2u.y) + w;
            lo = bflo(t2u.w); w = fmaf(f, bfhi(t2u.w) - lo, lo);
            z2.w = a2.w + bfhi(b2u.y) + w;
        }

        acc.x = fmaf(sigmoid_tanh(z1.x), softplusf(z2.x), acc.x);
        acc.y = fmaf(sigmoid_tanh(z1.y), softplusf(z2.y), acc.y);
        acc.z = fmaf(sigmoid_tanh(z1.z), softplusf(z2.z), acc.z);
        acc.w = fmaf(sigmoid_tanh(z1.w), softplusf(z2.w), acc.w);
    }

    float s  = acc.x + acc.y + acc.z + acc.w;
    float ss = acc.x * acc.x + acc.y * acc.y + acc.z * acc.z + acc.w * acc.w;
#pragma unroll
    for (int off = 16; off > 0; off >>= 1) {
        s  += __shfl_xor_sync(0xffffffffu, s, off);
        ss += __shfl_xor_sync(0xffffffffu, ss, off);
    }
    float mu = s * (1.f / 128.f);
    float var = ss * (1.f / 128.f) - mu * mu;
    float rinv = rsqrtf(var + 1e-5f);

    float4 gg = ((const float4*)lng)[lane];
    float4 bb = ((const float4*)lnb)[lane];
    float4 xo = ((float4*)g_x)[(size_t)n * 32 + lane];
    float4 o;
    o.x = softplusf((acc.x - mu) * rinv * gg.x + bb.x + xo.x);
    o.y = softplusf((acc.y - mu) * rinv * gg.y + bb.y + xo.y);
    o.z = softplusf((acc.z - mu) * rinv * gg.z + bb.z + xo.z);
    o.w = softplusf((acc.w - mu) * rinv * gg.w + bb.w + xo.w);
    ((float4*)g_x)[(size_t)n * 32 + lane] = o;
}

// ---------------- mean pool ----------------
__global__ void pool_kernel(const int* __restrict__ batch) {
    int n = blockIdx.x * 8 + (threadIdx.x >> 5);
    if (n >= N_NODES) return;
    int lane = threadIdx.x & 31;
    int b = 0;
    if (lane == 0) b = batch[n];
    b = __shfl_sync(0xffffffffu, b, 0);
    float4 v = ((const float4*)g_x)[(size_t)n * 32 + lane];
    float* base = g_pool + (size_t)b * NODE_D + 4 * lane;
    atomicAdd(base + 0, v.x);
    atomicAdd(base + 1, v.y);
    atomicAdd(base + 2, v.z);
    atomicAdd(base + 3, v.w);
    if (lane == 0) atomicAdd(g_cnt + b, 1.f);
}

// ---------------- head MLP ----------------
__global__ void head_kernel(const float* __restrict__ cfc_w, const float* __restrict__ cfc_b,
                            const float* __restrict__ fc_w,  const float* __restrict__ fc_b,
                            const float* __restrict__ out_w, const float* __restrict__ out_b,
                            float* __restrict__ out) {
    __shared__ float h0[FC_D], h1[FC_D];
    __shared__ float red[4];
    int g = blockIdx.x, c = threadIdx.x;
    float cn = fmaxf(g_cnt[g], 1.f);
    h0[c] = g_pool[(size_t)g * NODE_D + c] / cn;
    __syncthreads();
    float acc = cfc_b[c];
#pragma unroll 4
    for (int k = 0; k < NODE_D; k++) acc += h0[k] * cfc_w[k * FC_D + c];
    h1[c] = softplusf(acc);
    __syncthreads();
    acc = fc_b[c];
#pragma unroll 4
    for (int k = 0; k < FC_D; k++) acc += h1[k] * fc_w[k * FC_D + c];
    h0[c] = softplusf(acc);
    __syncthreads();
    acc = fc_b[FC_D + c];
#pragma unroll 4
    for (int k = 0; k < FC_D; k++) acc += h0[k] * fc_w[FC_D * FC_D + k * FC_D + c];
    h1[c] = softplusf(acc);
    __syncthreads();
    float p = h1[c] * out_w[c];
#pragma unroll
    for (int off = 16; off > 0; off >>= 1) p += __shfl_xor_sync(0xffffffffu, p, off);
    if ((c & 31) == 0) red[c >> 5] = p;
    __syncthreads();
    if (c == 0) out[g] = red[0] + red[1] + red[2] + red[3] + out_b[0];
}

// ---------------- launch ----------------
extern "C" void kernel_launch(void* const* d_in, const int* in_sizes, int n_in,
                              void* d_out, int out_size) {
    const int*   z         = (const int*)d_in[0];
    const float* R         = (const float*)d_in[1];
    const int*   ei        = (const int*)d_in[2];
    const int*   batch     = (const int*)d_in[3];
    const float* embedding = (const float*)d_in[4];
    const float* emb_w     = (const float*)d_in[5];
    const float* emb_b     = (const float*)d_in[6];
    const float* conv_w    = (const float*)d_in[7];
    const float* conv_b    = (const float*)d_in[8];
    const float* ln_g      = (const float*)d_in[9];
    const float* ln_b      = (const float*)d_in[10];
    const float* cfc_w     = (const float*)d_in[11];
    const float* cfc_b     = (const float*)d_in[12];
    const float* fc_w      = (const float*)d_in[13];
    const float* fc_b      = (const float*)d_in[14];
    const float* out_w     = (const float*)d_in[15];
    const float* out_b     = (const float*)d_in[16];
    float* out = (float*)d_out;

    const int* src = ei;
    const int* dst = ei + N_EDGES;

    zero_misc_kernel<<<SGRID, SB>>>();
    embed_kernel<<<N_NODES, NODE_D>>>(z, embedding, emb_w, emb_b);
    hist_kernel<<<(N_EDGES + 255) / 256, 256>>>(dst);
    scan_pass1<<<SGRID, SB>>>();
    scan_pass2<<<1, SB>>>();
    scan_pass3<<<SGRID, SB>>>();
    scatter_kernel<<<(N_EDGES + 255) / 256, 256>>>(R, src, dst);

    for (int l = 0; l < N_CONV; l++) {
        const float* Wl = conv_w + (size_t)l * 356 * 256;
        const float* bl = conv_b + (size_t)l * 256;
        build_tab_kernel<<<N_T - 1, 256>>>(Wl);
        pack_w_kernel<<<64, 256>>>(Wl);
        convert_x_kernel<<<(N_NODES * NODE_D / 4 + 255) / 256, 256>>>();
        dim3 ggrid(2, (N_NODES + TBM - 1) / TBM);
        gemm_mma_kernel<<<ggrid, 256>>>(bl);
        edge_agg_kernel<<<(N_NODES + 7) / 8, 256>>>(ln_g + l * NODE_D, ln_b + l * NODE_D);
    }

    pool_kernel<<<(N_NODES + 7) / 8, 256>>>(batch);
    head_kernel<<<N_GRAPHS, FC_D>>>(cfc_w, cfc_b, fc_w, fc_b, out_w, out_b, out);
}

// round 10
// speedup vs baseline: 2.4006x; 1.0721x over previous
#include <cuda_runtime.h>
#include <cuda_bf16.h>
#include <math.h>

#define N_NODES  50000
#define N_EDGES  800000
#define NODE_D   128
#define EDGE_D   100
#define EMB_D    92
#define N_GRAPHS 256
#define N_CONV   3
#define FC_D     128

#define DELTA    (6.0f / 99.0f)
#define N_T      1800
#define H_T      (DELTA / 16.0f)
#define NTF      (16 * (N_T - 1))          // 28784 fine rows
#define H_F      (DELTA / 256.0f)

#define SB    256
#define SGRID ((N_NODES + SB - 1) / SB)

// ---------------- scratch (device globals) ----------------
__device__ float g_x[N_NODES * NODE_D];               // node features fp32
__device__ __nv_bfloat16 g_xh[N_NODES * NODE_D];      // bf16 copy for tensor GEMM
__device__ float g_A[N_NODES * 256];                  // dst part (fp32, incl bias)
__device__ __nv_bfloat16 g_Bh[N_NODES * 256];         // src part (bf16)
__device__ uint2 g_Wp[8 * 64 * 32];                   // packed bf16 weights (B frags)
__device__ float g_tab[N_T * 256];                    // coarse fp32 table (exact)
__device__ __nv_bfloat16 g_tabf[(size_t)NTF * 256];   // fine bf16 nearest table
__device__ int   g_deg[N_NODES];
__device__ int   g_off[N_NODES];
__device__ int   g_rowstart[N_NODES + 1];
__device__ int   g_bsum[SGRID];
__device__ uint2 g_edge[N_EDGES];                     // (src, t_fine)
__device__ float g_pool[N_GRAPHS * NODE_D];
__device__ float g_cnt[N_GRAPHS];

// ---------------- fast math helpers ----------------
__device__ __forceinline__ float softplusf(float x) {
    return fmaxf(x, 0.f) + __logf(1.f + __expf(-fabsf(x)));
}
__device__ __forceinline__ float sigmoid_tanh(float x) {
    float th;
    asm("tanh.approx.f32 %0, %1;" : "=f"(th) : "f"(0.5f * x));
    return fmaf(0.5f, th, 0.5f);
}
__device__ __forceinline__ float bflo(unsigned u) { return __uint_as_float(u << 16); }
__device__ __forceinline__ float bfhi(unsigned u) { return __uint_as_float(u & 0xffff0000u); }

__device__ __forceinline__ void mma_bf16(float* c, const unsigned* a, uint2 b) {
    asm volatile(
        "mma.sync.aligned.m16n8k16.row.col.f32.bf16.bf16.f32 "
        "{%0,%1,%2,%3}, {%4,%5,%6,%7}, {%8,%9}, {%0,%1,%2,%3};"
        : "+f"(c[0]), "+f"(c[1]), "+f"(c[2]), "+f"(c[3])
        : "r"(a[0]), "r"(a[1]), "r"(a[2]), "r"(a[3]), "r"(b.x), "r"(b.y));
}

// ---------------- zero ----------------
__global__ void zero_misc_kernel() {
    int i = blockIdx.x * blockDim.x + threadIdx.x;
    if (i < N_NODES) g_deg[i] = 0;
    if (i < N_GRAPHS * NODE_D) g_pool[i] = 0.f;
    if (i < N_GRAPHS) g_cnt[i] = 0.f;
}

// ---------------- x0 = embedding[z] @ emb_w + emb_b (writes fp32 + bf16) ----------------
__global__ void embed_kernel(const int* __restrict__ z,
                             const float* __restrict__ emb,
                             const float* __restrict__ W,
                             const float* __restrict__ b) {
    __shared__ float er[EMB_D];
    int n = blockIdx.x;
    int zi = z[n];
    if (threadIdx.x < EMB_D) er[threadIdx.x] = emb[zi * EMB_D + threadIdx.x];
    __syncthreads();
    int c = threadIdx.x;
    float acc = b[c];
#pragma unroll 4
    for (int k = 0; k < EMB_D; k++) acc += er[k] * W[k * NODE_D + c];
    g_x[(size_t)n * NODE_D + c] = acc;
    g_xh[(size_t)n * NODE_D + c] = __float2bfloat16(acc);
}

// ---------------- counting sort by dst ----------------
__global__ void hist_kernel(const int* __restrict__ dst) {
    int e = blockIdx.x * blockDim.x + threadIdx.x;
    if (e < N_EDGES) atomicAdd(&g_deg[dst[e]], 1);
}

__global__ void scan_pass1() {
    __shared__ int ws[8];
    int i = blockIdx.x * SB + threadIdx.x;
    int v = (i < N_NODES) ? g_deg[i] : 0;
#pragma unroll
    for (int off = 16; off > 0; off >>= 1) v += __shfl_xor_sync(0xffffffffu, v, off);
    if ((threadIdx.x & 31) == 0) ws[threadIdx.x >> 5] = v;
    __syncthreads();
    if (threadIdx.x == 0) {
        int s = 0;
#pragma unroll
        for (int w = 0; w < 8; w++) s += ws[w];
        g_bsum[blockIdx.x] = s;
    }
}

__global__ void scan_pass2() {
    __shared__ int sm[SB];
    int t = threadIdx.x;
    int v = (t < SGRID) ? g_bsum[t] : 0;
    sm[t] = v;
    __syncthreads();
#pragma unroll
    for (int off = 1; off < SB; off <<= 1) {
        int u = (t >= off) ? sm[t - off] : 0;
        __syncthreads();
        sm[t] += u;
        __syncthreads();
    }
    if (t < SGRID) g_bsum[t] = sm[t] - v;
}

__global__ void scan_pass3() {
    __shared__ int sm[SB];
    int t = threadIdx.x;
    int i = blockIdx.x * SB + t;
    int v = (i < N_NODES) ? g_deg[i] : 0;
    sm[t] = v;
    __syncthreads();
#pragma unroll
    for (int off = 1; off < SB; off <<= 1) {
        int u = (t >= off) ? sm[t - off] : 0;
        __syncthreads();
        sm[t] += u;
        __syncthreads();
    }
    int ex = g_bsum[blockIdx.x] + sm[t] - v;
    if (i < N_NODES) {
        g_rowstart[i] = ex;
        g_off[i] = ex;
        if (i == N_NODES - 1) g_rowstart[N_NODES] = ex + v;
    }
}

__global__ void scatter_kernel(const float* __restrict__ R,
                               const int* __restrict__ src,
                               const int* __restrict__ dst) {
    int e = blockIdx.x * blockDim.x + threadIdx.x;
    if (e >= N_EDGES) return;
    int s = src[e], d = dst[e];
    float dx = R[s * 3 + 0] - R[d * 3 + 0];
    float dy = R[s * 3 + 1] - R[d * 3 + 1];
    float dz = R[s * 3 + 2] - R[d * 3 + 2];
    float dist = sqrtf(dx * dx + dy * dy + dz * dz);
    int t = (int)(fminf(dist / H_F + 0.5f, (float)(NTF - 1)));
    int pos = atomicAdd(&g_off[d], 1);
    g_edge[pos] = make_uint2((unsigned)s, (unsigned)t);
}

// ---------------- per-layer coarse table (exact fp32) ----------------
__global__ void build_tab_kernel(const float* __restrict__ Wl) {
    __shared__ float gs[EDGE_D];
    const float* W3 = Wl + 256 * 256;
    int t = blockIdx.x;
    float d = (float)t * H_T;
    const float coeff = -0.5f / (DELTA * DELTA);
    if (threadIdx.x < EDGE_D) {
        float u = d - (float)threadIdx.x * DELTA;
        gs[threadIdx.x] = expf(coeff * u * u);
    }
    __syncthreads();
    int c = threadIdx.x;
    float acc = 0.f;
#pragma unroll 4
    for (int k = 0; k < EDGE_D; k++) acc += gs[k] * W3[k * 256 + c];
    g_tab[(size_t)t * 256 + c] = acc;
}

// ---------------- expand coarse -> fine bf16 (lerp) ----------------
__global__ void expand_tab_kernel() {
    int tf = blockIdx.x;                    // 0..NTF-1
    int c = threadIdx.x;                    // 0..255
    int t = tf >> 4;
    float f = (float)(tf & 15) * (1.f / 16.f);
    float lo = g_tab[(size_t)t * 256 + c];
    float hi = g_tab[(size_t)(t + 1) * 256 + c];
    g_tabf[(size_t)tf * 256 + c] = __float2bfloat16(fmaf(f, hi - lo, lo));
}

// ---------------- per-layer weight pack: B fragments for mma ----------------
__global__ void pack_w_kernel(const float* __restrict__ Wl) {
    int idx = blockIdx.x * 256 + threadIdx.x;
    if (idx >= 8 * 64 * 32) return;
    int lane = idx & 31;
    int ntile = (idx >> 5) & 63;
    int kt = idx >> 11;
    int u = lane & 3, c = lane >> 2;
    int n = ntile * 8 + c;
    const float* W = Wl + ((n < 256) ? 0 : 128 * 256);
    int wc = n & 255;
    int k = kt * 16 + 2 * u;
    __nv_bfloat162 v0 = __floats2bfloat162_rn(W[(k + 0) * 256 + wc], W[(k + 1) * 256 + wc]);
    __nv_bfloat162 v1 = __floats2bfloat162_rn(W[(k + 8) * 256 + wc], W[(k + 9) * 256 + wc]);
    g_Wp[idx] = make_uint2(*(unsigned*)&v0, *(unsigned*)&v1);
}

// ---------------- tensor-core GEMM: AB = x @ [W1|W2] ----------------
#define TBM 64
__global__ void gemm_mma_kernel(const float* __restrict__ bias) {
    __shared__ __nv_bfloat16 As[TBM][136];
    int tid = threadIdx.x;
    int m0 = blockIdx.y * TBM;
    int n0 = blockIdx.x * 256;

#pragma unroll
    for (int i = 0; i < 4; i++) {
        int idx = tid + i * 256;
        int r = idx >> 4, cs = idx & 15;
        uint4 v = make_uint4(0, 0, 0, 0);
        if (m0 + r < N_NODES) v = *(const uint4*)(g_xh + (size_t)(m0 + r) * NODE_D + cs * 8);
        *(uint4*)&As[r][cs * 8] = v;
    }
    __syncthreads();

    int wid = tid >> 5, lane = tid & 31;
    int wm = wid >> 2, wn = wid & 3;
    int g = lane >> 2, u = lane & 3;
    int mbase = wm * 32;
    int ntile0 = (n0 + wn * 64) >> 3;

    float acc[2][8][4];
#pragma unroll
    for (int a = 0; a < 2; a++)
#pragma unroll
        for (int b = 0; b < 8; b++)
#pragma unroll
            for (int c = 0; c < 4; c++) acc[a][b][c] = 0.f;

#pragma unroll
    for (int kt = 0; kt < 8; kt++) {
        int k0 = kt * 16;
        unsigned afr[2][4];
#pragma unroll
        for (int mf = 0; mf < 2; mf++) {
            int rb = mbase + mf * 16;
            afr[mf][0] = *(unsigned*)&As[rb + g][k0 + 2 * u];
            afr[mf][1] = *(unsigned*)&As[rb + g + 8][k0 + 2 * u];
            afr[mf][2] = *(unsigned*)&As[rb + g][k0 + 8 + 2 * u];
            afr[mf][3] = *(unsigned*)&As[rb + g + 8][k0 + 8 + 2 * u];
        }
        uint2 bfr[8];
#pragma unroll
        for (int j = 0; j < 8; j++)
            bfr[j] = g_Wp[(kt * 64 + ntile0 + j) * 32 + lane];
#pragma unroll
        for (int mf = 0; mf < 2; mf++)
#pragma unroll
            for (int j = 0; j < 8; j++)
                mma_bf16(acc[mf][j], afr[mf], bfr[j]);
    }

#pragma unroll
    for (int mf = 0; mf < 2; mf++) {
        int row0 = m0 + mbase + mf * 16 + g;
#pragma unroll
        for (int j = 0; j < 8; j++) {
            int col = n0 + wn * 64 + j * 8 + 2 * u;
            float* ac = acc[mf][j];
            if (n0 == 0) {
                float2 bv = *(const float2*)(bias + col);
                if (row0 < N_NODES)
                    *(float2*)(g_A + (size_t)row0 * 256 + col) =
                        make_float2(ac[0] + bv.x, ac[1] + bv.y);
                if (row0 + 8 < N_NODES)
                    *(float2*)(g_A + (size_t)(row0 + 8) * 256 + col) =
                        make_float2(ac[2] + bv.x, ac[3] + bv.y);
            } else {
                int cb = col - 256;
                if (row0 < N_NODES) {
                    __nv_bfloat162 p = __floats2bfloat162_rn(ac[0], ac[1]);
                    *(unsigned*)(g_Bh + (size_t)row0 * 256 + cb) = *(unsigned*)&p;
                }
                if (row0 + 8 < N_NODES) {
                    __nv_bfloat162 p = __floats2bfloat162_rn(ac[2], ac[3]);
                    *(unsigned*)(g_Bh + (size_t)(row0 + 8) * 256 + cb) = *(unsigned*)&p;
                }
            }
        }
    }
}

// ---------------- fused edge aggregation + LN + residual + softplus (+bf16 x out) ----------------
__global__ void edge_agg_kernel(const float* __restrict__ lng,
                                const float* __restrict__ lnb) {
    int n = blockIdx.x * 8 + (threadIdx.x >> 5);
    if (n >= N_NODES) return;
    int lane = threadIdx.x & 31;

    int row = g_rowstart[n];
    int end = g_rowstart[n + 1];

    const float4* Arow = (const float4*)(g_A + (size_t)n * 256);
    float4 a1 = Arow[lane];        // z1 incl bias
    float4 a2 = Arow[32 + lane];   // z2

    float4 acc = make_float4(0.f, 0.f, 0.f, 0.f);

    for (int e = row; e < end; e++) {
        uint2 ed = __ldg(&g_edge[e]);
        unsigned s = ed.x, t = ed.y;

        const __nv_bfloat16* Bb = g_Bh + (size_t)s * 256;
        uint2 b1u = *(const uint2*)(Bb + 4 * lane);
        uint2 b2u = *(const uint2*)(Bb + 128 + 4 * lane);
        const __nv_bfloat16* Tp = g_tabf + (size_t)t * 256;
        uint2 t1u = *(const uint2*)(Tp + 4 * lane);
        uint2 t2u = *(const uint2*)(Tp + 128 + 4 * lane);

        float4 z1, z2;
        z1.x = a1.x + bflo(b1u.x) + bflo(t1u.x);
        z1.y = a1.y + bfhi(b1u.x) + bfhi(t1u.x);
        z1.z = a1.z + bflo(b1u.y) + bflo(t1u.y);
        z1.w = a1.w + bfhi(b1u.y) + bfhi(t1u.y);
        z2.x = a2.x + bflo(b2u.x) + bflo(t2u.x);
        z2.y = a2.y + bfhi(b2u.x) + bfhi(t2u.x);
        z2.z = a2.z + bflo(b2u.y) + bflo(t2u.y);
        z2.w = a2.w + bfhi(b2u.y) + bfhi(t2u.y);

        acc.x = fmaf(sigmoid_tanh(z1.x), softplusf(z2.x), acc.x);
        acc.y = fmaf(sigmoid_tanh(z1.y), softplusf(z2.y), acc.y);
        acc.z = fmaf(sigmoid_tanh(z1.z), softplusf(z2.z), acc.z);
        acc.w = fmaf(sigmoid_tanh(z1.w), softplusf(z2.w), acc.w);
    }

    float s  = acc.x + acc.y + acc.z + acc.w;
    float ss = acc.x * acc.x + acc.y * acc.y + acc.z * acc.z + acc.w * acc.w;
#pragma unroll
    for (int off = 16; off > 0; off >>= 1) {
        s  += __shfl_xor_sync(0xffffffffu, s, off);
        ss += __shfl_xor_sync(0xffffffffu, ss, off);
    }
    float mu = s * (1.f / 128.f);
    float var = ss * (1.f / 128.f) - mu * mu;
    float rinv = rsqrtf(var + 1e-5f);

    float4 gg = ((const float4*)lng)[lane];
    float4 bb = ((const float4*)lnb)[lane];
    float4 xo = ((float4*)g_x)[(size_t)n * 32 + lane];
    float4 o;
    o.x = softplusf((acc.x - mu) * rinv * gg.x + bb.x + xo.x);
    o.y = softplusf((acc.y - mu) * rinv * gg.y + bb.y + xo.y);
    o.z = softplusf((acc.z - mu) * rinv * gg.z + bb.z + xo.z);
    o.w = softplusf((acc.w - mu) * rinv * gg.w + bb.w + xo.w);
    ((float4*)g_x)[(size_t)n * 32 + lane] = o;
    // bf16 copy for next layer's tensor GEMM
    __nv_bfloat162 p0 = __floats2bfloat162_rn(o.x, o.y);
    __nv_bfloat162 p1 = __floats2bfloat162_rn(o.z, o.w);
    ((uint2*)g_xh)[(size_t)n * 32 + lane] = make_uint2(*(unsigned*)&p0, *(unsigned*)&p1);
}

// ---------------- mean pool ----------------
__global__ void pool_kernel(const int* __restrict__ batch) {
    int n = blockIdx.x * 8 + (threadIdx.x >> 5);
    if (n >= N_NODES) return;
    int lane = threadIdx.x & 31;
    int b = 0;
    if (lane == 0) b = batch[n];
    b = __shfl_sync(0xffffffffu, b, 0);
    float4 v = ((const float4*)g_x)[(size_t)n * 32 + lane];
    float* base = g_pool + (size_t)b * NODE_D + 4 * lane;
    atomicAdd(base + 0, v.x);
    atomicAdd(base + 1, v.y);
    atomicAdd(base + 2, v.z);
    atomicAdd(base + 3, v.w);
    if (lane == 0) atomicAdd(g_cnt + b, 1.f);
}

// ---------------- head MLP ----------------
__global__ void head_kernel(const float* __restrict__ cfc_w, const float* __restrict__ cfc_b,
                            const float* __restrict__ fc_w,  const float* __restrict__ fc_b,
                            const float* __restrict__ out_w, const float* __restrict__ out_b,
                            float* __restrict__ out) {
    __shared__ float h0[FC_D], h1[FC_D];
    __shared__ float red[4];
    int g = blockIdx.x, c = threadIdx.x;
    float cn = fmaxf(g_cnt[g], 1.f);
    h0[c] = g_pool[(size_t)g * NODE_D + c] / cn;
    __syncthreads();
    float acc = cfc_b[c];
#pragma unroll 4
    for (int k = 0; k < NODE_D; k++) acc += h0[k] * cfc_w[k * FC_D + c];
    h1[c] = softplusf(acc);
    __syncthreads();
    acc = fc_b[c];
#pragma unroll 4
    for (int k = 0; k < FC_D; k++) acc += h1[k] * fc_w[k * FC_D + c];
    h0[c] = softplusf(acc);
    __syncthreads();
    acc = fc_b[FC_D + c];
#pragma unroll 4
    for (int k = 0; k < FC_D; k++) acc += h0[k] * fc_w[FC_D * FC_D + k * FC_D + c];
    h1[c] = softplusf(acc);
    __syncthreads();
    float p = h1[c] * out_w[c];
#pragma unroll
    for (int off = 16; off > 0; off >>= 1) p += __shfl_xor_sync(0xffffffffu, p, off);
    if ((c & 31) == 0) red[c >> 5] = p;
    __syncthreads();
    if (c == 0) out[g] = red[0] + red[1] + red[2] + red[3] + out_b[0];
}

// ---------------- launch ----------------
extern "C" void kernel_launch(void* const* d_in, const int* in_sizes, int n_in,
                              void* d_out, int out_size) {
    const int*   z         = (const int*)d_in[0];
    const float* R         = (const float*)d_in[1];
    const int*   ei        = (const int*)d_in[2];
    const int*   batch     = (const int*)d_in[3];
    const float* embedding = (const float*)d_in[4];
    const float* emb_w     = (const float*)d_in[5];
    const float* emb_b     = (const float*)d_in[6];
    const float* conv_w    = (const float*)d_in[7];
    const float* conv_b    = (const float*)d_in[8];
    const float* ln_g      = (const float*)d_in[9];
    const float* ln_b      = (const float*)d_in[10];
    const float* cfc_w     = (const float*)d_in[11];
    const float* cfc_b     = (const float*)d_in[12];
    const float* fc_w      = (const float*)d_in[13];
    const float* fc_b      = (const float*)d_in[14];
    const float* out_w     = (const float*)d_in[15];
    const float* out_b     = (const float*)d_in[16];
    float* out = (float*)d_out;

    const int* src = ei;
    const int* dst = ei + N_EDGES;

    zero_misc_kernel<<<SGRID, SB>>>();
    embed_kernel<<<N_NODES, NODE_D>>>(z, embedding, emb_w, emb_b);
    hist_kernel<<<(N_EDGES + 255) / 256, 256>>>(dst);
    scan_pass1<<<SGRID, SB>>>();
    scan_pass2<<<1, SB>>>();
    scan_pass3<<<SGRID, SB>>>();
    scatter_kernel<<<(N_EDGES + 255) / 256, 256>>>(R, src, dst);

    for (int l = 0; l < N_CONV; l++) {
        const float* Wl = conv_w + (size_t)l * 356 * 256;
        const float* bl = conv_b + (size_t)l * 256;
        build_tab_kernel<<<N_T, 256>>>(Wl);
        expand_tab_kernel<<<NTF, 256>>>();
        pack_w_kernel<<<64, 256>>>(Wl);
        dim3 ggrid(2, (N_NODES + TBM - 1) / TBM);
        gemm_mma_kernel<<<ggrid, 256>>>(bl);
        edge_agg_kernel<<<(N_NODES + 7) / 8, 256>>>(ln_g + l * NODE_D, ln_b + l * NODE_D);
    }

    pool_kernel<<<(N_NODES + 7) / 8, 256>>>(batch);
    head_kernel<<<N_GRAPHS, FC_D>>>(cfc_w, cfc_b, fc_w, fc_b, out_w, out_b, out);
}

// round 11
// speedup vs baseline: 2.8966x; 1.2066x over previous
#include <cuda_runtime.h>
#include <cuda_bf16.h>
#include <math.h>

#define N_NODES  50000
#define N_EDGES  800000
#define NODE_D   128
#define EDGE_D   100
#define EMB_D    92
#define N_GRAPHS 256
#define N_CONV   3
#define FC_D     128

#define DELTA    (6.0f / 99.0f)
#define N_T      1800
#define H_T      (DELTA / 16.0f)
#define NTF      (16 * (N_T - 1))          // 28784 fine rows
#define H_F      (DELTA / 256.0f)

#define SB    256
#define SGRID ((N_NODES + SB - 1) / SB)

// ---------------- scratch (device globals) ----------------
__device__ float g_embt[100 * NODE_D];                // embedding @ emb_w + b (exact)
__device__ float g_x[N_NODES * NODE_D];
__device__ __nv_bfloat16 g_xh[N_NODES * NODE_D];
__device__ float g_A[N_NODES * 256];
__device__ __nv_bfloat16 g_Bh[N_NODES * 256];
__device__ uint2 g_Wp[N_CONV][8 * 64 * 32];
__device__ float g_tab[N_CONV][N_T * 256];
__device__ __nv_bfloat16 g_tabf[N_CONV][(size_t)NTF * 256];
__device__ int   g_deg[N_NODES];
__device__ int   g_off[N_NODES];
__device__ int   g_rowstart[N_NODES + 1];
__device__ int   g_bsum[SGRID];
__device__ uint2 g_edge[N_EDGES];
__device__ float g_pool[N_GRAPHS * NODE_D];
__device__ float g_cnt[N_GRAPHS];

// ---------------- fast math helpers ----------------
__device__ __forceinline__ float softplusf(float x) {
    return fmaxf(x, 0.f) + __logf(1.f + __expf(-fabsf(x)));
}
__device__ __forceinline__ float sigmoid_tanh(float x) {
    float th;
    asm("tanh.approx.f32 %0, %1;" : "=f"(th) : "f"(0.5f * x));
    return fmaf(0.5f, th, 0.5f);
}
__device__ __forceinline__ float bflo(unsigned u) { return __uint_as_float(u << 16); }
__device__ __forceinline__ float bfhi(unsigned u) { return __uint_as_float(u & 0xffff0000u); }

__device__ __forceinline__ void mma_bf16(float* c, const unsigned* a, uint2 b) {
    asm volatile(
        "mma.sync.aligned.m16n8k16.row.col.f32.bf16.bf16.f32 "
        "{%0,%1,%2,%3}, {%4,%5,%6,%7}, {%8,%9}, {%0,%1,%2,%3};"
        : "+f"(c[0]), "+f"(c[1]), "+f"(c[2]), "+f"(c[3])
        : "r"(a[0]), "r"(a[1]), "r"(a[2]), "r"(a[3]), "r"(b.x), "r"(b.y));
}

// ---------------- zero ----------------
__global__ void zero_misc_kernel() {
    int i = blockIdx.x * blockDim.x + threadIdx.x;
    if (i < N_NODES) g_deg[i] = 0;
    if (i < N_GRAPHS * NODE_D) g_pool[i] = 0.f;
    if (i < N_GRAPHS) g_cnt[i] = 0.f;
}

// ---------------- emb_table = embedding @ emb_w + emb_b (100 x 128, exact) ----------------
__global__ void emb_table_kernel(const float* __restrict__ emb,
                                 const float* __restrict__ W,
                                 const float* __restrict__ b) {
    __shared__ float er[EMB_D];
    int r = blockIdx.x;                    // 0..99
    if (threadIdx.x < EMB_D) er[threadIdx.x] = emb[r * EMB_D + threadIdx.x];
    __syncthreads();
    int c = threadIdx.x;
    float acc = b[c];
#pragma unroll 4
    for (int k = 0; k < EMB_D; k++) acc += er[k] * W[k * NODE_D + c];
    g_embt[r * NODE_D + c] = acc;
}

// ---------------- x0 = emb_table[z] (gather) ----------------
__global__ void embed_gather_kernel(const int* __restrict__ z) {
    int n = blockIdx.x * 8 + (threadIdx.x >> 5);
    if (n >= N_NODES) return;
    int lane = threadIdx.x & 31;
    int zi = 0;
    if (lane == 0) zi = z[n];
    zi = __shfl_sync(0xffffffffu, zi, 0);
    float4 v = ((const float4*)g_embt)[zi * 32 + lane];
    ((float4*)g_x)[(size_t)n * 32 + lane] = v;
    __nv_bfloat162 p0 = __floats2bfloat162_rn(v.x, v.y);
    __nv_bfloat162 p1 = __floats2bfloat162_rn(v.z, v.w);
    ((uint2*)g_xh)[(size_t)n * 32 + lane] = make_uint2(*(unsigned*)&p0, *(unsigned*)&p1);
}

// ---------------- counting sort by dst (+ graph node counts) ----------------
__global__ void hist_kernel(const int* __restrict__ dst, const int* __restrict__ batch) {
    int e = blockIdx.x * blockDim.x + threadIdx.x;
    if (e < N_EDGES) atomicAdd(&g_deg[dst[e]], 1);
    if (e < N_NODES) atomicAdd(&g_cnt[batch[e]], 1.f);
}

__global__ void scan_pass1() {
    __shared__ int ws[8];
    int i = blockIdx.x * SB + threadIdx.x;
    int v = (i < N_NODES) ? g_deg[i] : 0;
#pragma unroll
    for (int off = 16; off > 0; off >>= 1) v += __shfl_xor_sync(0xffffffffu, v, off);
    if ((threadIdx.x & 31) == 0) ws[threadIdx.x >> 5] = v;
    __syncthreads();
    if (threadIdx.x == 0) {
        int s = 0;
#pragma unroll
        for (int w = 0; w < 8; w++) s += ws[w];
        g_bsum[blockIdx.x] = s;
    }
}

__global__ void scan_pass2() {
    __shared__ int sm[SB];
    int t = threadIdx.x;
    int v = (t < SGRID) ? g_bsum[t] : 0;
    sm[t] = v;
    __syncthreads();
#pragma unroll
    for (int off = 1; off < SB; off <<= 1) {
        int u = (t >= off) ? sm[t - off] : 0;
        __syncthreads();
        sm[t] += u;
        __syncthreads();
    }
    if (t < SGRID) g_bsum[t] = sm[t] - v;
}

__global__ void scan_pass3() {
    __shared__ int sm[SB];
    int t = threadIdx.x;
    int i = blockIdx.x * SB + t;
    int v = (i < N_NODES) ? g_deg[i] : 0;
    sm[t] = v;
    __syncthreads();
#pragma unroll
    for (int off = 1; off < SB; off <<= 1) {
        int u = (t >= off) ? sm[t - off] : 0;
        __syncthreads();
        sm[t] += u;
        __syncthreads();
    }
    int ex = g_bsum[blockIdx.x] + sm[t] - v;
    if (i < N_NODES) {
        g_rowstart[i] = ex;
        g_off[i] = ex;
        if (i == N_NODES - 1) g_rowstart[N_NODES] = ex + v;
    }
}

__global__ void scatter_kernel(const float* __restrict__ R,
                               const int* __restrict__ src,
                               const int* __restrict__ dst) {
    int e = blockIdx.x * blockDim.x + threadIdx.x;
    if (e >= N_EDGES) return;
    int s = src[e], d = dst[e];
    float dx = R[s * 3 + 0] - R[d * 3 + 0];
    float dy = R[s * 3 + 1] - R[d * 3 + 1];
    float dz = R[s * 3 + 2] - R[d * 3 + 2];
    float dist = sqrtf(dx * dx + dy * dy + dz * dz);
    int t = (int)(fminf(dist / H_F + 0.5f, (float)(NTF - 1)));
    int pos = atomicAdd(&g_off[d], 1);
    g_edge[pos] = make_uint2((unsigned)s, (unsigned)t);
}

// ---------------- coarse tables, all layers (exact fp32) ----------------
__global__ void build_tab_kernel(const float* __restrict__ conv_w) {
    __shared__ float gs[EDGE_D];
    int l = blockIdx.y;
    const float* W3 = conv_w + (size_t)l * 356 * 256 + 256 * 256;
    int t = blockIdx.x;
    float d = (float)t * H_T;
    const float coeff = -0.5f / (DELTA * DELTA);
    if (threadIdx.x < EDGE_D) {
        float u = d - (float)threadIdx.x * DELTA;
        gs[threadIdx.x] = expf(coeff * u * u);
    }
    __syncthreads();
    int c = threadIdx.x;
    float acc = 0.f;
#pragma unroll 4
    for (int k = 0; k < EDGE_D; k++) acc += gs[k] * W3[k * 256 + c];
    g_tab[l][(size_t)t * 256 + c] = acc;
}

// ---------------- expand coarse -> fine bf16, all layers ----------------
__global__ void expand_tab_kernel() {
    int l = blockIdx.y;
    int tf = blockIdx.x;
    int c = threadIdx.x;
    int t = tf >> 4;
    float f = (float)(tf & 15) * (1.f / 16.f);
    float lo = g_tab[l][(size_t)t * 256 + c];
    float hi = g_tab[l][(size_t)(t + 1) * 256 + c];
    g_tabf[l][(size_t)tf * 256 + c] = __float2bfloat16(fmaf(f, hi - lo, lo));
}

// ---------------- weight pack, all layers ----------------
__global__ void pack_w_kernel(const float* __restrict__ conv_w) {
    int l = blockIdx.y;
    const float* Wl = conv_w + (size_t)l * 356 * 256;
    int idx = blockIdx.x * 256 + threadIdx.x;
    if (idx >= 8 * 64 * 32) return;
    int lane = idx & 31;
    int ntile = (idx >> 5) & 63;
    int kt = idx >> 11;
    int u = lane & 3, c = lane >> 2;
    int n = ntile * 8 + c;
    const float* W = Wl + ((n < 256) ? 0 : 128 * 256);
    int wc = n & 255;
    int k = kt * 16 + 2 * u;
    __nv_bfloat162 v0 = __floats2bfloat162_rn(W[(k + 0) * 256 + wc], W[(k + 1) * 256 + wc]);
    __nv_bfloat162 v1 = __floats2bfloat162_rn(W[(k + 8) * 256 + wc], W[(k + 9) * 256 + wc]);
    g_Wp[l][idx] = make_uint2(*(unsigned*)&v0, *(unsigned*)&v1);
}

// ---------------- tensor-core GEMM: AB = x @ [W1|W2] ----------------
#define TBM 64
__global__ void gemm_mma_kernel(const float* __restrict__ bias, int layer) {
    __shared__ __nv_bfloat16 As[TBM][136];
    int tid = threadIdx.x;
    int m0 = blockIdx.y * TBM;
    int n0 = blockIdx.x * 256;

#pragma unroll
    for (int i = 0; i < 4; i++) {
        int idx = tid + i * 256;
        int r = idx >> 4, cs = idx & 15;
        uint4 v = make_uint4(0, 0, 0, 0);
        if (m0 + r < N_NODES) v = *(const uint4*)(g_xh + (size_t)(m0 + r) * NODE_D + cs * 8);
        *(uint4*)&As[r][cs * 8] = v;
    }
    __syncthreads();

    int wid = tid >> 5, lane = tid & 31;
    int wm = wid >> 2, wn = wid & 3;
    int g = lane >> 2, u = lane & 3;
    int mbase = wm * 32;
    int ntile0 = (n0 + wn * 64) >> 3;
    const uint2* Wp = g_Wp[layer];

    float acc[2][8][4];
#pragma unroll
    for (int a = 0; a < 2; a++)
#pragma unroll
        for (int b = 0; b < 8; b++)
#pragma unroll
            for (int c = 0; c < 4; c++) acc[a][b][c] = 0.f;

#pragma unroll
    for (int kt = 0; kt < 8; kt++) {
        int k0 = kt * 16;
        unsigned afr[2][4];
#pragma unroll
        for (int mf = 0; mf < 2; mf++) {
            int rb = mbase + mf * 16;
            afr[mf][0] = *(unsigned*)&As[rb + g][k0 + 2 * u];
            afr[mf][1] = *(unsigned*)&As[rb + g + 8][k0 + 2 * u];
            afr[mf][2] = *(unsigned*)&As[rb + g][k0 + 8 + 2 * u];
            afr[mf][3] = *(unsigned*)&As[rb + g + 8][k0 + 8 + 2 * u];
        }
        uint2 bfr[8];
#pragma unroll
        for (int j = 0; j < 8; j++)
            bfr[j] = Wp[(kt * 64 + ntile0 + j) * 32 + lane];
#pragma unroll
        for (int mf = 0; mf < 2; mf++)
#pragma unroll
            for (int j = 0; j < 8; j++)
                mma_bf16(acc[mf][j], afr[mf], bfr[j]);
    }

#pragma unroll
    for (int mf = 0; mf < 2; mf++) {
        int row0 = m0 + mbase + mf * 16 + g;
#pragma unroll
        for (int j = 0; j < 8; j++) {
            int col = n0 + wn * 64 + j * 8 + 2 * u;
            float* ac = acc[mf][j];
            if (n0 == 0) {
                float2 bv = *(const float2*)(bias + col);
                if (row0 < N_NODES)
                    *(float2*)(g_A + (size_t)row0 * 256 + col) =
                        make_float2(ac[0] + bv.x, ac[1] + bv.y);
                if (row0 + 8 < N_NODES)
                    *(float2*)(g_A + (size_t)(row0 + 8) * 256 + col) =
                        make_float2(ac[2] + bv.x, ac[3] + bv.y);
            } else {
                int cb = col - 256;
                if (row0 < N_NODES) {
                    __nv_bfloat162 p = __floats2bfloat162_rn(ac[0], ac[1]);
                    *(unsigned*)(g_Bh + (size_t)row0 * 256 + cb) = *(unsigned*)&p;
                }
                if (row0 + 8 < N_NODES) {
                    __nv_bfloat162 p = __floats2bfloat162_rn(ac[2], ac[3]);
                    *(unsigned*)(g_Bh + (size_t)(row0 + 8) * 256 + cb) = *(unsigned*)&p;
                }
            }
        }
    }
}

// ---------------- fused edge aggregation + LN + residual + softplus ----------------
// unroll-by-2 over edges for MLP; LAST fuses mean-pool atomics
template <bool LAST>
__global__ void edge_agg_kernel(const float* __restrict__ lng,
                                const float* __restrict__ lnb,
                                const int* __restrict__ batch,
                                int layer) {
    int n = blockIdx.x * 8 + (threadIdx.x >> 5);
    if (n >= N_NODES) return;
    int lane = threadIdx.x & 31;

    int row = g_rowstart[n];
    int end = g_rowstart[n + 1];

    const float4* Arow = (const float4*)(g_A + (size_t)n * 256);
    float4 a1 = Arow[lane];
    float4 a2 = Arow[32 + lane];
    const __nv_bfloat16* tabf = g_tabf[layer];

    float4 acc = make_float4(0.f, 0.f, 0.f, 0.f);

    int e = row;
    for (; e + 1 < end; e += 2) {
        uint2 edA = __ldg(&g_edge[e]);
        uint2 edB = __ldg(&g_edge[e + 1]);

        const __nv_bfloat16* BbA = g_Bh + (size_t)edA.x * 256;
        const __nv_bfloat16* TpA = tabf + (size_t)edA.y * 256;
        const __nv_bfloat16* BbB = g_Bh + (size_t)edB.x * 256;
        const __nv_bfloat16* TpB = tabf + (size_t)edB.y * 256;

        uint2 b1A = *(const uint2*)(BbA + 4 * lane);
        uint2 b2A = *(const uint2*)(BbA + 128 + 4 * lane);
        uint2 t1A = *(const uint2*)(TpA + 4 * lane);
        uint2 t2A = *(const uint2*)(TpA + 128 + 4 * lane);
        uint2 b1B = *(const uint2*)(BbB + 4 * lane);
        uint2 b2B = *(const uint2*)(BbB + 128 + 4 * lane);
        uint2 t1B = *(const uint2*)(TpB + 4 * lane);
        uint2 t2B = *(const uint2*)(TpB + 128 + 4 * lane);

        float4 z1, z2;
        z1.x = a1.x + bflo(b1A.x) + bflo(t1A.x);
        z1.y = a1.y + bfhi(b1A.x) + bfhi(t1A.x);
        z1.z = a1.z + bflo(b1A.y) + bflo(t1A.y);
        z1.w = a1.w + bfhi(b1A.y) + bfhi(t1A.y);
        z2.x = a2.x + bflo(b2A.x) + bflo(t2A.x);
        z2.y = a2.y + bfhi(b2A.x) + bfhi(t2A.x);
        z2.z = a2.z + bflo(b2A.y) + bflo(t2A.y);
        z2.w = a2.w + bfhi(b2A.y) + bfhi(t2A.y);
        acc.x = fmaf(sigmoid_tanh(z1.x), softplusf(z2.x), acc.x);
        acc.y = fmaf(sigmoid_tanh(z1.y), softplusf(z2.y), acc.y);
        acc.z = fmaf(sigmoid_tanh(z1.z), softplusf(z2.z), acc.z);
        acc.w = fmaf(sigmoid_tanh(z1.w), softplusf(z2.w), acc.w);

        z1.x = a1.x + bflo(b1B.x) + bflo(t1B.x);
        z1.y = a1.y + bfhi(b1B.x) + bfhi(t1B.x);
        z1.z = a1.z + bflo(b1B.y) + bflo(t1B.y);
        z1.w = a1.w + bfhi(b1B.y) + bfhi(t1B.y);
        z2.x = a2.x + bflo(b2B.x) + bflo(t2B.x);
        z2.y = a2.y + bfhi(b2B.x) + bfhi(t2B.x);
        z2.z = a2.z + bflo(b2B.y) + bflo(t2B.y);
        z2.w = a2.w + bfhi(b2B.y) + bfhi(t2B.y);
        acc.x = fmaf(sigmoid_tanh(z1.x), softplusf(z2.x), acc.x);
        acc.y = fmaf(sigmoid_tanh(z1.y), softplusf(z2.y), acc.y);
        acc.z = fmaf(sigmoid_tanh(z1.z), softplusf(z2.z), acc.z);
        acc.w = fmaf(sigmoid_tanh(z1.w), softplusf(z2.w), acc.w);
    }
    if (e < end) {
        uint2 ed = __ldg(&g_edge[e]);
        const __nv_bfloat16* Bb = g_Bh + (size_t)ed.x * 256;
        const __nv_bfloat16* Tp = tabf + (size_t)ed.y * 256;
        uint2 b1u = *(const uint2*)(Bb + 4 * lane);
        uint2 b2u = *(const uint2*)(Bb + 128 + 4 * lane);
        uint2 t1u = *(const uint2*)(Tp + 4 * lane);
        uint2 t2u = *(const uint2*)(Tp + 128 + 4 * lane);
        float4 z1, z2;
        z1.x = a1.x + bflo(b1u.x) + bflo(t1u.x);
        z1.y = a1.y + bfhi(b1u.x) + bfhi(t1u.x);
        z1.z = a1.z + bflo(b1u.y) + bflo(t1u.y);
        z1.w = a1.w + bfhi(b1u.y) + bfhi(t1u.y);
        z2.x = a2.x + bflo(b2u.x) + bflo(t2u.x);
        z2.y = a2.y + bfhi(b2u.x) + bfhi(t2u.x);
        z2.z = a2.z + bflo(b2u.y) + bflo(t2u.y);
        z2.w = a2.w + bfhi(b2u.y) + bfhi(t2u.y);
        acc.x = fmaf(sigmoid_tanh(z1.x), softplusf(z2.x), acc.x);
        acc.y = fmaf(sigmoid_tanh(z1.y), softplusf(z2.y), acc.y);
        acc.z = fmaf(sigmoid_tanh(z1.z), softplusf(z2.z), acc.z);
        acc.w = fmaf(sigmoid_tanh(z1.w), softplusf(z2.w), acc.w);
    }

    float s  = acc.x + acc.y + acc.z + acc.w;
    float ss = acc.x * acc.x + acc.y * acc.y + acc.z * acc.z + acc.w * acc.w;
#pragma unroll
    for (int off = 16; off > 0; off >>= 1) {
        s  += __shfl_xor_sync(0xffffffffu, s, off);
        ss += __shfl_xor_sync(0xffffffffu, ss, off);
    }
    float mu = s * (1.f / 128.f);
    float var = ss * (1.f / 128.f) - mu * mu;
    float rinv = rsqrtf(var + 1e-5f);

    float4 gg = ((const float4*)lng)[lane];
    float4 bb = ((const float4*)lnb)[lane];
    float4 xo = ((float4*)g_x)[(size_t)n * 32 + lane];
    float4 o;
    o.x = softplusf((acc.x - mu) * rinv * gg.x + bb.x + xo.x);
    o.y = softplusf((acc.y - mu) * rinv * gg.y + bb.y + xo.y);
    o.z = softplusf((acc.z - mu) * rinv * gg.z + bb.z + xo.z);
    o.w = softplusf((acc.w - mu) * rinv * gg.w + bb.w + xo.w);

    if (!LAST) {
        ((float4*)g_x)[(size_t)n * 32 + lane] = o;
        __nv_bfloat162 p0 = __floats2bfloat162_rn(o.x, o.y);
        __nv_bfloat162 p1 = __floats2bfloat162_rn(o.z, o.w);
        ((uint2*)g_xh)[(size_t)n * 32 + lane] = make_uint2(*(unsigned*)&p0, *(unsigned*)&p1);
    } else {
        int b = 0;
        if (lane == 0) b = batch[n];
        b = __shfl_sync(0xffffffffu, b, 0);
        float* base = g_pool + (size_t)b * NODE_D + 4 * lane;
        atomicAdd(base + 0, o.x);
        atomicAdd(base + 1, o.y);
        atomicAdd(base + 2, o.z);
        atomicAdd(base + 3, o.w);
    }
}

// ---------------- head MLP ----------------
__global__ void head_kernel(const float* __restrict__ cfc_w, const float* __restrict__ cfc_b,
                            const float* __restrict__ fc_w,  const float* __restrict__ fc_b,
                            const float* __restrict__ out_w, const float* __restrict__ out_b,
                            float* __restrict__ out) {
    __shared__ float h0[FC_D], h1[FC_D];
    __shared__ float red[4];
    int g = blockIdx.x, c = threadIdx.x;
    float cn = fmaxf(g_cnt[g], 1.f);
    h0[c] = g_pool[(size_t)g * NODE_D + c] / cn;
    __syncthreads();
    float acc = cfc_b[c];
#pragma unroll 4
    for (int k = 0; k < NODE_D; k++) acc += h0[k] * cfc_w[k * FC_D + c];
    h1[c] = softplusf(acc);
    __syncthreads();
    acc = fc_b[c];
#pragma unroll 4
    for (int k = 0; k < FC_D; k++) acc += h1[k] * fc_w[k * FC_D + c];
    h0[c] = softplusf(acc);
    __syncthreads();
    acc = fc_b[FC_D + c];
#pragma unroll 4
    for (int k = 0; k < FC_D; k++) acc += h0[k] * fc_w[FC_D * FC_D + k * FC_D + c];
    h1[c] = softplusf(acc);
    __syncthreads();
    float p = h1[c] * out_w[c];
#pragma unroll
    for (int off = 16; off > 0; off >>= 1) p += __shfl_xor_sync(0xffffffffu, p, off);
    if ((c & 31) == 0) red[c >> 5] = p;
    __syncthreads();
    if (c == 0) out[g] = red[0] + red[1] + red[2] + red[3] + out_b[0];
}

// ---------------- launch ----------------
extern "C" void kernel_launch(void* const* d_in, const int* in_sizes, int n_in,
                              void* d_out, int out_size) {
    const int*   z         = (const int*)d_in[0];
    const float* R         = (const float*)d_in[1];
    const int*   ei        = (const int*)d_in[2];
    const int*   batch     = (const int*)d_in[3];
    const float* embedding = (const float*)d_in[4];
    const float* emb_w     = (const float*)d_in[5];
    const float* emb_b     = (const float*)d_in[6];
    const float* conv_w    = (const float*)d_in[7];
    const float* conv_b    = (const float*)d_in[8];
    const float* ln_g      = (const float*)d_in[9];
    const float* ln_b      = (const float*)d_in[10];
    const float* cfc_w     = (const float*)d_in[11];
    const float* cfc_b     = (const float*)d_in[12];
    const float* fc_w      = (const float*)d_in[13];
    const float* fc_b      = (const float*)d_in[14];
    const float* out_w     = (const float*)d_in[15];
    const float* out_b     = (const float*)d_in[16];
    float* out = (float*)d_out;

    const int* src = ei;
    const int* dst = ei + N_EDGES;

    zero_misc_kernel<<<SGRID, SB>>>();
    emb_table_kernel<<<100, NODE_D>>>(embedding, emb_w, emb_b);
    embed_gather_kernel<<<(N_NODES + 7) / 8, 256>>>(z);
    hist_kernel<<<(N_EDGES + 255) / 256, 256>>>(dst, batch);
    scan_pass1<<<SGRID, SB>>>();
    scan_pass2<<<1, SB>>>();
    scan_pass3<<<SGRID, SB>>>();
    scatter_kernel<<<(N_EDGES + 255) / 256, 256>>>(R, src, dst);

    // all-layer prep (weights only; no x dependence)
    build_tab_kernel<<<dim3(N_T, N_CONV), 256>>>(conv_w);
    expand_tab_kernel<<<dim3(NTF, N_CONV), 256>>>();
    pack_w_kernel<<<dim3(64, N_CONV), 256>>>(conv_w);

    for (int l = 0; l < N_CONV; l++) {
        const float* bl = conv_b + (size_t)l * 256;
        dim3 ggrid(2, (N_NODES + TBM - 1) / TBM);
        gemm_mma_kernel<<<ggrid, 256>>>(bl, l);
        if (l < N_CONV - 1)
            edge_agg_kernel<false><<<(N_NODES + 7) / 8, 256>>>(
                ln_g + l * NODE_D, ln_b + l * NODE_D, batch, l);
        else
            edge_agg_kernel<true><<<(N_NODES + 7) / 8, 256>>>(
                ln_g + l * NODE_D, ln_b + l * NODE_D, batch, l);
    }

    head_kernel<<<N_GRAPHS, FC_D>>>(cfc_w, cfc_b, fc_w, fc_b, out_w, out_b, out);
}

// round 12
// speedup vs baseline: 3.0180x; 1.0419x over previous
#include <cuda_runtime.h>
#include <cuda_bf16.h>
#include <math.h>

#define N_NODES  50000
#define N_EDGES  800000
#define NODE_D   128
#define EDGE_D   100
#define EMB_D    92
#define N_GRAPHS 256
#define N_CONV   3
#define FC_D     128

#define DELTA    (6.0f / 99.0f)
#define N_T      1800
#define H_T      (DELTA / 16.0f)
#define NTF      (16 * (N_T - 1))          // 28784 fine rows
#define H_F      (DELTA / 256.0f)

#define SB    256
#define SGRID ((N_NODES + SB - 1) / SB)

// ---------------- scratch (device globals) ----------------
__device__ float g_embt[100 * NODE_D];
__device__ float g_x[N_NODES * NODE_D];
__device__ __nv_bfloat16 g_xh[N_NODES * NODE_D];
__device__ float g_A[N_NODES * 256];
__device__ __nv_bfloat16 g_Bh[N_NODES * 256];
__device__ uint2 g_Wp[N_CONV][8 * 64 * 32];
__device__ float g_tab[N_CONV][N_T * 256];
__device__ __nv_bfloat16 g_tabf[N_CONV][(size_t)NTF * 256];
__device__ int   g_deg[N_NODES];
__device__ int   g_off[N_NODES];
__device__ int   g_rowstart[N_NODES + 1];
__device__ int   g_bsum[SGRID];
__device__ uint2 g_edge[N_EDGES];
__device__ float g_pool[N_GRAPHS * NODE_D];
__device__ float g_cnt[N_GRAPHS];

// ---------------- fast math helpers ----------------
__device__ __forceinline__ float softplusf(float x) {
    return fmaxf(x, 0.f) + __logf(1.f + __expf(-fabsf(x)));
}
__device__ __forceinline__ float sigmoid_tanh(float x) {
    float th;
    asm("tanh.approx.f32 %0, %1;" : "=f"(th) : "f"(0.5f * x));
    return fmaf(0.5f, th, 0.5f);
}
__device__ __forceinline__ float bflo(unsigned u) { return __uint_as_float(u << 16); }
__device__ __forceinline__ float bfhi(unsigned u) { return __uint_as_float(u & 0xffff0000u); }

__device__ __forceinline__ void mma_bf16(float* c, const unsigned* a, uint2 b) {
    asm volatile(
        "mma.sync.aligned.m16n8k16.row.col.f32.bf16.bf16.f32 "
        "{%0,%1,%2,%3}, {%4,%5,%6,%7}, {%8,%9}, {%0,%1,%2,%3};"
        : "+f"(c[0]), "+f"(c[1]), "+f"(c[2]), "+f"(c[3])
        : "r"(a[0]), "r"(a[1]), "r"(a[2]), "r"(a[3]), "r"(b.x), "r"(b.y));
}

// per-edge message accumulate
__device__ __forceinline__ void edge_accum(const float4& a1, const float4& a2,
                                           uint2 b1u, uint2 b2u, uint2 t1u, uint2 t2u,
                                           float4& acc) {
    float4 z1, z2;
    z1.x = a1.x + bflo(b1u.x) + bflo(t1u.x);
    z1.y = a1.y + bfhi(b1u.x) + bfhi(t1u.x);
    z1.z = a1.z + bflo(b1u.y) + bflo(t1u.y);
    z1.w = a1.w + bfhi(b1u.y) + bfhi(t1u.y);
    z2.x = a2.x + bflo(b2u.x) + bflo(t2u.x);
    z2.y = a2.y + bfhi(b2u.x) + bfhi(t2u.x);
    z2.z = a2.z + bflo(b2u.y) + bflo(t2u.y);
    z2.w = a2.w + bfhi(b2u.y) + bfhi(t2u.y);
    acc.x = fmaf(sigmoid_tanh(z1.x), softplusf(z2.x), acc.x);
    acc.y = fmaf(sigmoid_tanh(z1.y), softplusf(z2.y), acc.y);
    acc.z = fmaf(sigmoid_tanh(z1.z), softplusf(z2.z), acc.z);
    acc.w = fmaf(sigmoid_tanh(z1.w), softplusf(z2.w), acc.w);
}

// ---------------- zero ----------------
__global__ void zero_misc_kernel() {
    int i = blockIdx.x * blockDim.x + threadIdx.x;
    if (i < N_NODES) g_deg[i] = 0;
    if (i < N_GRAPHS * NODE_D) g_pool[i] = 0.f;
}

// ---------------- emb_table = embedding @ emb_w + emb_b ----------------
__global__ void emb_table_kernel(const float* __restrict__ emb,
                                 const float* __restrict__ W,
                                 const float* __restrict__ b) {
    __shared__ float er[EMB_D];
    int r = blockIdx.x;
    if (threadIdx.x < EMB_D) er[threadIdx.x] = emb[r * EMB_D + threadIdx.x];
    __syncthreads();
    int c = threadIdx.x;
    float acc = b[c];
#pragma unroll 4
    for (int k = 0; k < EMB_D; k++) acc += er[k] * W[k * NODE_D + c];
    g_embt[r * NODE_D + c] = acc;
}

// ---------------- x0 = emb_table[z] ----------------
__global__ void embed_gather_kernel(const int* __restrict__ z) {
    int n = blockIdx.x * 8 + (threadIdx.x >> 5);
    if (n >= N_NODES) return;
    int lane = threadIdx.x & 31;
    int zi = 0;
    if (lane == 0) zi = z[n];
    zi = __shfl_sync(0xffffffffu, zi, 0);
    float4 v = ((const float4*)g_embt)[zi * 32 + lane];
    ((float4*)g_x)[(size_t)n * 32 + lane] = v;
    __nv_bfloat162 p0 = __floats2bfloat162_rn(v.x, v.y);
    __nv_bfloat162 p1 = __floats2bfloat162_rn(v.z, v.w);
    ((uint2*)g_xh)[(size_t)n * 32 + lane] = make_uint2(*(unsigned*)&p0, *(unsigned*)&p1);
}

// ---------------- graph node counts: binary search on sorted batch ----------------
__global__ void graph_count_kernel(const int* __restrict__ batch) {
    int g = threadIdx.x;                   // 0..255 (one block)
    if (g >= N_GRAPHS) return;
    // lower bound of g
    int lo = 0, hi = N_NODES;
    while (lo < hi) { int m = (lo + hi) >> 1; if (batch[m] < g) lo = m + 1; else hi = m; }
    int a = lo;
    lo = 0; hi = N_NODES;
    while (lo < hi) { int m = (lo + hi) >> 1; if (batch[m] <= g) lo = m + 1; else hi = m; }
    g_cnt[g] = (float)(lo - a);
}

// ---------------- counting sort by dst ----------------
__global__ void hist_kernel(const int* __restrict__ dst) {
    int e = blockIdx.x * blockDim.x + threadIdx.x;
    if (e < N_EDGES) atomicAdd(&g_deg[dst[e]], 1);
}

__global__ void scan_pass1() {
    __shared__ int ws[8];
    int i = blockIdx.x * SB + threadIdx.x;
    int v = (i < N_NODES) ? g_deg[i] : 0;
#pragma unroll
    for (int off = 16; off > 0; off >>= 1) v += __shfl_xor_sync(0xffffffffu, v, off);
    if ((threadIdx.x & 31) == 0) ws[threadIdx.x >> 5] = v;
    __syncthreads();
    if (threadIdx.x == 0) {
        int s = 0;
#pragma unroll
        for (int w = 0; w < 8; w++) s += ws[w];
        g_bsum[blockIdx.x] = s;
    }
}

__global__ void scan_pass2() {
    __shared__ int sm[SB];
    int t = threadIdx.x;
    int v = (t < SGRID) ? g_bsum[t] : 0;
    sm[t] = v;
    __syncthreads();
#pragma unroll
    for (int off = 1; off < SB; off <<= 1) {
        int u = (t >= off) ? sm[t - off] : 0;
        __syncthreads();
        sm[t] += u;
        __syncthreads();
    }
    if (t < SGRID) g_bsum[t] = sm[t] - v;
}

__global__ void scan_pass3() {
    __shared__ int sm[SB];
    int t = threadIdx.x;
    int i = blockIdx.x * SB + t;
    int v = (i < N_NODES) ? g_deg[i] : 0;
    sm[t] = v;
    __syncthreads();
#pragma unroll
    for (int off = 1; off < SB; off <<= 1) {
        int u = (t >= off) ? sm[t - off] : 0;
        __syncthreads();
        sm[t] += u;
        __syncthreads();
    }
    int ex = g_bsum[blockIdx.x] + sm[t] - v;
    if (i < N_NODES) {
        g_rowstart[i] = ex;
        g_off[i] = ex;
        if (i == N_NODES - 1) g_rowstart[N_NODES] = ex + v;
    }
}

__global__ void scatter_kernel(const float* __restrict__ R,
                               const int* __restrict__ src,
                               const int* __restrict__ dst) {
    int e = blockIdx.x * blockDim.x + threadIdx.x;
    if (e >= N_EDGES) return;
    int s = src[e], d = dst[e];
    float dx = R[s * 3 + 0] - R[d * 3 + 0];
    float dy = R[s * 3 + 1] - R[d * 3 + 1];
    float dz = R[s * 3 + 2] - R[d * 3 + 2];
    float dist = sqrtf(dx * dx + dy * dy + dz * dz);
    int t = (int)(fminf(dist / H_F + 0.5f, (float)(NTF - 1)));
    int pos = atomicAdd(&g_off[d], 1);
    g_edge[pos] = make_uint2((unsigned)s, (unsigned)t);
}

// ---------------- coarse tables, all layers ----------------
__global__ void build_tab_kernel(const float* __restrict__ conv_w) {
    __shared__ float gs[EDGE_D];
    int l = blockIdx.y;
    const float* W3 = conv_w + (size_t)l * 356 * 256 + 256 * 256;
    int t = blockIdx.x;
    float d = (float)t * H_T;
    const float coeff = -0.5f / (DELTA * DELTA);
    if (threadIdx.x < EDGE_D) {
        float u = d - (float)threadIdx.x * DELTA;
        gs[threadIdx.x] = expf(coeff * u * u);
    }
    __syncthreads();
    int c = threadIdx.x;
    float acc = 0.f;
#pragma unroll 4
    for (int k = 0; k < EDGE_D; k++) acc += gs[k] * W3[k * 256 + c];
    g_tab[l][(size_t)t * 256 + c] = acc;
}

__global__ void expand_tab_kernel() {
    int l = blockIdx.y;
    int tf = blockIdx.x;
    int c = threadIdx.x;
    int t = tf >> 4;
    float f = (float)(tf & 15) * (1.f / 16.f);
    float lo = g_tab[l][(size_t)t * 256 + c];
    float hi = g_tab[l][(size_t)(t + 1) * 256 + c];
    g_tabf[l][(size_t)tf * 256 + c] = __float2bfloat16(fmaf(f, hi - lo, lo));
}

__global__ void pack_w_kernel(const float* __restrict__ conv_w) {
    int l = blockIdx.y;
    const float* Wl = conv_w + (size_t)l * 356 * 256;
    int idx = blockIdx.x * 256 + threadIdx.x;
    if (idx >= 8 * 64 * 32) return;
    int lane = idx & 31;
    int ntile = (idx >> 5) & 63;
    int kt = idx >> 11;
    int u = lane & 3, c = lane >> 2;
    int n = ntile * 8 + c;
    const float* W = Wl + ((n < 256) ? 0 : 128 * 256);
    int wc = n & 255;
    int k = kt * 16 + 2 * u;
    __nv_bfloat162 v0 = __floats2bfloat162_rn(W[(k + 0) * 256 + wc], W[(k + 1) * 256 + wc]);
    __nv_bfloat162 v1 = __floats2bfloat162_rn(W[(k + 8) * 256 + wc], W[(k + 9) * 256 + wc]);
    g_Wp[l][idx] = make_uint2(*(unsigned*)&v0, *(unsigned*)&v1);
}

// ---------------- tensor-core GEMM ----------------
#define TBM 64
__global__ void gemm_mma_kernel(const float* __restrict__ bias, int layer) {
    __shared__ __nv_bfloat16 As[TBM][136];
    int tid = threadIdx.x;
    int m0 = blockIdx.y * TBM;
    int n0 = blockIdx.x * 256;

#pragma unroll
    for (int i = 0; i < 4; i++) {
        int idx = tid + i * 256;
        int r = idx >> 4, cs = idx & 15;
        uint4 v = make_uint4(0, 0, 0, 0);
        if (m0 + r < N_NODES) v = *(const uint4*)(g_xh + (size_t)(m0 + r) * NODE_D + cs * 8);
        *(uint4*)&As[r][cs * 8] = v;
    }
    __syncthreads();

    int wid = tid >> 5, lane = tid & 31;
    int wm = wid >> 2, wn = wid & 3;
    int g = lane >> 2, u = lane & 3;
    int mbase = wm * 32;
    int ntile0 = (n0 + wn * 64) >> 3;
    const uint2* Wp = g_Wp[layer];

    float acc[2][8][4];
#pragma unroll
    for (int a = 0; a < 2; a++)
#pragma unroll
        for (int b = 0; b < 8; b++)
#pragma unroll
            for (int c = 0; c < 4; c++) acc[a][b][c] = 0.f;

#pragma unroll
    for (int kt = 0; kt < 8; kt++) {
        int k0 = kt * 16;
        unsigned afr[2][4];
#pragma unroll
        for (int mf = 0; mf < 2; mf++) {
            int rb = mbase + mf * 16;
            afr[mf][0] = *(unsigned*)&As[rb + g][k0 + 2 * u];
            afr[mf][1] = *(unsigned*)&As[rb + g + 8][k0 + 2 * u];
            afr[mf][2] = *(unsigned*)&As[rb + g][k0 + 8 + 2 * u];
            afr[mf][3] = *(unsigned*)&As[rb + g + 8][k0 + 8 + 2 * u];
        }
        uint2 bfr[8];
#pragma unroll
        for (int j = 0; j < 8; j++)
            bfr[j] = Wp[(kt * 64 + ntile0 + j) * 32 + lane];
#pragma unroll
        for (int mf = 0; mf < 2; mf++)
#pragma unroll
            for (int j = 0; j < 8; j++)
                mma_bf16(acc[mf][j], afr[mf], bfr[j]);
    }

#pragma unroll
    for (int mf = 0; mf < 2; mf++) {
        int row0 = m0 + mbase + mf * 16 + g;
#pragma unroll
        for (int j = 0; j < 8; j++) {
            int col = n0 + wn * 64 + j * 8 + 2 * u;
            float* ac = acc[mf][j];
            if (n0 == 0) {
                float2 bv = *(const float2*)(bias + col);
                if (row0 < N_NODES)
                    *(float2*)(g_A + (size_t)row0 * 256 + col) =
                        make_float2(ac[0] + bv.x, ac[1] + bv.y);
                if (row0 + 8 < N_NODES)
                    *(float2*)(g_A + (size_t)(row0 + 8) * 256 + col) =
                        make_float2(ac[2] + bv.x, ac[3] + bv.y);
            } else {
                int cb = col - 256;
                if (row0 < N_NODES) {
                    __nv_bfloat162 p = __floats2bfloat162_rn(ac[0], ac[1]);
                    *(unsigned*)(g_Bh + (size_t)row0 * 256 + cb) = *(unsigned*)&p;
                }
                if (row0 + 8 < N_NODES) {
                    __nv_bfloat162 p = __floats2bfloat162_rn(ac[2], ac[3]);
                    *(unsigned*)(g_Bh + (size_t)(row0 + 8) * 256 + cb) = *(unsigned*)&p;
                }
            }
        }
    }
}

// ---------------- fused edge aggregation (unroll-4) + LN + residual + softplus ----------------
template <bool LAST>
__global__ void edge_agg_kernel(const float* __restrict__ lng,
                                const float* __restrict__ lnb,
                                const int* __restrict__ batch,
                                int layer) {
    int n = blockIdx.x * 8 + (threadIdx.x >> 5);
    if (n >= N_NODES) return;
    int lane = threadIdx.x & 31;

    int row = g_rowstart[n];
    int end = g_rowstart[n + 1];

    const float4* Arow = (const float4*)(g_A + (size_t)n * 256);
    float4 a1 = Arow[lane];
    float4 a2 = Arow[32 + lane];
    const __nv_bfloat16* tabf = g_tabf[layer];

    float4 acc = make_float4(0.f, 0.f, 0.f, 0.f);

    int e = row;
    for (; e + 3 < end; e += 4) {
        uint2 ed0 = __ldg(&g_edge[e + 0]);
        uint2 ed1 = __ldg(&g_edge[e + 1]);
        uint2 ed2 = __ldg(&g_edge[e + 2]);
        uint2 ed3 = __ldg(&g_edge[e + 3]);

        const __nv_bfloat16* B0 = g_Bh + (size_t)ed0.x * 256;
        const __nv_bfloat16* T0 = tabf + (size_t)ed0.y * 256;
        const __nv_bfloat16* B1 = g_Bh + (size_t)ed1.x * 256;
        const __nv_bfloat16* T1 = tabf + (size_t)ed1.y * 256;
        const __nv_bfloat16* B2 = g_Bh + (size_t)ed2.x * 256;
        const __nv_bfloat16* T2 = tabf + (size_t)ed2.y * 256;
        const __nv_bfloat16* B3 = g_Bh + (size_t)ed3.x * 256;
        const __nv_bfloat16* T3 = tabf + (size_t)ed3.y * 256;

        uint2 b10 = *(const uint2*)(B0 + 4 * lane), b20 = *(const uint2*)(B0 + 128 + 4 * lane);
        uint2 t10 = *(const uint2*)(T0 + 4 * lane), t20 = *(const uint2*)(T0 + 128 + 4 * lane);
        uint2 b11 = *(const uint2*)(B1 + 4 * lane), b21 = *(const uint2*)(B1 + 128 + 4 * lane);
        uint2 t11 = *(const uint2*)(T1 + 4 * lane), t21 = *(const uint2*)(T1 + 128 + 4 * lane);
        uint2 b12 = *(const uint2*)(B2 + 4 * lane), b22 = *(const uint2*)(B2 + 128 + 4 * lane);
        uint2 t12 = *(const uint2*)(T2 + 4 * lane), t22 = *(const uint2*)(T2 + 128 + 4 * lane);
        uint2 b13 = *(const uint2*)(B3 + 4 * lane), b23 = *(const uint2*)(B3 + 128 + 4 * lane);
        uint2 t13 = *(const uint2*)(T3 + 4 * lane), t23 = *(const uint2*)(T3 + 128 + 4 * lane);

        edge_accum(a1, a2, b10, b20, t10, t20, acc);
        edge_accum(a1, a2, b11, b21, t11, t21, acc);
        edge_accum(a1, a2, b12, b22, t12, t22, acc);
        edge_accum(a1, a2, b13, b23, t13, t23, acc);
    }
    for (; e < end; e++) {
        uint2 ed = __ldg(&g_edge[e]);
        const __nv_bfloat16* Bb = g_Bh + (size_t)ed.x * 256;
        const __nv_bfloat16* Tp = tabf + (size_t)ed.y * 256;
        uint2 b1u = *(const uint2*)(Bb + 4 * lane);
        uint2 b2u = *(const uint2*)(Bb + 128 + 4 * lane);
        uint2 t1u = *(const uint2*)(Tp + 4 * lane);
        uint2 t2u = *(const uint2*)(Tp + 128 + 4 * lane);
        edge_accum(a1, a2, b1u, b2u, t1u, t2u, acc);
    }

    float s  = acc.x + acc.y + acc.z + acc.w;
    float ss = acc.x * acc.x + acc.y * acc.y + acc.z * acc.z + acc.w * acc.w;
#pragma unroll
    for (int off = 16; off > 0; off >>= 1) {
        s  += __shfl_xor_sync(0xffffffffu, s, off);
        ss += __shfl_xor_sync(0xffffffffu, ss, off);
    }
    float mu = s * (1.f / 128.f);
    float var = ss * (1.f / 128.f) - mu * mu;
    float rinv = rsqrtf(var + 1e-5f);

    float4 gg = ((const float4*)lng)[lane];
    float4 bb = ((const float4*)lnb)[lane];
    float4 xo = ((float4*)g_x)[(size_t)n * 32 + lane];
    float4 o;
    o.x = softplusf((acc.x - mu) * rinv * gg.x + bb.x + xo.x);
    o.y = softplusf((acc.y - mu) * rinv * gg.y + bb.y + xo.y);
    o.z = softplusf((acc.z - mu) * rinv * gg.z + bb.z + xo.z);
    o.w = softplusf((acc.w - mu) * rinv * gg.w + bb.w + xo.w);

    if (!LAST) {
        ((float4*)g_x)[(size_t)n * 32 + lane] = o;
        __nv_bfloat162 p0 = __floats2bfloat162_rn(o.x, o.y);
        __nv_bfloat162 p1 = __floats2bfloat162_rn(o.z, o.w);
        ((uint2*)g_xh)[(size_t)n * 32 + lane] = make_uint2(*(unsigned*)&p0, *(unsigned*)&p1);
    } else {
        int b = 0;
        if (lane == 0) b = batch[n];
        b = __shfl_sync(0xffffffffu, b, 0);
        float* base = g_pool + (size_t)b * NODE_D + 4 * lane;
        atomicAdd(base + 0, o.x);
        atomicAdd(base + 1, o.y);
        atomicAdd(base + 2, o.z);
        atomicAdd(base + 3, o.w);
    }
}

// ---------------- head MLP ----------------
__global__ void head_kernel(const float* __restrict__ cfc_w, const float* __restrict__ cfc_b,
                            const float* __restrict__ fc_w,  const float* __restrict__ fc_b,
                            const float* __restrict__ out_w, const float* __restrict__ out_b,
                            float* __restrict__ out) {
    __shared__ float h0[FC_D], h1[FC_D];
    __shared__ float red[4];
    int g = blockIdx.x, c = threadIdx.x;
    float cn = fmaxf(g_cnt[g], 1.f);
    h0[c] = g_pool[(size_t)g * NODE_D + c] / cn;
    __syncthreads();
    float acc = cfc_b[c];
#pragma unroll 4
    for (int k = 0; k < NODE_D; k++) acc += h0[k] * cfc_w[k * FC_D + c];
    h1[c] = softplusf(acc);
    __syncthreads();
    acc = fc_b[c];
#pragma unroll 4
    for (int k = 0; k < FC_D; k++) acc += h1[k] * fc_w[k * FC_D + c];
    h0[c] = softplusf(acc);
    __syncthreads();
    acc = fc_b[FC_D + c];
#pragma unroll 4
    for (int k = 0; k < FC_D; k++) acc += h0[k] * fc_w[FC_D * FC_D + k * FC_D + c];
    h1[c] = softplusf(acc);
    __syncthreads();
    float p = h1[c] * out_w[c];
#pragma unroll
    for (int off = 16; off > 0; off >>= 1) p += __shfl_xor_sync(0xffffffffu, p, off);
    if ((c & 31) == 0) red[c >> 5] = p;
    __syncthreads();
    if (c == 0) out[g] = red[0] + red[1] + red[2] + red[3] + out_b[0];
}

// ---------------- launch ----------------
extern "C" void kernel_launch(void* const* d_in, const int* in_sizes, int n_in,
                              void* d_out, int out_size) {
    const int*   z         = (const int*)d_in[0];
    const float* R         = (const float*)d_in[1];
    const int*   ei        = (const int*)d_in[2];
    const int*   batch     = (const int*)d_in[3];
    const float* embedding = (const float*)d_in[4];
    const float* emb_w     = (const float*)d_in[5];
    const float* emb_b     = (const float*)d_in[6];
    const float* conv_w    = (const float*)d_in[7];
    const float* conv_b    = (const float*)d_in[8];
    const float* ln_g      = (const float*)d_in[9];
    const float* ln_b      = (const float*)d_in[10];
    const float* cfc_w     = (const float*)d_in[11];
    const float* cfc_b     = (const float*)d_in[12];
    const float* fc_w      = (const float*)d_in[13];
    const float* fc_b      = (const float*)d_in[14];
    const float* out_w     = (const float*)d_in[15];
    const float* out_b     = (const float*)d_in[16];
    float* out = (float*)d_out;

    const int* src = ei;
    const int* dst = ei + N_EDGES;

    // secondary stream for weight-prep overlap (created once, outside capture)
    static cudaStream_t s_prep = nullptr;
    static cudaEvent_t ev_fork = nullptr, ev_join = nullptr;
    if (s_prep == nullptr) {
        cudaStreamCreateWithFlags(&s_prep, cudaStreamNonBlocking);
        cudaEventCreateWithFlags(&ev_fork, cudaEventDisableTiming);
        cudaEventCreateWithFlags(&ev_join, cudaEventDisableTiming);
    }

    // fork: weight-only prep on s_prep
    cudaEventRecord(ev_fork, 0);
    cudaStreamWaitEvent(s_prep, ev_fork, 0);
    pack_w_kernel<<<dim3(64, N_CONV), 256, 0, s_prep>>>(conv_w);
    build_tab_kernel<<<dim3(N_T, N_CONV), 256, 0, s_prep>>>(conv_w);
    expand_tab_kernel<<<dim3(NTF, N_CONV), 256, 0, s_prep>>>();
    cudaEventRecord(ev_join, s_prep);

    // main chain: embedding + edge sort
    zero_misc_kernel<<<SGRID, SB>>>();
    emb_table_kernel<<<100, NODE_D>>>(embedding, emb_w, emb_b);
    embed_gather_kernel<<<(N_NODES + 7) / 8, 256>>>(z);
    graph_count_kernel<<<1, 256>>>(batch);
    hist_kernel<<<(N_EDGES + 255) / 256, 256>>>(dst);
    scan_pass1<<<SGRID, SB>>>();
    scan_pass2<<<1, SB>>>();
    scan_pass3<<<SGRID, SB>>>();
    scatter_kernel<<<(N_EDGES + 255) / 256, 256>>>(R, src, dst);

    // join prep before conv layers
    cudaStreamWaitEvent(0, ev_join, 0);

    for (int l = 0; l < N_CONV; l++) {
        const float* bl = conv_b + (size_t)l * 256;
        dim3 ggrid(2, (N_NODES + TBM - 1) / TBM);
        gemm_mma_kernel<<<ggrid, 256>>>(bl, l);
        if (l < N_CONV - 1)
            edge_agg_kernel<false><<<(N_NODES + 7) / 8, 256>>>(
                ln_g + l * NODE_D, ln_b + l * NODE_D, batch, l);
        else
            edge_agg_kernel<true><<<(N_NODES + 7) / 8, 256>>>(
                ln_g + l * NODE_D, ln_b + l * NODE_D, batch, l);
    }

    head_kernel<<<N_GRAPHS, FC_D>>>(cfc_w, cfc_b, fc_w, fc_b, out_w, out_b, out);
}

// round 13
// speedup vs baseline: 3.0276x; 1.0032x over previous
#include <cuda_runtime.h>
#include <cuda_bf16.h>
#include <math.h>

#define N_NODES  50000
#define N_EDGES  800000
#define NODE_D   128
#define EDGE_D   100
#define EMB_D    92
#define N_GRAPHS 256
#define N_CONV   3
#define FC_D     128

#define DELTA    (6.0f / 99.0f)
#define N_T      1800
#define H_T      (DELTA / 16.0f)
#define NTF      (16 * (N_T - 1))          // 28784 fine rows
#define H_F      (DELTA / 256.0f)

#define SB    256
#define SGRID ((N_NODES + SB - 1) / SB)

// ---------------- scratch (device globals) ----------------
__device__ float g_embt[100 * NODE_D];
__device__ float g_x[N_NODES * NODE_D];
__device__ __nv_bfloat16 g_xh[N_NODES * NODE_D];
__device__ float g_A[N_NODES * 256];
__device__ __nv_bfloat16 g_Bh[N_NODES * 256];
__device__ uint2 g_Wp[N_CONV][8 * 64 * 32];
__device__ float g_tab[N_CONV][N_T * 256];
__device__ __nv_bfloat16 g_tabf[N_CONV][(size_t)NTF * 256];
__device__ int   g_deg[N_NODES];
__device__ int   g_off[N_NODES];
__device__ int   g_rowstart[N_NODES + 1];
__device__ int   g_bsum[SGRID];
__device__ uint2 g_edge[N_EDGES];
__device__ float g_pool[N_GRAPHS * NODE_D];
__device__ float g_cnt[N_GRAPHS];

// ---------------- fast math helpers ----------------
__device__ __forceinline__ float softplusf(float x) {
    return fmaxf(x, 0.f) + __logf(1.f + __expf(-fabsf(x)));
}
__device__ __forceinline__ float bflo(unsigned u) { return __uint_as_float(u << 16); }
__device__ __forceinline__ float bfhi(unsigned u) { return __uint_as_float(u & 0xffff0000u); }

// packed bf16x2 add (b + t fusion)
__device__ __forceinline__ unsigned bf2add(unsigned a, unsigned b) {
    unsigned r;
    asm("add.rn.bf16x2 %0, %1, %2;" : "=r"(r) : "r"(a), "r"(b));
    return r;
}

// packed f16x2 sigmoid via tanh.approx.f16x2: sigma(x) = 0.5*tanh(x/2)+0.5
__device__ __forceinline__ float2 sigmoid2(float x, float y) {
    unsigned h;
    asm("cvt.rn.f16x2.f32 %0, %1, %2;" : "=r"(h) : "f"(y * 0.5f), "f"(x * 0.5f));
    asm("tanh.approx.f16x2 %0, %0;" : "+r"(h));
    float tx, ty;
    asm("{ .reg .b16 lo, hi; mov.b32 {lo, hi}, %2; cvt.f32.f16 %0, lo; cvt.f32.f16 %1, hi; }"
        : "=f"(tx), "=f"(ty) : "r"(h));
    return make_float2(fmaf(0.5f, tx, 0.5f), fmaf(0.5f, ty, 0.5f));
}

__device__ __forceinline__ void mma_bf16(float* c, const unsigned* a, uint2 b) {
    asm volatile(
        "mma.sync.aligned.m16n8k16.row.col.f32.bf16.bf16.f32 "
        "{%0,%1,%2,%3}, {%4,%5,%6,%7}, {%8,%9}, {%0,%1,%2,%3};"
        : "+f"(c[0]), "+f"(c[1]), "+f"(c[2]), "+f"(c[3])
        : "r"(a[0]), "r"(a[1]), "r"(a[2]), "r"(a[3]), "r"(b.x), "r"(b.y));
}

// per-edge message accumulate
__device__ __forceinline__ void edge_accum(const float4& a1, const float4& a2,
                                           uint2 b1u, uint2 b2u, uint2 t1u, uint2 t2u,
                                           float4& acc) {
    unsigned s10 = bf2add(b1u.x, t1u.x), s11 = bf2add(b1u.y, t1u.y);
    unsigned s20 = bf2add(b2u.x, t2u.x), s21 = bf2add(b2u.y, t2u.y);
    float4 z1, z2;
    z1.x = a1.x + bflo(s10); z1.y = a1.y + bfhi(s10);
    z1.z = a1.z + bflo(s11); z1.w = a1.w + bfhi(s11);
    z2.x = a2.x + bflo(s20); z2.y = a2.y + bfhi(s20);
    z2.z = a2.z + bflo(s21); z2.w = a2.w + bfhi(s21);
    float2 sA = sigmoid2(z1.x, z1.y);
    float2 sB = sigmoid2(z1.z, z1.w);
    acc.x = fmaf(sA.x, softplusf(z2.x), acc.x);
    acc.y = fmaf(sA.y, softplusf(z2.y), acc.y);
    acc.z = fmaf(sB.x, softplusf(z2.z), acc.z);
    acc.w = fmaf(sB.y, softplusf(z2.w), acc.w);
}

// ---------------- zero ----------------
__global__ void zero_misc_kernel() {
    int i = blockIdx.x * blockDim.x + threadIdx.x;
    if (i < N_NODES) g_deg[i] = 0;
    if (i < N_GRAPHS * NODE_D) g_pool[i] = 0.f;
}

// ---------------- emb_table = embedding @ emb_w + emb_b ----------------
__global__ void emb_table_kernel(const float* __restrict__ emb,
                                 const float* __restrict__ W,
                                 const float* __restrict__ b) {
    __shared__ float er[EMB_D];
    int r = blockIdx.x;
    if (threadIdx.x < EMB_D) er[threadIdx.x] = emb[r * EMB_D + threadIdx.x];
    __syncthreads();
    int c = threadIdx.x;
    float acc = b[c];
#pragma unroll 4
    for (int k = 0; k < EMB_D; k++) acc += er[k] * W[k * NODE_D + c];
    g_embt[r * NODE_D + c] = acc;
}

// ---------------- x0 = emb_table[z] ----------------
__global__ void embed_gather_kernel(const int* __restrict__ z) {
    int n = blockIdx.x * 8 + (threadIdx.x >> 5);
    if (n >= N_NODES) return;
    int lane = threadIdx.x & 31;
    int zi = 0;
    if (lane == 0) zi = z[n];
    zi = __shfl_sync(0xffffffffu, zi, 0);
    float4 v = ((const float4*)g_embt)[zi * 32 + lane];
    ((float4*)g_x)[(size_t)n * 32 + lane] = v;
    __nv_bfloat162 p0 = __floats2bfloat162_rn(v.x, v.y);
    __nv_bfloat162 p1 = __floats2bfloat162_rn(v.z, v.w);
    ((uint2*)g_xh)[(size_t)n * 32 + lane] = make_uint2(*(unsigned*)&p0, *(unsigned*)&p1);
}

// ---------------- graph node counts: binary search on sorted batch ----------------
__global__ void graph_count_kernel(const int* __restrict__ batch) {
    int g = threadIdx.x;
    if (g >= N_GRAPHS) return;
    int lo = 0, hi = N_NODES;
    while (lo < hi) { int m = (lo + hi) >> 1; if (batch[m] < g) lo = m + 1; else hi = m; }
    int a = lo;
    lo = 0; hi = N_NODES;
    while (lo < hi) { int m = (lo + hi) >> 1; if (batch[m] <= g) lo = m + 1; else hi = m; }
    g_cnt[g] = (float)(lo - a);
}

// ---------------- counting sort by dst ----------------
__global__ void hist_kernel(const int* __restrict__ dst) {
    int e = blockIdx.x * blockDim.x + threadIdx.x;
    if (e < N_EDGES) atomicAdd(&g_deg[dst[e]], 1);
}

__global__ void scan_pass1() {
    __shared__ int ws[8];
    int i = blockIdx.x * SB + threadIdx.x;
    int v = (i < N_NODES) ? g_deg[i] : 0;
#pragma unroll
    for (int off = 16; off > 0; off >>= 1) v += __shfl_xor_sync(0xffffffffu, v, off);
    if ((threadIdx.x & 31) == 0) ws[threadIdx.x >> 5] = v;
    __syncthreads();
    if (threadIdx.x == 0) {
        int s = 0;
#pragma unroll
        for (int w = 0; w < 8; w++) s += ws[w];
        g_bsum[blockIdx.x] = s;
    }
}

__global__ void scan_pass2() {
    __shared__ int sm[SB];
    int t = threadIdx.x;
    int v = (t < SGRID) ? g_bsum[t] : 0;
    sm[t] = v;
    __syncthreads();
#pragma unroll
    for (int off = 1; off < SB; off <<= 1) {
        int u = (t >= off) ? sm[t - off] : 0;
        __syncthreads();
        sm[t] += u;
        __syncthreads();
    }
    if (t < SGRID) g_bsum[t] = sm[t] - v;
}

__global__ void scan_pass3() {
    __shared__ int sm[SB];
    int t = threadIdx.x;
    int i = blockIdx.x * SB + t;
    int v = (i < N_NODES) ? g_deg[i] : 0;
    sm[t] = v;
    __syncthreads();
#pragma unroll
    for (int off = 1; off < SB; off <<= 1) {
        int u = (t >= off) ? sm[t - off] : 0;
        __syncthreads();
        sm[t] += u;
        __syncthreads();
    }
    int ex = g_bsum[blockIdx.x] + sm[t] - v;
    if (i < N_NODES) {
        g_rowstart[i] = ex;
        g_off[i] = ex;
        if (i == N_NODES - 1) g_rowstart[N_NODES] = ex + v;
    }
}

__global__ void scatter_kernel(const float* __restrict__ R,
                               const int* __restrict__ src,
                               const int* __restrict__ dst) {
    int e = blockIdx.x * blockDim.x + threadIdx.x;
    if (e >= N_EDGES) return;
    int s = src[e], d = dst[e];
    float dx = R[s * 3 + 0] - R[d * 3 + 0];
    float dy = R[s * 3 + 1] - R[d * 3 + 1];
    float dz = R[s * 3 + 2] - R[d * 3 + 2];
    float dist = sqrtf(dx * dx + dy * dy + dz * dz);
    int t = (int)(fminf(dist / H_F + 0.5f, (float)(NTF - 1)));
    int pos = atomicAdd(&g_off[d], 1);
    g_edge[pos] = make_uint2((unsigned)s, (unsigned)t);
}

// ---------------- coarse tables, all layers ----------------
__global__ void build_tab_kernel(const float* __restrict__ conv_w) {
    __shared__ float gs[EDGE_D];
    int l = blockIdx.y;
    const float* W3 = conv_w + (size_t)l * 356 * 256 + 256 * 256;
    int t = blockIdx.x;
    float d = (float)t * H_T;
    const float coeff = -0.5f / (DELTA * DELTA);
    if (threadIdx.x < EDGE_D) {
        float u = d - (float)threadIdx.x * DELTA;
        gs[threadIdx.x] = expf(coeff * u * u);
    }
    __syncthreads();
    int c = threadIdx.x;
    float acc = 0.f;
#pragma unroll 4
    for (int k = 0; k < EDGE_D; k++) acc += gs[k] * W3[k * 256 + c];
    g_tab[l][(size_t)t * 256 + c] = acc;
}

__global__ void expand_tab_kernel() {
    int l = blockIdx.y;
    int tf = blockIdx.x;
    int c = threadIdx.x;
    int t = tf >> 4;
    float f = (float)(tf & 15) * (1.f / 16.f);
    float lo = g_tab[l][(size_t)t * 256 + c];
    float hi = g_tab[l][(size_t)(t + 1) * 256 + c];
    g_tabf[l][(size_t)tf * 256 + c] = __float2bfloat16(fmaf(f, hi - lo, lo));
}

__global__ void pack_w_kernel(const float* __restrict__ conv_w) {
    int l = blockIdx.y;
    const float* Wl = conv_w + (size_t)l * 356 * 256;
    int idx = blockIdx.x * 256 + threadIdx.x;
    if (idx >= 8 * 64 * 32) return;
    int lane = idx & 31;
    int ntile = (idx >> 5) & 63;
    int kt = idx >> 11;
    int u = lane & 3, c = lane >> 2;
    int n = ntile * 8 + c;
    const float* W = Wl + ((n < 256) ? 0 : 128 * 256);
    int wc = n & 255;
    int k = kt * 16 + 2 * u;
    __nv_bfloat162 v0 = __floats2bfloat162_rn(W[(k + 0) * 256 + wc], W[(k + 1) * 256 + wc]);
    __nv_bfloat162 v1 = __floats2bfloat162_rn(W[(k + 8) * 256 + wc], W[(k + 9) * 256 + wc]);
    g_Wp[l][idx] = make_uint2(*(unsigned*)&v0, *(unsigned*)&v1);
}

// ---------------- tensor-core GEMM ----------------
#define TBM 64
__global__ void gemm_mma_kernel(const float* __restrict__ bias, int layer) {
    __shared__ __nv_bfloat16 As[TBM][136];
    int tid = threadIdx.x;
    int m0 = blockIdx.y * TBM;
    int n0 = blockIdx.x * 256;

#pragma unroll
    for (int i = 0; i < 4; i++) {
        int idx = tid + i * 256;
        int r = idx >> 4, cs = idx & 15;
        uint4 v = make_uint4(0, 0, 0, 0);
        if (m0 + r < N_NODES) v = *(const uint4*)(g_xh + (size_t)(m0 + r) * NODE_D + cs * 8);
        *(uint4*)&As[r][cs * 8] = v;
    }
    __syncthreads();

    int wid = tid >> 5, lane = tid & 31;
    int wm = wid >> 2, wn = wid & 3;
    int g = lane >> 2, u = lane & 3;
    int mbase = wm * 32;
    int ntile0 = (n0 + wn * 64) >> 3;
    const uint2* Wp = g_Wp[layer];

    float acc[2][8][4];
#pragma unroll
    for (int a = 0; a < 2; a++)
#pragma unroll
        for (int b = 0; b < 8; b++)
#pragma unroll
            for (int c = 0; c < 4; c++) acc[a][b][c] = 0.f;

#pragma unroll
    for (int kt = 0; kt < 8; kt++) {
        int k0 = kt * 16;
        unsigned afr[2][4];
#pragma unroll
        for (int mf = 0; mf < 2; mf++) {
            int rb = mbase + mf * 16;
            afr[mf][0] = *(unsigned*)&As[rb + g][k0 + 2 * u];
            afr[mf][1] = *(unsigned*)&As[rb + g + 8][k0 + 2 * u];
            afr[mf][2] = *(unsigned*)&As[rb + g][k0 + 8 + 2 * u];
            afr[mf][3] = *(unsigned*)&As[rb + g + 8][k0 + 8 + 2 * u];
        }
        uint2 bfr[8];
#pragma unroll
        for (int j = 0; j < 8; j++)
            bfr[j] = Wp[(kt * 64 + ntile0 + j) * 32 + lane];
#pragma unroll
        for (int mf = 0; mf < 2; mf++)
#pragma unroll
            for (int j = 0; j < 8; j++)
                mma_bf16(acc[mf][j], afr[mf], bfr[j]);
    }

#pragma unroll
    for (int mf = 0; mf < 2; mf++) {
        int row0 = m0 + mbase + mf * 16 + g;
#pragma unroll
        for (int j = 0; j < 8; j++) {
            int col = n0 + wn * 64 + j * 8 + 2 * u;
            float* ac = acc[mf][j];
            if (n0 == 0) {
                float2 bv = *(const float2*)(bias + col);
                if (row0 < N_NODES)
                    *(float2*)(g_A + (size_t)row0 * 256 + col) =
                        make_float2(ac[0] + bv.x, ac[1] + bv.y);
                if (row0 + 8 < N_NODES)
                    *(float2*)(g_A + (size_t)(row0 + 8) * 256 + col) =
                        make_float2(ac[2] + bv.x, ac[3] + bv.y);
            } else {
                int cb = col - 256;
                if (row0 < N_NODES) {
                    __nv_bfloat162 p = __floats2bfloat162_rn(ac[0], ac[1]);
                    *(unsigned*)(g_Bh + (size_t)row0 * 256 + cb) = *(unsigned*)&p;
                }
                if (row0 + 8 < N_NODES) {
                    __nv_bfloat162 p = __floats2bfloat162_rn(ac[2], ac[3]);
                    *(unsigned*)(g_Bh + (size_t)(row0 + 8) * 256 + cb) = *(unsigned*)&p;
                }
            }
        }
    }
}

// ---------------- fused edge aggregation (1 warp = 1 block = 1 node) ----------------
template <bool LAST>
__global__ void __launch_bounds__(32) edge_agg_kernel(const float* __restrict__ lng,
                                                      const float* __restrict__ lnb,
                                                      const int* __restrict__ batch,
                                                      int layer) {
    int n = blockIdx.x;
    int lane = threadIdx.x;

    int row = g_rowstart[n];
    int end = g_rowstart[n + 1];

    const float4* Arow = (const float4*)(g_A + (size_t)n * 256);
    float4 a1 = Arow[lane];
    float4 a2 = Arow[32 + lane];
    const __nv_bfloat16* tabf = g_tabf[layer];

    float4 acc = make_float4(0.f, 0.f, 0.f, 0.f);

    int e = row;
    for (; e + 3 < end; e += 4) {
        uint2 ed0 = __ldg(&g_edge[e + 0]);
        uint2 ed1 = __ldg(&g_edge[e + 1]);
        uint2 ed2 = __ldg(&g_edge[e + 2]);
        uint2 ed3 = __ldg(&g_edge[e + 3]);

        const __nv_bfloat16* B0 = g_Bh + (size_t)ed0.x * 256;
        const __nv_bfloat16* T0 = tabf + (size_t)ed0.y * 256;
        const __nv_bfloat16* B1 = g_Bh + (size_t)ed1.x * 256;
        const __nv_bfloat16* T1 = tabf + (size_t)ed1.y * 256;
        const __nv_bfloat16* B2 = g_Bh + (size_t)ed2.x * 256;
        const __nv_bfloat16* T2 = tabf + (size_t)ed2.y * 256;
        const __nv_bfloat16* B3 = g_Bh + (size_t)ed3.x * 256;
        const __nv_bfloat16* T3 = tabf + (size_t)ed3.y * 256;

        uint2 b10 = *(const uint2*)(B0 + 4 * lane), b20 = *(const uint2*)(B0 + 128 + 4 * lane);
        uint2 t10 = *(const uint2*)(T0 + 4 * lane), t20 = *(const uint2*)(T0 + 128 + 4 * lane);
        uint2 b11 = *(const uint2*)(B1 + 4 * lane), b21 = *(const uint2*)(B1 + 128 + 4 * lane);
        uint2 t11 = *(const uint2*)(T1 + 4 * lane), t21 = *(const uint2*)(T1 + 128 + 4 * lane);
        uint2 b12 = *(const uint2*)(B2 + 4 * lane), b22 = *(const uint2*)(B2 + 128 + 4 * lane);
        uint2 t12 = *(const uint2*)(T2 + 4 * lane), t22 = *(const uint2*)(T2 + 128 + 4 * lane);
        uint2 b13 = *(const uint2*)(B3 + 4 * lane), b23 = *(const uint2*)(B3 + 128 + 4 * lane);
        uint2 t13 = *(const uint2*)(T3 + 4 * lane), t23 = *(const uint2*)(T3 + 128 + 4 * lane);

        edge_accum(a1, a2, b10, b20, t10, t20, acc);
        edge_accum(a1, a2, b11, b21, t11, t21, acc);
        edge_accum(a1, a2, b12, b22, t12, t22, acc);
        edge_accum(a1, a2, b13, b23, t13, t23, acc);
    }
    for (; e < end; e++) {
        uint2 ed = __ldg(&g_edge[e]);
        const __nv_bfloat16* Bb = g_Bh + (size_t)ed.x * 256;
        const __nv_bfloat16* Tp = tabf + (size_t)ed.y * 256;
        uint2 b1u = *(const uint2*)(Bb + 4 * lane);
        uint2 b2u = *(const uint2*)(Bb + 128 + 4 * lane);
        uint2 t1u = *(const uint2*)(Tp + 4 * lane);
        uint2 t2u = *(const uint2*)(Tp + 128 + 4 * lane);
        edge_accum(a1, a2, b1u, b2u, t1u, t2u, acc);
    }

    float s  = acc.x + acc.y + acc.z + acc.w;
    float ss = acc.x * acc.x + acc.y * acc.y + acc.z * acc.z + acc.w * acc.w;
#pragma unroll
    for (int off = 16; off > 0; off >>= 1) {
        s  += __shfl_xor_sync(0xffffffffu, s, off);
        ss += __shfl_xor_sync(0xffffffffu, ss, off);
    }
    float mu = s * (1.f / 128.f);
    float var = ss * (1.f / 128.f) - mu * mu;
    float rinv = rsqrtf(var + 1e-5f);

    float4 gg = ((const float4*)lng)[lane];
    float4 bb = ((const float4*)lnb)[lane];
    float4 xo = ((float4*)g_x)[(size_t)n * 32 + lane];
    float4 o;
    o.x = softplusf((acc.x - mu) * rinv * gg.x + bb.x + xo.x);
    o.y = softplusf((acc.y - mu) * rinv * gg.y + bb.y + xo.y);
    o.z = softplusf((acc.z - mu) * rinv * gg.z + bb.z + xo.z);
    o.w = softplusf((acc.w - mu) * rinv * gg.w + bb.w + xo.w);

    if (!LAST) {
        ((float4*)g_x)[(size_t)n * 32 + lane] = o;
        __nv_bfloat162 p0 = __floats2bfloat162_rn(o.x, o.y);
        __nv_bfloat162 p1 = __floats2bfloat162_rn(o.z, o.w);
        ((uint2*)g_xh)[(size_t)n * 32 + lane] = make_uint2(*(unsigned*)&p0, *(unsigned*)&p1);
    } else {
        int b = 0;
        if (lane == 0) b = batch[n];
        b = __shfl_sync(0xffffffffu, b, 0);
        float* base = g_pool + (size_t)b * NODE_D + 4 * lane;
        atomicAdd(base + 0, o.x);
        atomicAdd(base + 1, o.y);
        atomicAdd(base + 2, o.z);
        atomicAdd(base + 3, o.w);
    }
}

// ---------------- head MLP ----------------
__global__ void head_kernel(const float* __restrict__ cfc_w, const float* __restrict__ cfc_b,
                            const float* __restrict__ fc_w,  const float* __restrict__ fc_b,
                            const float* __restrict__ out_w, const float* __restrict__ out_b,
                            float* __restrict__ out) {
    __shared__ float h0[FC_D], h1[FC_D];
    __shared__ float red[4];
    int g = blockIdx.x, c = threadIdx.x;
    float cn = fmaxf(g_cnt[g], 1.f);
    h0[c] = g_pool[(size_t)g * NODE_D + c] / cn;
    __syncthreads();
    float acc = cfc_b[c];
#pragma unroll 4
    for (int k = 0; k < NODE_D; k++) acc += h0[k] * cfc_w[k * FC_D + c];
    h1[c] = softplusf(acc);
    __syncthreads();
    acc = fc_b[c];
#pragma unroll 4
    for (int k = 0; k < FC_D; k++) acc += h1[k] * fc_w[k * FC_D + c];
    h0[c] = softplusf(acc);
    __syncthreads();
    acc = fc_b[FC_D + c];
#pragma unroll 4
    for (int k = 0; k < FC_D; k++) acc += h0[k] * fc_w[FC_D * FC_D + k * FC_D + c];
    h1[c] = softplusf(acc);
    __syncthreads();
    float p = h1[c] * out_w[c];
#pragma unroll
    for (int off = 16; off > 0; off >>= 1) p += __shfl_xor_sync(0xffffffffu, p, off);
    if ((c & 31) == 0) red[c >> 5] = p;
    __syncthreads();
    if (c == 0) out[g] = red[0] + red[1] + red[2] + red[3] + out_b[0];
}

// ---------------- launch ----------------
extern "C" void kernel_launch(void* const* d_in, const int* in_sizes, int n_in,
                              void* d_out, int out_size) {
    const int*   z         = (const int*)d_in[0];
    const float* R         = (const float*)d_in[1];
    const int*   ei        = (const int*)d_in[2];
    const int*   batch     = (const int*)d_in[3];
    const float* embedding = (const float*)d_in[4];
    const float* emb_w     = (const float*)d_in[5];
    const float* emb_b     = (const float*)d_in[6];
    const float* conv_w    = (const float*)d_in[7];
    const float* conv_b    = (const float*)d_in[8];
    const float* ln_g      = (const float*)d_in[9];
    const float* ln_b      = (const float*)d_in[10];
    const float* cfc_w     = (const float*)d_in[11];
    const float* cfc_b     = (const float*)d_in[12];
    const float* fc_w      = (const float*)d_in[13];
    const float* fc_b      = (const float*)d_in[14];
    const float* out_w     = (const float*)d_in[15];
    const float* out_b     = (const float*)d_in[16];
    float* out = (float*)d_out;

    const int* src = ei;
    const int* dst = ei + N_EDGES;

    static cudaStream_t s_prep = nullptr;
    static cudaEvent_t ev_fork = nullptr, ev_join = nullptr;
    if (s_prep == nullptr) {
        cudaStreamCreateWithFlags(&s_prep, cudaStreamNonBlocking);
        cudaEventCreateWithFlags(&ev_fork, cudaEventDisableTiming);
        cudaEventCreateWithFlags(&ev_join, cudaEventDisableTiming);
    }

    // fork: weight-only prep on s_prep
    cudaEventRecord(ev_fork, 0);
    cudaStreamWaitEvent(s_prep, ev_fork, 0);
    pack_w_kernel<<<dim3(64, N_CONV), 256, 0, s_prep>>>(conv_w);
    build_tab_kernel<<<dim3(N_T, N_CONV), 256, 0, s_prep>>>(conv_w);
    expand_tab_kernel<<<dim3(NTF, N_CONV), 256, 0, s_prep>>>();
    cudaEventRecord(ev_join, s_prep);

    // main chain: embedding + edge sort
    zero_misc_kernel<<<SGRID, SB>>>();
    emb_table_kernel<<<100, NODE_D>>>(embedding, emb_w, emb_b);
    embed_gather_kernel<<<(N_NODES + 7) / 8, 256>>>(z);
    graph_count_kernel<<<1, 256>>>(batch);
    hist_kernel<<<(N_EDGES + 255) / 256, 256>>>(dst);
    scan_pass1<<<SGRID, SB>>>();
    scan_pass2<<<1, SB>>>();
    scan_pass3<<<SGRID, SB>>>();
    scatter_kernel<<<(N_EDGES + 255) / 256, 256>>>(R, src, dst);

    // join prep before conv layers
    cudaStreamWaitEvent(0, ev_join, 0);

    for (int l = 0; l < N_CONV; l++) {
        const float* bl = conv_b + (size_t)l * 256;
        dim3 ggrid(2, (N_NODES + TBM - 1) / TBM);
        gemm_mma_kernel<<<ggrid, 256>>>(bl, l);
        if (l < N_CONV - 1)
            edge_agg_kernel<false><<<N_NODES, 32>>>(
                ln_g + l * NODE_D, ln_b + l * NODE_D, batch, l);
        else
            edge_agg_kernel<true><<<N_NODES, 32>>>(
                ln_g + l * NODE_D, ln_b + l * NODE_D, batch, l);
    }

    head_kernel<<<N_GRAPHS, FC_D>>>(cfc_w, cfc_b, fc_w, fc_b, out_w, out_b, out);
}

// round 14
// speedup vs baseline: 3.1827x; 1.0512x over previous
#include <cuda_runtime.h>
#include <cuda_bf16.h>
#include <math.h>

#define N_NODES  50000
#define N_EDGES  800000
#define NODE_D   128
#define EDGE_D   100
#define EMB_D    92
#define N_GRAPHS 256
#define N_CONV   3
#define FC_D     128

#define DELTA    (6.0f / 99.0f)
#define N_T      1800
#define H_T      (DELTA / 16.0f)
#define NTF      (16 * (N_T - 1))          // 28784 fine rows
#define H_F      (DELTA / 256.0f)

#define SB    256
#define SGRID ((N_NODES + SB - 1) / SB)

// ---------------- scratch (device globals) ----------------
__device__ float g_embt[100 * NODE_D];
__device__ float g_x[N_NODES * NODE_D];
__device__ __nv_bfloat16 g_xh[N_NODES * NODE_D];
__device__ float g_A[N_NODES * 256];
__device__ __nv_bfloat16 g_Bh[N_NODES * 256];         // INTERLEAVED: [z1[0],z2[0],z1[1],z2[1],...]
__device__ uint2 g_Wp[N_CONV][8 * 64 * 32];
__device__ float g_tab[N_CONV][N_T * 256];            // logical layout
__device__ __nv_bfloat16 g_tabf[N_CONV][(size_t)NTF * 256];  // INTERLEAVED like g_Bh
__device__ int   g_deg[N_NODES];
__device__ int   g_off[N_NODES];
__device__ int   g_rowstart[N_NODES + 1];
__device__ int   g_bsum[SGRID];
__device__ uint2 g_edge[N_EDGES];
__device__ float g_pool[N_GRAPHS * NODE_D];
__device__ float g_cnt[N_GRAPHS];

// ---------------- fast math helpers ----------------
__device__ __forceinline__ float softplusf(float x) {
    return fmaxf(x, 0.f) + __logf(1.f + __expf(-fabsf(x)));
}
__device__ __forceinline__ float bflo(unsigned u) { return __uint_as_float(u << 16); }
__device__ __forceinline__ float bfhi(unsigned u) { return __uint_as_float(u & 0xffff0000u); }

// packed bf16x2 add (fuses z1 and z2 components of one channel)
__device__ __forceinline__ unsigned bf2add(unsigned a, unsigned b) {
    unsigned r;
    asm("add.rn.bf16x2 %0, %1, %2;" : "=r"(r) : "r"(a), "r"(b));
    return r;
}

// packed f16x2 sigmoid via tanh.approx.f16x2: sigma(x) = 0.5*tanh(x/2)+0.5
__device__ __forceinline__ float2 sigmoid2(float x, float y) {
    unsigned h;
    asm("cvt.rn.f16x2.f32 %0, %1, %2;" : "=r"(h) : "f"(y * 0.5f), "f"(x * 0.5f));
    asm("tanh.approx.f16x2 %0, %0;" : "+r"(h));
    float tx, ty;
    asm("{ .reg .b16 lo, hi; mov.b32 {lo, hi}, %2; cvt.f32.f16 %0, lo; cvt.f32.f16 %1, hi; }"
        : "=f"(tx), "=f"(ty) : "r"(h));
    return make_float2(fmaf(0.5f, tx, 0.5f), fmaf(0.5f, ty, 0.5f));
}

__device__ __forceinline__ void mma_bf16(float* c, const unsigned* a, uint2 b) {
    asm volatile(
        "mma.sync.aligned.m16n8k16.row.col.f32.bf16.bf16.f32 "
        "{%0,%1,%2,%3}, {%4,%5,%6,%7}, {%8,%9}, {%0,%1,%2,%3};"
        : "+f"(c[0]), "+f"(c[1]), "+f"(c[2]), "+f"(c[3])
        : "r"(a[0]), "r"(a[1]), "r"(a[2]), "r"(a[3]), "r"(b.x), "r"(b.y));
}

// per-edge message accumulate (interleaved packed operands)
__device__ __forceinline__ void edge_accum(const float4& a1, const float4& a2,
                                           uint4 bu, uint4 tu, float4& acc) {
    unsigned s0 = bf2add(bu.x, tu.x);
    unsigned s1 = bf2add(bu.y, tu.y);
    unsigned s2 = bf2add(bu.z, tu.z);
    unsigned s3 = bf2add(bu.w, tu.w);
    float4 z1, z2;
    z1.x = a1.x + bflo(s0); z2.x = a2.x + bfhi(s0);
    z1.y = a1.y + bflo(s1); z2.y = a2.y + bfhi(s1);
    z1.z = a1.z + bflo(s2); z2.z = a2.z + bfhi(s2);
    z1.w = a1.w + bflo(s3); z2.w = a2.w + bfhi(s3);
    float2 sA = sigmoid2(z1.x, z1.y);
    float2 sB = sigmoid2(z1.z, z1.w);
    acc.x = fmaf(sA.x, softplusf(z2.x), acc.x);
    acc.y = fmaf(sA.y, softplusf(z2.y), acc.y);
    acc.z = fmaf(sB.x, softplusf(z2.z), acc.z);
    acc.w = fmaf(sB.y, softplusf(z2.w), acc.w);
}

// ---------------- zero ----------------
__global__ void zero_misc_kernel() {
    int i = blockIdx.x * blockDim.x + threadIdx.x;
    if (i < N_NODES) g_deg[i] = 0;
    if (i < N_GRAPHS * NODE_D) g_pool[i] = 0.f;
}

// ---------------- emb_table = embedding @ emb_w + emb_b ----------------
__global__ void emb_table_kernel(const float* __restrict__ emb,
                                 const float* __restrict__ W,
                                 const float* __restrict__ b) {
    __shared__ float er[EMB_D];
    int r = blockIdx.x;
    if (threadIdx.x < EMB_D) er[threadIdx.x] = emb[r * EMB_D + threadIdx.x];
    __syncthreads();
    int c = threadIdx.x;
    float acc = b[c];
#pragma unroll 4
    for (int k = 0; k < EMB_D; k++) acc += er[k] * W[k * NODE_D + c];
    g_embt[r * NODE_D + c] = acc;
}

// ---------------- x0 = emb_table[z] ----------------
__global__ void embed_gather_kernel(const int* __restrict__ z) {
    int n = blockIdx.x * 8 + (threadIdx.x >> 5);
    if (n >= N_NODES) return;
    int lane = threadIdx.x & 31;
    int zi = 0;
    if (lane == 0) zi = z[n];
    zi = __shfl_sync(0xffffffffu, zi, 0);
    float4 v = ((const float4*)g_embt)[zi * 32 + lane];
    ((float4*)g_x)[(size_t)n * 32 + lane] = v;
    __nv_bfloat162 p0 = __floats2bfloat162_rn(v.x, v.y);
    __nv_bfloat162 p1 = __floats2bfloat162_rn(v.z, v.w);
    ((uint2*)g_xh)[(size_t)n * 32 + lane] = make_uint2(*(unsigned*)&p0, *(unsigned*)&p1);
}

// ---------------- graph node counts: binary search on sorted batch ----------------
__global__ void graph_count_kernel(const int* __restrict__ batch) {
    int g = threadIdx.x;
    if (g >= N_GRAPHS) return;
    int lo = 0, hi = N_NODES;
    while (lo < hi) { int m = (lo + hi) >> 1; if (batch[m] < g) lo = m + 1; else hi = m; }
    int a = lo;
    lo = 0; hi = N_NODES;
    while (lo < hi) { int m = (lo + hi) >> 1; if (batch[m] <= g) lo = m + 1; else hi = m; }
    g_cnt[g] = (float)(lo - a);
}

// ---------------- counting sort by dst ----------------
__global__ void hist_kernel(const int* __restrict__ dst) {
    int e = blockIdx.x * blockDim.x + threadIdx.x;
    if (e < N_EDGES) atomicAdd(&g_deg[dst[e]], 1);
}

__global__ void scan_pass1() {
    __shared__ int ws[8];
    int i = blockIdx.x * SB + threadIdx.x;
    int v = (i < N_NODES) ? g_deg[i] : 0;
#pragma unroll
    for (int off = 16; off > 0; off >>= 1) v += __shfl_xor_sync(0xffffffffu, v, off);
    if ((threadIdx.x & 31) == 0) ws[threadIdx.x >> 5] = v;
    __syncthreads();
    if (threadIdx.x == 0) {
        int s = 0;
#pragma unroll
        for (int w = 0; w < 8; w++) s += ws[w];
        g_bsum[blockIdx.x] = s;
    }
}

__global__ void scan_pass2() {
    __shared__ int sm[SB];
    int t = threadIdx.x;
    int v = (t < SGRID) ? g_bsum[t] : 0;
    sm[t] = v;
    __syncthreads();
#pragma unroll
    for (int off = 1; off < SB; off <<= 1) {
        int u = (t >= off) ? sm[t - off] : 0;
        __syncthreads();
        sm[t] += u;
        __syncthreads();
    }
    if (t < SGRID) g_bsum[t] = sm[t] - v;
}

__global__ void scan_pass3() {
    __shared__ int sm[SB];
    int t = threadIdx.x;
    int i = blockIdx.x * SB + t;
    int v = (i < N_NODES) ? g_deg[i] : 0;
    sm[t] = v;
    __syncthreads();
#pragma unroll
    for (int off = 1; off < SB; off <<= 1) {
        int u = (t >= off) ? sm[t - off] : 0;
        __syncthreads();
        sm[t] += u;
        __syncthreads();
    }
    int ex = g_bsum[blockIdx.x] + sm[t] - v;
    if (i < N_NODES) {
        g_rowstart[i] = ex;
        g_off[i] = ex;
        if (i == N_NODES - 1) g_rowstart[N_NODES] = ex + v;
    }
}

__global__ void scatter_kernel(const float* __restrict__ R,
                               const int* __restrict__ src,
                               const int* __restrict__ dst) {
    int e = blockIdx.x * blockDim.x + threadIdx.x;
    if (e >= N_EDGES) return;
    int s = src[e], d = dst[e];
    float dx = R[s * 3 + 0] - R[d * 3 + 0];
    float dy = R[s * 3 + 1] - R[d * 3 + 1];
    float dz = R[s * 3 + 2] - R[d * 3 + 2];
    float dist = sqrtf(dx * dx + dy * dy + dz * dz);
    int t = (int)(fminf(dist / H_F + 0.5f, (float)(NTF - 1)));
    int pos = atomicAdd(&g_off[d], 1);
    g_edge[pos] = make_uint2((unsigned)s, (unsigned)t);
}

// ---------------- coarse tables, all layers (logical layout) ----------------
__global__ void build_tab_kernel(const float* __restrict__ conv_w) {
    __shared__ float gs[EDGE_D];
    int l = blockIdx.y;
    const float* W3 = conv_w + (size_t)l * 356 * 256 + 256 * 256;
    int t = blockIdx.x;
    float d = (float)t * H_T;
    const float coeff = -0.5f / (DELTA * DELTA);
    if (threadIdx.x < EDGE_D) {
        float u = d - (float)threadIdx.x * DELTA;
        gs[threadIdx.x] = expf(coeff * u * u);
    }
    __syncthreads();
    int c = threadIdx.x;
    float acc = 0.f;
#pragma unroll 4
    for (int k = 0; k < EDGE_D; k++) acc += gs[k] * W3[k * 256 + c];
    g_tab[l][(size_t)t * 256 + c] = acc;
}

// ---------------- expand coarse -> fine bf16 (INTERLEAVED channels) ----------------
__global__ void expand_tab_kernel() {
    int l = blockIdx.y;
    int tf = blockIdx.x;
    int c = threadIdx.x;                    // physical position 0..255
    int lc = (c & 1) ? 128 + (c >> 1) : (c >> 1);   // logical channel
    int t = tf >> 4;
    float f = (float)(tf & 15) * (1.f / 16.f);
    float lo = g_tab[l][(size_t)t * 256 + lc];
    float hi = g_tab[l][(size_t)(t + 1) * 256 + lc];
    g_tabf[l][(size_t)tf * 256 + c] = __float2bfloat16(fmaf(f, hi - lo, lo));
}

// ---------------- weight pack (src half column-permuted for interleaved output) ----------------
__global__ void pack_w_kernel(const float* __restrict__ conv_w) {
    int l = blockIdx.y;
    const float* Wl = conv_w + (size_t)l * 356 * 256;
    int idx = blockIdx.x * 256 + threadIdx.x;
    if (idx >= 8 * 64 * 32) return;
    int lane = idx & 31;
    int ntile = (idx >> 5) & 63;
    int kt = idx >> 11;
    int u = lane & 3, c = lane >> 2;
    int n = ntile * 8 + c;                  // physical output col 0..511
    const float* W = Wl + ((n < 256) ? 0 : 128 * 256);
    int wc;
    if (n < 256) {
        wc = n;                             // dst half: logical layout
    } else {
        int p = n - 256;                    // physical col in src half
        wc = (p & 1) ? 128 + (p >> 1) : (p >> 1);   // interleave: 2c->z1[c], 2c+1->z2[c]
    }
    int k = kt * 16 + 2 * u;
    __nv_bfloat162 v0 = __floats2bfloat162_rn(W[(k + 0) * 256 + wc], W[(k + 1) * 256 + wc]);
    __nv_bfloat162 v1 = __floats2bfloat162_rn(W[(k + 8) * 256 + wc], W[(k + 9) * 256 + wc]);
    g_Wp[l][idx] = make_uint2(*(unsigned*)&v0, *(unsigned*)&v1);
}

// ---------------- tensor-core GEMM ----------------
#define TBM 64
__global__ void gemm_mma_kernel(const float* __restrict__ bias, int layer) {
    __shared__ __nv_bfloat16 As[TBM][136];
    int tid = threadIdx.x;
    int m0 = blockIdx.y * TBM;
    int n0 = blockIdx.x * 256;

#pragma unroll
    for (int i = 0; i < 4; i++) {
        int idx = tid + i * 256;
        int r = idx >> 4, cs = idx & 15;
        uint4 v = make_uint4(0, 0, 0, 0);
        if (m0 + r < N_NODES) v = *(const uint4*)(g_xh + (size_t)(m0 + r) * NODE_D + cs * 8);
        *(uint4*)&As[r][cs * 8] = v;
    }
    __syncthreads();

    int wid = tid >> 5, lane = tid & 31;
    int wm = wid >> 2, wn = wid & 3;
    int g = lane >> 2, u = lane & 3;
    int mbase = wm * 32;
    int ntile0 = (n0 + wn * 64) >> 3;
    const uint2* Wp = g_Wp[layer];

    float acc[2][8][4];
#pragma unroll
    for (int a = 0; a < 2; a++)
#pragma unroll
        for (int b = 0; b < 8; b++)
#pragma unroll
            for (int c = 0; c < 4; c++) acc[a][b][c] = 0.f;

#pragma unroll
    for (int kt = 0; kt < 8; kt++) {
        int k0 = kt * 16;
        unsigned afr[2][4];
#pragma unroll
        for (int mf = 0; mf < 2; mf++) {
            int rb = mbase + mf * 16;
            afr[mf][0] = *(unsigned*)&As[rb + g][k0 + 2 * u];
            afr[mf][1] = *(unsigned*)&As[rb + g + 8][k0 + 2 * u];
            afr[mf][2] = *(unsigned*)&As[rb + g][k0 + 8 + 2 * u];
            afr[mf][3] = *(unsigned*)&As[rb + g + 8][k0 + 8 + 2 * u];
        }
        uint2 bfr[8];
#pragma unroll
        for (int j = 0; j < 8; j++)
            bfr[j] = Wp[(kt * 64 + ntile0 + j) * 32 + lane];
#pragma unroll
        for (int mf = 0; mf < 2; mf++)
#pragma unroll
            for (int j = 0; j < 8; j++)
                mma_bf16(acc[mf][j], afr[mf], bfr[j]);
    }

#pragma unroll
    for (int mf = 0; mf < 2; mf++) {
        int row0 = m0 + mbase + mf * 16 + g;
#pragma unroll
        for (int j = 0; j < 8; j++) {
            int col = n0 + wn * 64 + j * 8 + 2 * u;
            float* ac = acc[mf][j];
            if (n0 == 0) {
                float2 bv = *(const float2*)(bias + col);
                if (row0 < N_NODES)
                    *(float2*)(g_A + (size_t)row0 * 256 + col) =
                        make_float2(ac[0] + bv.x, ac[1] + bv.y);
                if (row0 + 8 < N_NODES)
                    *(float2*)(g_A + (size_t)(row0 + 8) * 256 + col) =
                        make_float2(ac[2] + bv.x, ac[3] + bv.y);
            } else {
                int cb = col - 256;          // physical interleaved position
                if (row0 < N_NODES) {
                    __nv_bfloat162 p = __floats2bfloat162_rn(ac[0], ac[1]);
                    *(unsigned*)(g_Bh + (size_t)row0 * 256 + cb) = *(unsigned*)&p;
                }
                if (row0 + 8 < N_NODES) {
                    __nv_bfloat162 p = __floats2bfloat162_rn(ac[2], ac[3]);
                    *(unsigned*)(g_Bh + (size_t)(row0 + 8) * 256 + cb) = *(unsigned*)&p;
                }
            }
        }
    }
}

// ---------------- fused edge aggregation (2 warps/block, packed loads) ----------------
template <bool LAST>
__global__ void __launch_bounds__(64) edge_agg_kernel(const float* __restrict__ lng,
                                                      const float* __restrict__ lnb,
                                                      const int* __restrict__ batch,
                                                      int layer) {
    int n = blockIdx.x * 2 + (threadIdx.x >> 5);
    if (n >= N_NODES) return;
    int lane = threadIdx.x & 31;

    int row = g_rowstart[n];
    int end = g_rowstart[n + 1];

    const float4* Arow = (const float4*)(g_A + (size_t)n * 256);
    float4 a1 = Arow[lane];
    float4 a2 = Arow[32 + lane];
    const __nv_bfloat16* tabf = g_tabf[layer];
    int loff = 8 * lane;                    // 16B per lane

    float4 acc = make_float4(0.f, 0.f, 0.f, 0.f);

    int e = row;
    for (; e + 3 < end; e += 4) {
        uint2 ed0 = __ldg(&g_edge[e + 0]);
        uint2 ed1 = __ldg(&g_edge[e + 1]);
        uint2 ed2 = __ldg(&g_edge[e + 2]);
        uint2 ed3 = __ldg(&g_edge[e + 3]);

        uint4 b0 = *(const uint4*)(g_Bh + (size_t)ed0.x * 256 + loff);
        uint4 t0 = *(const uint4*)(tabf + (size_t)ed0.y * 256 + loff);
        uint4 b1 = *(const uint4*)(g_Bh + (size_t)ed1.x * 256 + loff);
        uint4 t1 = *(const uint4*)(tabf + (size_t)ed1.y * 256 + loff);
        uint4 b2 = *(const uint4*)(g_Bh + (size_t)ed2.x * 256 + loff);
        uint4 t2 = *(const uint4*)(tabf + (size_t)ed2.y * 256 + loff);
        uint4 b3 = *(const uint4*)(g_Bh + (size_t)ed3.x * 256 + loff);
        uint4 t3 = *(const uint4*)(tabf + (size_t)ed3.y * 256 + loff);

        edge_accum(a1, a2, b0, t0, acc);
        edge_accum(a1, a2, b1, t1, acc);
        edge_accum(a1, a2, b2, t2, acc);
        edge_accum(a1, a2, b3, t3, acc);
    }
    for (; e < end; e++) {
        uint2 ed = __ldg(&g_edge[e]);
        uint4 bu = *(const uint4*)(g_Bh + (size_t)ed.x * 256 + loff);
        uint4 tu = *(const uint4*)(tabf + (size_t)ed.y * 256 + loff);
        edge_accum(a1, a2, bu, tu, acc);
    }

    float s  = acc.x + acc.y + acc.z + acc.w;
    float ss = acc.x * acc.x + acc.y * acc.y + acc.z * acc.z + acc.w * acc.w;
#pragma unroll
    for (int off = 16; off > 0; off >>= 1) {
        s  += __shfl_xor_sync(0xffffffffu, s, off);
        ss += __shfl_xor_sync(0xffffffffu, ss, off);
    }
    float mu = s * (1.f / 128.f);
    float var = ss * (1.f / 128.f) - mu * mu;
    float rinv = rsqrtf(var + 1e-5f);

    float4 gg = ((const float4*)lng)[lane];
    float4 bb = ((const float4*)lnb)[lane];
    float4 xo = ((float4*)g_x)[(size_t)n * 32 + lane];
    float4 o;
    o.x = softplusf((acc.x - mu) * rinv * gg.x + bb.x + xo.x);
    o.y = softplusf((acc.y - mu) * rinv * gg.y + bb.y + xo.y);
    o.z = softplusf((acc.z - mu) * rinv * gg.z + bb.z + xo.z);
    o.w = softplusf((acc.w - mu) * rinv * gg.w + bb.w + xo.w);

    if (!LAST) {
        ((float4*)g_x)[(size_t)n * 32 + lane] = o;
        __nv_bfloat162 p0 = __floats2bfloat162_rn(o.x, o.y);
        __nv_bfloat162 p1 = __floats2bfloat162_rn(o.z, o.w);
        ((uint2*)g_xh)[(size_t)n * 32 + lane] = make_uint2(*(unsigned*)&p0, *(unsigned*)&p1);
    } else {
        int b = 0;
        if (lane == 0) b = batch[n];
        b = __shfl_sync(0xffffffffu, b, 0);
        float* base = g_pool + (size_t)b * NODE_D + 4 * lane;
        atomicAdd(base + 0, o.x);
        atomicAdd(base + 1, o.y);
        atomicAdd(base + 2, o.z);
        atomicAdd(base + 3, o.w);
    }
}

// ---------------- head MLP ----------------
__global__ void head_kernel(const float* __restrict__ cfc_w, const float* __restrict__ cfc_b,
                            const float* __restrict__ fc_w,  const float* __restrict__ fc_b,
                            const float* __restrict__ out_w, const float* __restrict__ out_b,
                            float* __restrict__ out) {
    __shared__ float h0[FC_D], h1[FC_D];
    __shared__ float red[4];
    int g = blockIdx.x, c = threadIdx.x;
    float cn = fmaxf(g_cnt[g], 1.f);
    h0[c] = g_pool[(size_t)g * NODE_D + c] / cn;
    __syncthreads();
    float acc = cfc_b[c];
#pragma unroll 4
    for (int k = 0; k < NODE_D; k++) acc += h0[k] * cfc_w[k * FC_D + c];
    h1[c] = softplusf(acc);
    __syncthreads();
    acc = fc_b[c];
#pragma unroll 4
    for (int k = 0; k < FC_D; k++) acc += h1[k] * fc_w[k * FC_D + c];
    h0[c] = softplusf(acc);
    __syncthreads();
    acc = fc_b[FC_D + c];
#pragma unroll 4
    for (int k = 0; k < FC_D; k++) acc += h0[k] * fc_w[FC_D * FC_D + k * FC_D + c];
    h1[c] = softplusf(acc);
    __syncthreads();
    float p = h1[c] * out_w[c];
#pragma unroll
    for (int off = 16; off > 0; off >>= 1) p += __shfl_xor_sync(0xffffffffu, p, off);
    if ((c & 31) == 0) red[c >> 5] = p;
    __syncthreads();
    if (c == 0) out[g] = red[0] + red[1] + red[2] + red[3] + out_b[0];
}

// ---------------- launch ----------------
extern "C" void kernel_launch(void* const* d_in, const int* in_sizes, int n_in,
                              void* d_out, int out_size) {
    const int*   z         = (const int*)d_in[0];
    const float* R         = (const float*)d_in[1];
    const int*   ei        = (const int*)d_in[2];
    const int*   batch     = (const int*)d_in[3];
    const float* embedding = (const float*)d_in[4];
    const float* emb_w     = (const float*)d_in[5];
    const float* emb_b     = (const float*)d_in[6];
    const float* conv_w    = (const float*)d_in[7];
    const float* conv_b    = (const float*)d_in[8];
    const float* ln_g      = (const float*)d_in[9];
    const float* ln_b      = (const float*)d_in[10];
    const float* cfc_w     = (const float*)d_in[11];
    const float* cfc_b     = (const float*)d_in[12];
    const float* fc_w      = (const float*)d_in[13];
    const float* fc_b      = (const float*)d_in[14];
    const float* out_w     = (const float*)d_in[15];
    const float* out_b     = (const float*)d_in[16];
    float* out = (float*)d_out;

    const int* src = ei;
    const int* dst = ei + N_EDGES;

    static cudaStream_t s_prep = nullptr;
    static cudaEvent_t ev_fork = nullptr, ev_join = nullptr;
    if (s_prep == nullptr) {
        cudaStreamCreateWithFlags(&s_prep, cudaStreamNonBlocking);
        cudaEventCreateWithFlags(&ev_fork, cudaEventDisableTiming);
        cudaEventCreateWithFlags(&ev_join, cudaEventDisableTiming);
    }

    // fork: weight-only prep on s_prep
    cudaEventRecord(ev_fork, 0);
    cudaStreamWaitEvent(s_prep, ev_fork, 0);
    pack_w_kernel<<<dim3(64, N_CONV), 256, 0, s_prep>>>(conv_w);
    build_tab_kernel<<<dim3(N_T, N_CONV), 256, 0, s_prep>>>(conv_w);
    expand_tab_kernel<<<dim3(NTF, N_CONV), 256, 0, s_prep>>>();
    cudaEventRecord(ev_join, s_prep);

    // main chain: embedding + edge sort
    zero_misc_kernel<<<SGRID, SB>>>();
    emb_table_kernel<<<100, NODE_D>>>(embedding, emb_w, emb_b);
    embed_gather_kernel<<<(N_NODES + 7) / 8, 256>>>(z);
    graph_count_kernel<<<1, 256>>>(batch);
    hist_kernel<<<(N_EDGES + 255) / 256, 256>>>(dst);
    scan_pass1<<<SGRID, SB>>>();
    scan_pass2<<<1, SB>>>();
    scan_pass3<<<SGRID, SB>>>();
    scatter_kernel<<<(N_EDGES + 255) / 256, 256>>>(R, src, dst);

    // join prep before conv layers
    cudaStreamWaitEvent(0, ev_join, 0);

    for (int l = 0; l < N_CONV; l++) {
        const float* bl = conv_b + (size_t)l * 256;
        dim3 ggrid(2, (N_NODES + TBM - 1) / TBM);
        gemm_mma_kernel<<<ggrid, 256>>>(bl, l);
        if (l < N_CONV - 1)
            edge_agg_kernel<false><<<(N_NODES + 1) / 2, 64>>>(
                ln_g + l * NODE_D, ln_b + l * NODE_D, batch, l);
        else
            edge_agg_kernel<true><<<(N_NODES + 1) / 2, 64>>>(
                ln_g + l * NODE_D, ln_b + l * NODE_D, batch, l);
    }

    head_kernel<<<N_GRAPHS, FC_D>>>(cfc_w, cfc_b, fc_w, fc_b, out_w, out_b, out);
}

// round 15
// speedup vs baseline: 3.2683x; 1.0269x over previous
#include <cuda_runtime.h>
#include <cuda_bf16.h>
#include <math.h>

#define N_NODES  50000
#define N_EDGES  800000
#define NODE_D   128
#define EDGE_D   100
#define EMB_D    92
#define N_GRAPHS 256
#define N_CONV   3
#define FC_D     128

#define DELTA    (6.0f / 99.0f)
#define N_T      1800
#define H_T      (DELTA / 16.0f)
#define NTF      (16 * (N_T - 1))          // 28784 fine rows
#define H_F      (DELTA / 256.0f)

#define SB    256
#define SGRID ((N_NODES + SB - 1) / SB)
#define GHGRID ((N_NODES + 7) / 8)

// ---------------- scratch (device globals) ----------------
__device__ float g_embt[100 * NODE_D];
__device__ float g_x[N_NODES * NODE_D];
__device__ __nv_bfloat16 g_xh[N_NODES * NODE_D];
__device__ float g_A[N_NODES * 256];
__device__ __nv_bfloat16 g_Bh[N_NODES * 256];         // INTERLEAVED: [z1[0],z2[0],z1[1],z2[1],...]
__device__ uint2 g_Wp[N_CONV][8 * 64 * 32];
__device__ float g_tab[N_CONV][N_T * 256];            // logical layout
__device__ __nv_bfloat16 g_tabf[N_CONV][(size_t)NTF * 256];  // INTERLEAVED like g_Bh
__device__ int   g_deg[N_NODES];
__device__ int   g_off[N_NODES];
__device__ int   g_rowstart[N_NODES + 1];
__device__ int   g_bsum[SGRID];
__device__ uint2 g_edge[N_EDGES];
__device__ float g_pool[N_GRAPHS * NODE_D];
__device__ float g_cnt[N_GRAPHS];

// ---------------- fast math helpers ----------------
__device__ __forceinline__ float softplusf(float x) {
    return fmaxf(x, 0.f) + __logf(1.f + __expf(-fabsf(x)));
}
__device__ __forceinline__ float bflo(unsigned u) { return __uint_as_float(u << 16); }
__device__ __forceinline__ float bfhi(unsigned u) { return __uint_as_float(u & 0xffff0000u); }

__device__ __forceinline__ unsigned bf2add(unsigned a, unsigned b) {
    unsigned r;
    asm("add.rn.bf16x2 %0, %1, %2;" : "=r"(r) : "r"(a), "r"(b));
    return r;
}

// packed f16x2 sigmoid via tanh.approx.f16x2: sigma(x) = 0.5*tanh(x/2)+0.5
__device__ __forceinline__ float2 sigmoid2(float x, float y) {
    unsigned h;
    asm("cvt.rn.f16x2.f32 %0, %1, %2;" : "=r"(h) : "f"(y * 0.5f), "f"(x * 0.5f));
    asm("tanh.approx.f16x2 %0, %0;" : "+r"(h));
    float tx, ty;
    asm("{ .reg .b16 lo, hi; mov.b32 {lo, hi}, %2; cvt.f32.f16 %0, lo; cvt.f32.f16 %1, hi; }"
        : "=f"(tx), "=f"(ty) : "r"(h));
    return make_float2(fmaf(0.5f, tx, 0.5f), fmaf(0.5f, ty, 0.5f));
}

__device__ __forceinline__ void mma_bf16(float* c, const unsigned* a, uint2 b) {
    asm volatile(
        "mma.sync.aligned.m16n8k16.row.col.f32.bf16.bf16.f32 "
        "{%0,%1,%2,%3}, {%4,%5,%6,%7}, {%8,%9}, {%0,%1,%2,%3};"
        : "+f"(c[0]), "+f"(c[1]), "+f"(c[2]), "+f"(c[3])
        : "r"(a[0]), "r"(a[1]), "r"(a[2]), "r"(a[3]), "r"(b.x), "r"(b.y));
}

// per-edge message accumulate (interleaved packed operands)
__device__ __forceinline__ void edge_accum(const float4& a1, const float4& a2,
                                           uint4 bu, uint4 tu, float4& acc) {
    unsigned s0 = bf2add(bu.x, tu.x);
    unsigned s1 = bf2add(bu.y, tu.y);
    unsigned s2 = bf2add(bu.z, tu.z);
    unsigned s3 = bf2add(bu.w, tu.w);
    float4 z1, z2;
    z1.x = a1.x + bflo(s0); z2.x = a2.x + bfhi(s0);
    z1.y = a1.y + bflo(s1); z2.y = a2.y + bfhi(s1);
    z1.z = a1.z + bflo(s2); z2.z = a2.z + bfhi(s2);
    z1.w = a1.w + bflo(s3); z2.w = a2.w + bfhi(s3);
    float2 sA = sigmoid2(z1.x, z1.y);
    float2 sB = sigmoid2(z1.z, z1.w);
    acc.x = fmaf(sA.x, softplusf(z2.x), acc.x);
    acc.y = fmaf(sA.y, softplusf(z2.y), acc.y);
    acc.z = fmaf(sB.x, softplusf(z2.z), acc.z);
    acc.w = fmaf(sB.y, softplusf(z2.w), acc.w);
}

// ---------------- fused setup: zero + emb_table + graph_count ----------------
__global__ void setup_kernel(const float* __restrict__ emb,
                             const float* __restrict__ W,
                             const float* __restrict__ b,
                             const int* __restrict__ batch) {
    __shared__ float er[EMB_D];
    int bx = blockIdx.x;
    if (bx < SGRID) {
        int i = bx * SB + threadIdx.x;
        if (i < N_NODES) g_deg[i] = 0;
        if (i < N_GRAPHS * NODE_D) g_pool[i] = 0.f;
    } else if (bx < SGRID + 100) {
        int r = bx - SGRID;
        if (threadIdx.x < EMB_D) er[threadIdx.x] = emb[r * EMB_D + threadIdx.x];
        __syncthreads();
        int c = threadIdx.x;
        if (c < NODE_D) {
            float acc = b[c];
#pragma unroll 4
            for (int k = 0; k < EMB_D; k++) acc += er[k] * W[k * NODE_D + c];
            g_embt[r * NODE_D + c] = acc;
        }
    } else {
        int g = threadIdx.x;
        if (g < N_GRAPHS) {
            int lo = 0, hi = N_NODES;
            while (lo < hi) { int m = (lo + hi) >> 1; if (batch[m] < g) lo = m + 1; else hi = m; }
            int a = lo;
            lo = 0; hi = N_NODES;
            while (lo < hi) { int m = (lo + hi) >> 1; if (batch[m] <= g) lo = m + 1; else hi = m; }
            g_cnt[g] = (float)(lo - a);
        }
    }
}

// ---------------- fused: x0 gather + dst histogram ----------------
__global__ void gather_hist_kernel(const int* __restrict__ z,
                                   const int* __restrict__ dst) {
    int n = blockIdx.x * 8 + (threadIdx.x >> 5);
    int lane = threadIdx.x & 31;
    if (n < N_NODES) {
        int zi = z[n];                       // same addr per warp -> broadcast
        float4 v = ((const float4*)g_embt)[zi * 32 + lane];
        ((float4*)g_x)[(size_t)n * 32 + lane] = v;
        __nv_bfloat162 p0 = __floats2bfloat162_rn(v.x, v.y);
        __nv_bfloat162 p1 = __floats2bfloat162_rn(v.z, v.w);
        ((uint2*)g_xh)[(size_t)n * 32 + lane] = make_uint2(*(unsigned*)&p0, *(unsigned*)&p1);
    }
    int gid = blockIdx.x * blockDim.x + threadIdx.x;
    if (gid < N_EDGES) atomicAdd(&g_deg[dst[gid]], 1);
}

// ---------------- scan passes ----------------
__global__ void scan_pass1() {
    __shared__ int ws[8];
    int i = blockIdx.x * SB + threadIdx.x;
    int v = (i < N_NODES) ? g_deg[i] : 0;
#pragma unroll
    for (int off = 16; off > 0; off >>= 1) v += __shfl_xor_sync(0xffffffffu, v, off);
    if ((threadIdx.x & 31) == 0) ws[threadIdx.x >> 5] = v;
    __syncthreads();
    if (threadIdx.x == 0) {
        int s = 0;
#pragma unroll
        for (int w = 0; w < 8; w++) s += ws[w];
        g_bsum[blockIdx.x] = s;
    }
}

__global__ void scan_pass2() {
    __shared__ int sm[SB];
    int t = threadIdx.x;
    int v = (t < SGRID) ? g_bsum[t] : 0;
    sm[t] = v;
    __syncthreads();
#pragma unroll
    for (int off = 1; off < SB; off <<= 1) {
        int u = (t >= off) ? sm[t - off] : 0;
        __syncthreads();
        sm[t] += u;
        __syncthreads();
    }
    if (t < SGRID) g_bsum[t] = sm[t] - v;
}

__global__ void scan_pass3() {
    __shared__ int sm[SB];
    int t = threadIdx.x;
    int i = blockIdx.x * SB + t;
    int v = (i < N_NODES) ? g_deg[i] : 0;
    sm[t] = v;
    __syncthreads();
#pragma unroll
    for (int off = 1; off < SB; off <<= 1) {
        int u = (t >= off) ? sm[t - off] : 0;
        __syncthreads();
        sm[t] += u;
        __syncthreads();
    }
    int ex = g_bsum[blockIdx.x] + sm[t] - v;
    if (i < N_NODES) {
        g_rowstart[i] = ex;
        g_off[i] = ex;
        if (i == N_NODES - 1) g_rowstart[N_NODES] = ex + v;
    }
}

__global__ void scatter_kernel(const float* __restrict__ R,
                               const int* __restrict__ src,
                               const int* __restrict__ dst) {
    int e = blockIdx.x * blockDim.x + threadIdx.x;
    if (e >= N_EDGES) return;
    int s = src[e], d = dst[e];
    float dx = R[s * 3 + 0] - R[d * 3 + 0];
    float dy = R[s * 3 + 1] - R[d * 3 + 1];
    float dz = R[s * 3 + 2] - R[d * 3 + 2];
    float dist = sqrtf(dx * dx + dy * dy + dz * dz);
    int t = (int)(fminf(dist / H_F + 0.5f, (float)(NTF - 1)));
    int pos = atomicAdd(&g_off[d], 1);
    g_edge[pos] = make_uint2((unsigned)s, (unsigned)t);
}

// ---------------- coarse tables, all layers (logical layout) ----------------
__global__ void build_tab_kernel(const float* __restrict__ conv_w) {
    __shared__ float gs[EDGE_D];
    int l = blockIdx.y;
    const float* W3 = conv_w + (size_t)l * 356 * 256 + 256 * 256;
    int t = blockIdx.x;
    float d = (float)t * H_T;
    const float coeff = -0.5f / (DELTA * DELTA);
    if (threadIdx.x < EDGE_D) {
        float u = d - (float)threadIdx.x * DELTA;
        gs[threadIdx.x] = expf(coeff * u * u);
    }
    __syncthreads();
    int c = threadIdx.x;
    float acc = 0.f;
#pragma unroll 4
    for (int k = 0; k < EDGE_D; k++) acc += gs[k] * W3[k * 256 + c];
    g_tab[l][(size_t)t * 256 + c] = acc;
}

// ---------------- expand coarse -> fine bf16 (INTERLEAVED channels) ----------------
__global__ void expand_tab_kernel() {
    int l = blockIdx.y;
    int tf = blockIdx.x;
    int c = threadIdx.x;
    int lc = (c & 1) ? 128 + (c >> 1) : (c >> 1);
    int t = tf >> 4;
    float f = (float)(tf & 15) * (1.f / 16.f);
    float lo = g_tab[l][(size_t)t * 256 + lc];
    float hi = g_tab[l][(size_t)(t + 1) * 256 + lc];
    g_tabf[l][(size_t)tf * 256 + c] = __float2bfloat16(fmaf(f, hi - lo, lo));
}

// ---------------- weight pack (src half column-permuted for interleaved output) ----------------
__global__ void pack_w_kernel(const float* __restrict__ conv_w) {
    int l = blockIdx.y;
    const float* Wl = conv_w + (size_t)l * 356 * 256;
    int idx = blockIdx.x * 256 + threadIdx.x;
    if (idx >= 8 * 64 * 32) return;
    int lane = idx & 31;
    int ntile = (idx >> 5) & 63;
    int kt = idx >> 11;
    int u = lane & 3, c = lane >> 2;
    int n = ntile * 8 + c;
    const float* W = Wl + ((n < 256) ? 0 : 128 * 256);
    int wc;
    if (n < 256) {
        wc = n;
    } else {
        int p = n - 256;
        wc = (p & 1) ? 128 + (p >> 1) : (p >> 1);
    }
    int k = kt * 16 + 2 * u;
    __nv_bfloat162 v0 = __floats2bfloat162_rn(W[(k + 0) * 256 + wc], W[(k + 1) * 256 + wc]);
    __nv_bfloat162 v1 = __floats2bfloat162_rn(W[(k + 8) * 256 + wc], W[(k + 9) * 256 + wc]);
    g_Wp[l][idx] = make_uint2(*(unsigned*)&v0, *(unsigned*)&v1);
}

// ---------------- tensor-core GEMM ----------------
#define TBM 64
__global__ void gemm_mma_kernel(const float* __restrict__ bias, int layer) {
    __shared__ __nv_bfloat16 As[TBM][136];
    int tid = threadIdx.x;
    int m0 = blockIdx.y * TBM;
    int n0 = blockIdx.x * 256;

#pragma unroll
    for (int i = 0; i < 4; i++) {
        int idx = tid + i * 256;
        int r = idx >> 4, cs = idx & 15;
        uint4 v = make_uint4(0, 0, 0, 0);
        if (m0 + r < N_NODES) v = *(const uint4*)(g_xh + (size_t)(m0 + r) * NODE_D + cs * 8);
        *(uint4*)&As[r][cs * 8] = v;
    }
    __syncthreads();

    int wid = tid >> 5, lane = tid & 31;
    int wm = wid >> 2, wn = wid & 3;
    int g = lane >> 2, u = lane & 3;
    int mbase = wm * 32;
    int ntile0 = (n0 + wn * 64) >> 3;
    const uint2* Wp = g_Wp[layer];

    float acc[2][8][4];
#pragma unroll
    for (int a = 0; a < 2; a++)
#pragma unroll
        for (int b = 0; b < 8; b++)
#pragma unroll
            for (int c = 0; c < 4; c++) acc[a][b][c] = 0.f;

#pragma unroll
    for (int kt = 0; kt < 8; kt++) {
        int k0 = kt * 16;
        unsigned afr[2][4];
#pragma unroll
        for (int mf = 0; mf < 2; mf++) {
            int rb = mbase + mf * 16;
            afr[mf][0] = *(unsigned*)&As[rb + g][k0 + 2 * u];
            afr[mf][1] = *(unsigned*)&As[rb + g + 8][k0 + 2 * u];
            afr[mf][2] = *(unsigned*)&As[rb + g][k0 + 8 + 2 * u];
            afr[mf][3] = *(unsigned*)&As[rb + g + 8][k0 + 8 + 2 * u];
        }
        uint2 bfr[8];
#pragma unroll
        for (int j = 0; j < 8; j++)
            bfr[j] = Wp[(kt * 64 + ntile0 + j) * 32 + lane];
#pragma unroll
        for (int mf = 0; mf < 2; mf++)
#pragma unroll
            for (int j = 0; j < 8; j++)
                mma_bf16(acc[mf][j], afr[mf], bfr[j]);
    }

#pragma unroll
    for (int mf = 0; mf < 2; mf++) {
        int row0 = m0 + mbase + mf * 16 + g;
#pragma unroll
        for (int j = 0; j < 8; j++) {
            int col = n0 + wn * 64 + j * 8 + 2 * u;
            float* ac = acc[mf][j];
            if (n0 == 0) {
                float2 bv = *(const float2*)(bias + col);
                if (row0 < N_NODES)
                    *(float2*)(g_A + (size_t)row0 * 256 + col) =
                        make_float2(ac[0] + bv.x, ac[1] + bv.y);
                if (row0 + 8 < N_NODES)
                    *(float2*)(g_A + (size_t)(row0 + 8) * 256 + col) =
                        make_float2(ac[2] + bv.x, ac[3] + bv.y);
            } else {
                int cb = col - 256;
                if (row0 < N_NODES) {
                    __nv_bfloat162 p = __floats2bfloat162_rn(ac[0], ac[1]);
                    *(unsigned*)(g_Bh + (size_t)row0 * 256 + cb) = *(unsigned*)&p;
                }
                if (row0 + 8 < N_NODES) {
                    __nv_bfloat162 p = __floats2bfloat162_rn(ac[2], ac[3]);
                    *(unsigned*)(g_Bh + (size_t)(row0 + 8) * 256 + cb) = *(unsigned*)&p;
                }
            }
        }
    }
}

// ---------------- fused edge aggregation (2 warps/block, meta-prefetch, pairwise buffers) --------
template <bool LAST>
__global__ void __launch_bounds__(64) edge_agg_kernel(const float* __restrict__ lng,
                                                      const float* __restrict__ lnb,
                                                      const int* __restrict__ batch,
                                                      int layer) {
    int n = blockIdx.x * 2 + (threadIdx.x >> 5);
    if (n >= N_NODES) return;
    int lane = threadIdx.x & 31;

    int row = g_rowstart[n];
    int end = g_rowstart[n + 1];

    const float4* Arow = (const float4*)(g_A + (size_t)n * 256);
    float4 a1 = Arow[lane];
    float4 a2 = Arow[32 + lane];
    const __nv_bfloat16* tabf = g_tabf[layer];
    int loff = 8 * lane;                    // 16B per lane

    float4 acc = make_float4(0.f, 0.f, 0.f, 0.f);

    int e = row;
    for (; e + 3 < end; e += 4) {
        // prefetch all 4 edge metas (independent small loads)
        uint2 ed0 = __ldg(&g_edge[e + 0]);
        uint2 ed1 = __ldg(&g_edge[e + 1]);
        uint2 ed2 = __ldg(&g_edge[e + 2]);
        uint2 ed3 = __ldg(&g_edge[e + 3]);

        // pair 1: edges 0,1 (4 LDG.128 in flight)
        uint4 b0 = __ldg((const uint4*)(g_Bh + (size_t)ed0.x * 256 + loff));
        uint4 t0 = __ldg((const uint4*)(tabf + (size_t)ed0.y * 256 + loff));
        uint4 b1 = __ldg((const uint4*)(g_Bh + (size_t)ed1.x * 256 + loff));
        uint4 t1 = __ldg((const uint4*)(tabf + (size_t)ed1.y * 256 + loff));
        edge_accum(a1, a2, b0, t0, acc);
        edge_accum(a1, a2, b1, t1, acc);

        // pair 2: edges 2,3 (buffers reused -> lower register pressure)
        uint4 b2 = __ldg((const uint4*)(g_Bh + (size_t)ed2.x * 256 + loff));
        uint4 t2 = __ldg((const uint4*)(tabf + (size_t)ed2.y * 256 + loff));
        uint4 b3 = __ldg((const uint4*)(g_Bh + (size_t)ed3.x * 256 + loff));
        uint4 t3 = __ldg((const uint4*)(tabf + (size_t)ed3.y * 256 + loff));
        edge_accum(a1, a2, b2, t2, acc);
        edge_accum(a1, a2, b3, t3, acc);
    }
    for (; e < end; e++) {
        uint2 ed = __ldg(&g_edge[e]);
        uint4 bu = __ldg((const uint4*)(g_Bh + (size_t)ed.x * 256 + loff));
        uint4 tu = __ldg((const uint4*)(tabf + (size_t)ed.y * 256 + loff));
        edge_accum(a1, a2, bu, tu, acc);
    }

    float s  = acc.x + acc.y + acc.z + acc.w;
    float ss = acc.x * acc.x + acc.y * acc.y + acc.z * acc.z + acc.w * acc.w;
#pragma unroll
    for (int off = 16; off > 0; off >>= 1) {
        s  += __shfl_xor_sync(0xffffffffu, s, off);
        ss += __shfl_xor_sync(0xffffffffu, ss, off);
    }
    float mu = s * (1.f / 128.f);
    float var = ss * (1.f / 128.f) - mu * mu;
    float rinv = rsqrtf(var + 1e-5f);

    float4 gg = ((const float4*)lng)[lane];
    float4 bb = ((const float4*)lnb)[lane];
    float4 xo = ((float4*)g_x)[(size_t)n * 32 + lane];
    float4 o;
    o.x = softplusf((acc.x - mu) * rinv * gg.x + bb.x + xo.x);
    o.y = softplusf((acc.y - mu) * rinv * gg.y + bb.y + xo.y);
    o.z = softplusf((acc.z - mu) * rinv * gg.z + bb.z + xo.z);
    o.w = softplusf((acc.w - mu) * rinv * gg.w + bb.w + xo.w);

    if (!LAST) {
        ((float4*)g_x)[(size_t)n * 32 + lane] = o;
        __nv_bfloat162 p0 = __floats2bfloat162_rn(o.x, o.y);
        __nv_bfloat162 p1 = __floats2bfloat162_rn(o.z, o.w);
        ((uint2*)g_xh)[(size_t)n * 32 + lane] = make_uint2(*(unsigned*)&p0, *(unsigned*)&p1);
    } else {
        int b = batch[n];                   // same addr per warp -> broadcast
        float* base = g_pool + (size_t)b * NODE_D + 4 * lane;
        atomicAdd(base + 0, o.x);
        atomicAdd(base + 1, o.y);
        atomicAdd(base + 2, o.z);
        atomicAdd(base + 3, o.w);
    }
}

// ---------------- head MLP ----------------
__global__ void head_kernel(const float* __restrict__ cfc_w, const float* __restrict__ cfc_b,
                            const float* __restrict__ fc_w,  const float* __restrict__ fc_b,
                            const float* __restrict__ out_w, const float* __restrict__ out_b,
                            float* __restrict__ out) {
    __shared__ float h0[FC_D], h1[FC_D];
    __shared__ float red[4];
    int g = blockIdx.x, c = threadIdx.x;
    float cn = fmaxf(g_cnt[g], 1.f);
    h0[c] = g_pool[(size_t)g * NODE_D + c] / cn;
    __syncthreads();
    float acc = cfc_b[c];
#pragma unroll 4
    for (int k = 0; k < NODE_D; k++) acc += h0[k] * cfc_w[k * FC_D + c];
    h1[c] = softplusf(acc);
    __syncthreads();
    acc = fc_b[c];
#pragma unroll 4
    for (int k = 0; k < FC_D; k++) acc += h1[k] * fc_w[k * FC_D + c];
    h0[c] = softplusf(acc);
    __syncthreads();
    acc = fc_b[FC_D + c];
#pragma unroll 4
    for (int k = 0; k < FC_D; k++) acc += h0[k] * fc_w[FC_D * FC_D + k * FC_D + c];
    h1[c] = softplusf(acc);
    __syncthreads();
    float p = h1[c] * out_w[c];
#pragma unroll
    for (int off = 16; off > 0; off >>= 1) p += __shfl_xor_sync(0xffffffffu, p, off);
    if ((c & 31) == 0) red[c >> 5] = p;
    __syncthreads();
    if (c == 0) out[g] = red[0] + red[1] + red[2] + red[3] + out_b[0];
}

// ---------------- launch ----------------
extern "C" void kernel_launch(void* const* d_in, const int* in_sizes, int n_in,
                              void* d_out, int out_size) {
    const int*   z         = (const int*)d_in[0];
    const float* R         = (const float*)d_in[1];
    const int*   ei        = (const int*)d_in[2];
    const int*   batch     = (const int*)d_in[3];
    const float* embedding = (const float*)d_in[4];
    const float* emb_w     = (const float*)d_in[5];
    const float* emb_b     = (const float*)d_in[6];
    const float* conv_w    = (const float*)d_in[7];
    const float* conv_b    = (const float*)d_in[8];
    const float* ln_g      = (const float*)d_in[9];
    const float* ln_b      = (const float*)d_in[10];
    const float* cfc_w     = (const float*)d_in[11];
    const float* cfc_b     = (const float*)d_in[12];
    const float* fc_w      = (const float*)d_in[13];
    const float* fc_b      = (const float*)d_in[14];
    const float* out_w     = (const float*)d_in[15];
    const float* out_b     = (const float*)d_in[16];
    float* out = (float*)d_out;

    const int* src = ei;
    const int* dst = ei + N_EDGES;

    static cudaStream_t s_prep = nullptr;
    static cudaEvent_t ev_fork = nullptr, ev_join = nullptr;
    if (s_prep == nullptr) {
        cudaStreamCreateWithFlags(&s_prep, cudaStreamNonBlocking);
        cudaEventCreateWithFlags(&ev_fork, cudaEventDisableTiming);
        cudaEventCreateWithFlags(&ev_join, cudaEventDisableTiming);
    }

    // fork: weight-only prep on s_prep
    cudaEventRecord(ev_fork, 0);
    cudaStreamWaitEvent(s_prep, ev_fork, 0);
    pack_w_kernel<<<dim3(64, N_CONV), 256, 0, s_prep>>>(conv_w);
    build_tab_kernel<<<dim3(N_T, N_CONV), 256, 0, s_prep>>>(conv_w);
    expand_tab_kernel<<<dim3(NTF, N_CONV), 256, 0, s_prep>>>();
    cudaEventRecord(ev_join, s_prep);

    // main chain: setup (zero + emb table + graph counts), gather+hist, sort
    setup_kernel<<<SGRID + 101, SB>>>(embedding, emb_w, emb_b, batch);
    gather_hist_kernel<<<GHGRID, SB>>>(z, dst);
    scan_pass1<<<SGRID, SB>>>();
    scan_pass2<<<1, SB>>>();
    scan_pass3<<<SGRID, SB>>>();
    scatter_kernel<<<(N_EDGES + 255) / 256, 256>>>(R, src, dst);

    // join prep before conv layers
    cudaStreamWaitEvent(0, ev_join, 0);

    for (int l = 0; l < N_CONV; l++) {
        const float* bl = conv_b + (size_t)l * 256;
        dim3 ggrid(2, (N_NODES + TBM - 1) / TBM);
        gemm_mma_kernel<<<ggrid, 256>>>(bl, l);
        if (l < N_CONV - 1)
            edge_agg_kernel<false><<<(N_NODES + 1) / 2, 64>>>(
                ln_g + l * NODE_D, ln_b + l * NODE_D, batch, l);
        else
            edge_agg_kernel<true><<<(N_NODES + 1) / 2, 64>>>(
                ln_g + l * NODE_D, ln_b + l * NODE_D, batch, l);
    }

    head_kernel<<<N_GRAPHS, FC_D>>>(cfc_w, cfc_b, fc_w, fc_b, out_w, out_b, out);
}